// round 2
// baseline (speedup 1.0000x reference)
#include <cuda_runtime.h>

// ---------------- problem constants ----------------
#define BN   16
#define CH   128
#define HWN  1024
#define SN   8
#define SBN  128
#define CHW  131072        // CH*HWN

// ---------------- device scratch ----------------
__device__ float g_ht [BN*CHW];
__device__ float g_q  [BN*CHW];
__device__ float g_k  [SBN*CHW];
__device__ float g_v  [SBN*CHW];
__device__ float g_av [BN*CHW];
__device__ float g_att[BN*CHW];
__device__ float g_o  [BN*CHW];
__device__ float g_stats[2*SBN];
__device__ float g_pool[SBN*2*HWN];
__device__ float g_qsa[BN*HWN];
__device__ float g_ksa[SBN*HWN];
__device__ float g_qfg[SN*BN*CH];
__device__ float g_sprob[SBN*HWN];
__device__ float g_tl[SN*BN];
__device__ float g_tp[SN*BN];
__device__ float g_peN[SN*2*CH];
__device__ float g_se1[BN*CH];
__device__ float g_se2[BN*32];
__device__ float g_se3[BN*CH];
__device__ float g_wT[1048576];   // transposed weights, see offsets in host code

__device__ __forceinline__ float sigmf(float x){ return 1.f/(1.f + __expf(-x)); }

__device__ __forceinline__ bool mask_at(const unsigned char* m, int b){
    if (m[1] != 0) return m[b] != 0;                 // 1-byte bools
    const unsigned int* w = (const unsigned int*)m;  // 4-byte elements
    return w[b] != 0;
}

// packed fp32x2 helpers (sm_100+)
__device__ __forceinline__ void fma2(unsigned long long &d, unsigned long long a, unsigned long long b){
    asm("fma.rn.f32x2 %0, %1, %2, %0;" : "+l"(d) : "l"(a), "l"(b));
}
__device__ __forceinline__ unsigned long long bcast2(float v){
    unsigned long long r;
    asm("mov.b64 %0, {%1, %1};" : "=l"(r) : "f"(v));
    return r;
}
__device__ __forceinline__ void unpack2(unsigned long long p, float &lo, float &hi){
    asm("mov.b64 {%0, %1}, %2;" : "=f"(lo), "=f"(hi) : "l"(p));
}

// ---------------- weight transpose: (Cout,Cin,kh,kw) -> [c][tap][co] ----------------
__global__ void transw_k(const float* __restrict__ w, float* __restrict__ wT,
                         int cin, int ktaps)
{
    int n = cin*ktaps*128;
    for (int i = blockIdx.x*blockDim.x + threadIdx.x; i < n; i += gridDim.x*blockDim.x){
        int co = i & 127;
        int r  = i >> 7;
        int tap = r % ktaps;
        int c   = r / ktaps;
        wT[i] = w[(co*cin + c)*ktaps + tap];
    }
}

// ---------------- pos_emb row normalization ----------------
__global__ void pe_norm_k(const float* __restrict__ pe, float* __restrict__ peN)
{
    int s = blockIdx.x;
    int t = threadIdx.x;
    float v = pe[s*256 + t];
    float q = v*v;
    #pragma unroll
    for (int o=16;o;o>>=1) q += __shfl_down_sync(0xffffffffu, q, o);
    __shared__ float a[8];
    __shared__ float fac;
    if ((t&31)==0) a[t>>5] = q;
    __syncthreads();
    if (t==0){
        float S=0.f;
        #pragma unroll
        for (int i=0;i<8;i++) S += a[i];
        float n = sqrtf(S);
        fac = fminf(1.f, 1.f/fmaxf(n, 1e-7f));
    }
    __syncthreads();
    peN[s*256 + t] = v*fac;
}

// ---------------- 3x3 conv, pad=1, Cout=128, f32x2 pipe ----------------
// block: 256 thr = 32 x-lanes * 8 co-groups(16 co). Each thread: 8 y-rows x 16 couts.
// grid: nimg*4 (8-row tiles).
// modes: 0 single src; 1 concat(s0,s1); 2 concat+pe(s2); 3 concat(inputs64, s1+s2)
__global__ __launch_bounds__(256,1)
void conv3x3f2_k(const float* __restrict__ s0, const float* __restrict__ s1,
                 const float* __restrict__ s2, const float* __restrict__ wT,
                 float* __restrict__ dst, int cin, int mode)
{
    __shared__ float sIn[8*10*34];   // 2720 floats: 8 ci x (8+2 halo rows) x 34
    __shared__ float sW [8*9*128];   // 9216 floats
    const int t   = threadIdx.x;
    const int img = blockIdx.x >> 2;
    const int y0  = (blockIdx.x & 3) << 3;
    const int x   = t & 31;
    const int cg  = t >> 5;

    unsigned long long acc[64];      // [y][co-pair] packed f32x2
    #pragma unroll
    for (int i=0;i<64;i++) acc[i]=0ull;

    const int nchunk = cin >> 3;
    for (int cc=0; cc<nchunk; cc++){
        // stage weights: 9216 floats = 2304 float4
        {
            const float4* wp = (const float4*)(wT + cc*9216);
            #pragma unroll
            for (int e=0;e<9;e++) ((float4*)sW)[t + (e<<8)] = wp[t + (e<<8)];
        }
        // stage inputs: 8 ci x 10 rows x 34
        for (int e=t; e<2720; e+=256){
            int ci = e/340; int rem = e - ci*340;
            int r  = rem/34; int xx = rem - r*34;
            int y  = y0 - 1 + r; int xg = xx - 1;
            float val = 0.f;
            if ((unsigned)y < 32u && (unsigned)xg < 32u){
                int c = (cc<<3) + ci;
                int p = (y<<5) + xg;
                if (mode == 0){
                    val = s0[((size_t)img*cin + c)*1024 + p];
                } else if (mode == 1){
                    val = (c < 128) ? s0[((size_t)img*128 + c)*1024 + p]
                                    : s1[((size_t)img*128 + (c-128))*1024 + p];
                } else if (mode == 2){
                    float bv = (c < 128) ? s0[((size_t)img*128 + c)*1024 + p]
                                         : s1[((size_t)img*128 + (c-128))*1024 + p];
                    val = bv + s2[(img>>4)*256 + c];
                } else {
                    val = (c < 64) ? s0[((size_t)img*64 + c)*1024 + p]
                                   : s1[((size_t)img*128 + (c-64))*1024 + p]
                                   + s2[((size_t)img*128 + (c-64))*1024 + p];
                }
            }
            sIn[(ci*10 + r)*34 + xx] = val;
        }
        __syncthreads();
        #pragma unroll 1
        for (int ci=0; ci<8; ci++){
            float inr[30];
            #pragma unroll
            for (int r=0;r<10;r++){
                #pragma unroll
                for (int d=0;d<3;d++) inr[r*3+d] = sIn[(ci*10+r)*34 + x + d];
            }
            #pragma unroll
            for (int tap=0; tap<9; tap++){
                const int dy = tap/3, dx = tap - dy*3;
                const ulonglong2* wq = (const ulonglong2*)&sW[(ci*9+tap)*128 + (cg<<4)];
                ulonglong2 wa = wq[0], wb = wq[1], wc = wq[2], wd = wq[3];
                #pragma unroll
                for (int y=0;y<8;y++){
                    unsigned long long iv2 = bcast2(inr[(y+dy)*3 + dx]);
                    unsigned long long* a = &acc[y*8];
                    fma2(a[0], iv2, wa.x); fma2(a[1], iv2, wa.y);
                    fma2(a[2], iv2, wb.x); fma2(a[3], iv2, wb.y);
                    fma2(a[4], iv2, wc.x); fma2(a[5], iv2, wc.y);
                    fma2(a[6], iv2, wd.x); fma2(a[7], iv2, wd.y);
                }
            }
        }
        __syncthreads();
    }
    // store: acc[y*8+j] -> co = cg*16 + 2j, 2j+1
    #pragma unroll
    for (int j=0;j<8;j++){
        int co = (cg<<4) + (j<<1);
        float* d0 = dst + ((size_t)img*128 + co)*1024 + (y0<<5) + x;
        float* d1 = d0 + 1024;
        #pragma unroll
        for (int y=0;y<8;y++){
            float lo, hi;
            unpack2(acc[y*8+j], lo, hi);
            d0[y<<5] = lo;
            d1[y<<5] = hi;
        }
    }
}

// ---------------- 1x1 conv (vpost), 128->128 ----------------
__global__ __launch_bounds__(256,2)
void conv1x1_k(const float* __restrict__ src, const float* __restrict__ wT,
               float* __restrict__ dst)
{
    __shared__ float sIn[8*128];
    __shared__ float sW [8*128];
    const int t   = threadIdx.x;
    const int img = blockIdx.x >> 3;
    const int p0  = (blockIdx.x & 7) << 7;
    const int xl  = t & 31;
    const int cg  = t >> 5;
    float acc[64];
    #pragma unroll
    for (int i=0;i<64;i++) acc[i]=0.f;

    for (int cc=0; cc<16; cc++){
        for (int e=t; e<1024; e+=256){
            int ci = e>>7, i = e&127;
            sIn[e] = src[((size_t)img*128 + (cc<<3)+ci)*1024 + p0 + i];
            sW [e] = wT[(cc<<10) + e];
        }
        __syncthreads();
        #pragma unroll
        for (int ci=0;ci<8;ci++){
            float inr[4];
            #pragma unroll
            for (int y=0;y<4;y++) inr[y] = sIn[ci*128 + (y<<5) + xl];
            const float4* wq = (const float4*)&sW[ci*128 + (cg<<4)];
            float4 w0=wq[0], w1=wq[1], w2=wq[2], w3=wq[3];
            #pragma unroll
            for (int y=0;y<4;y++){
                float iv = inr[y];
                float* a = &acc[y*16];
                a[0]  += iv*w0.x; a[1]  += iv*w0.y; a[2]  += iv*w0.z; a[3]  += iv*w0.w;
                a[4]  += iv*w1.x; a[5]  += iv*w1.y; a[6]  += iv*w1.z; a[7]  += iv*w1.w;
                a[8]  += iv*w2.x; a[9]  += iv*w2.y; a[10] += iv*w2.z; a[11] += iv*w2.w;
                a[12] += iv*w3.x; a[13] += iv*w3.y; a[14] += iv*w3.z; a[15] += iv*w3.w;
            }
        }
        __syncthreads();
    }
    #pragma unroll
    for (int j=0;j<16;j++){
        int co = (cg<<4)+j;
        #pragma unroll
        for (int y=0;y<4;y++)
            dst[((size_t)img*128+co)*1024 + p0 + (y<<5) + xl] = acc[y*16+j];
    }
}

// ---------------- GroupNorm(groups=1) ----------------
__global__ void gn_reduce_k(const float* __restrict__ x, float* __restrict__ stats)
{
    const int img = blockIdx.x;
    const float4* p = (const float4*)(x + (size_t)img*CHW);
    float s=0.f, s2=0.f;
    for (int i=threadIdx.x; i<32768; i+=blockDim.x){
        float4 v = p[i];
        s  += v.x+v.y+v.z+v.w;
        s2 += v.x*v.x+v.y*v.y+v.z*v.z+v.w*v.w;
    }
    #pragma unroll
    for (int o=16;o;o>>=1){
        s  += __shfl_down_sync(0xffffffffu, s , o);
        s2 += __shfl_down_sync(0xffffffffu, s2, o);
    }
    __shared__ float sa[8], sb[8];
    if ((threadIdx.x&31)==0){ sa[threadIdx.x>>5]=s; sb[threadIdx.x>>5]=s2; }
    __syncthreads();
    if (threadIdx.x==0){
        float S=0.f, S2=0.f;
        #pragma unroll
        for (int i=0;i<8;i++){ S+=sa[i]; S2+=sb[i]; }
        float mu  = S*(1.f/131072.f);
        float var = S2*(1.f/131072.f) - mu*mu;
        stats[img*2]   = mu;
        stats[img*2+1] = rsqrtf(var + 1e-5f);
    }
}

__global__ void gn_apply_k(float* __restrict__ x, const float* __restrict__ stats,
                           const float* __restrict__ gw, const float* __restrict__ gb,
                           int nimg, int act)
{
    int n4 = nimg*32768;
    for (int i = blockIdx.x*blockDim.x + threadIdx.x; i < n4; i += gridDim.x*blockDim.x){
        int base = i<<2;
        int img = base>>17; int c = (base>>10)&127;
        float mu = stats[2*img], rs = stats[2*img+1];
        float sc = rs*gw[c];
        float sh = gb[c] - mu*sc;
        float4 v = ((float4*)x)[i];
        v.x = v.x*sc+sh; v.y = v.y*sc+sh; v.z = v.z*sc+sh; v.w = v.w*sc+sh;
        if (act){
            v.x *= sigmf(v.x); v.y *= sigmf(v.y); v.z *= sigmf(v.z); v.w *= sigmf(v.w);
        }
        ((float4*)x)[i] = v;
    }
}

// ---------------- channel mean/max pooling ----------------
__global__ void pool_k(const float* __restrict__ x, float* __restrict__ pool, int nimg)
{
    int i = blockIdx.x*blockDim.x + threadIdx.x;
    if (i >= nimg*HWN) return;
    int img = i>>10, p = i&1023;
    const float* base = x + (size_t)img*CHW + p;
    float s = 0.f, m = -3.402823466e38f;
    #pragma unroll 4
    for (int c=0;c<128;c++){
        float v = base[(size_t)c<<10];
        s += v; m = fmaxf(m, v);
    }
    pool[img*2048 + p]        = s*(1.f/128.f);
    pool[img*2048 + 1024 + p] = m;
}

// ---------------- 2->1 3x3 conv + sigmoid ----------------
__global__ void saconv_k(const float* __restrict__ pool, const float* __restrict__ w,
                         const float* __restrict__ b, float* __restrict__ sa, int nimg)
{
    int i = blockIdx.x*blockDim.x + threadIdx.x;
    if (i >= nimg*HWN) return;
    int img = i>>10, p = i&1023, y = p>>5, x = p&31;
    float acc = b[0];
    #pragma unroll
    for (int c2=0;c2<2;c2++){
        #pragma unroll
        for (int dy=-1;dy<=1;dy++){
            #pragma unroll
            for (int dx=-1;dx<=1;dx++){
                int yy=y+dy, xx=x+dx;
                if ((unsigned)yy<32u && (unsigned)xx<32u)
                    acc += pool[img*2048 + c2*1024 + (yy<<5)+xx] * w[c2*9 + (dy+1)*3 + (dx+1)];
            }
        }
    }
    sa[i] = sigmf(acc);
}

// ---------------- q_fg ----------------
__global__ void qfg_k()
{
    int wid  = (blockIdx.x*blockDim.x + threadIdx.x) >> 5;
    int lane = threadIdx.x & 31;
    if (wid >= SN*BN*CH) return;
    int c = wid & 127, b = (wid>>7)&15, s = wid>>11;
    const float* qp = g_q   + ((size_t)b*128 + c)*1024;
    const float* kp = g_ksa + (size_t)(s*16+b)*1024;
    float acc = 0.f;
    for (int p=lane; p<1024; p+=32) acc += qp[p]*kp[p];
    #pragma unroll
    for (int o=16;o;o>>=1) acc += __shfl_down_sync(0xffffffffu, acc, o);
    if (!lane) g_qfg[wid] = acc*(1.f/1024.f);
}

// ---------------- s_prob ----------------
__global__ void sprob_k()
{
    int img = blockIdx.x;
    __shared__ float fq[128];
    int t = threadIdx.x;
    if (t < 128) fq[t] = g_qfg[img*128 + t];
    __syncthreads();
    for (int p=t; p<1024; p+=256){
        const float* kp = g_k + (size_t)img*CHW + p;
        float acc = 0.f;
        #pragma unroll 4
        for (int c=0;c<128;c++) acc += fq[c]*kp[(size_t)c<<10];
        g_sprob[img*1024 + p] = sigmf(acc);
    }
}

// ---------------- t logits ----------------
__global__ void tlogit_k()
{
    int img = blockIdx.x, b = img & 15;
    float acc = 0.f;
    for (int i=threadIdx.x; i<CHW; i+=256){
        int p = i & 1023;
        acc += g_q[(size_t)b*CHW + i]*g_qsa[b*1024+p]
             * g_k[(size_t)img*CHW + i]*g_ksa[img*1024+p];
    }
    #pragma unroll
    for (int o=16;o;o>>=1) acc += __shfl_down_sync(0xffffffffu, acc, o);
    __shared__ float sh[8];
    if ((threadIdx.x&31)==0) sh[threadIdx.x>>5] = acc;
    __syncthreads();
    if (threadIdx.x==0){
        float S=0.f;
        #pragma unroll
        for (int i=0;i<8;i++) S += sh[i];
        g_tl[img] = S * rsqrtf(131072.f);
    }
}

__global__ void tprob_k()
{
    int b = threadIdx.x;
    if (b >= 16) return;
    float m = -3.402823466e38f;
    #pragma unroll
    for (int s=0;s<8;s++) m = fmaxf(m, g_tl[s*16+b]);
    float e[8]; float sum = 0.f;
    #pragma unroll
    for (int s=0;s<8;s++){ e[s] = __expf(g_tl[s*16+b] - m); sum += e[s]; }
    float inv = 1.f/sum;
    #pragma unroll
    for (int s=0;s<8;s++) g_tp[s*16+b] = e[s]*inv;
}

// ---------------- av ----------------
__global__ void av_k()
{
    int i = blockIdx.x*blockDim.x + threadIdx.x;
    if (i >= BN*CHW/4) return;
    int base = i<<2;
    int b = base>>17; int c = (base>>10)&127; int p = base&1023;
    float4 acc = make_float4(0.f,0.f,0.f,0.f);
    #pragma unroll
    for (int s=0;s<8;s++){
        int img = s*16 + b;
        float tw = g_tp[img];
        float4 sp = *(const float4*)&g_sprob[img*1024 + p];
        float4 vv = *(const float4*)&g_v[((size_t)img*128 + c)*1024 + p];
        acc.x += tw*sp.x*vv.x; acc.y += tw*sp.y*vv.y;
        acc.z += tw*sp.z*vv.z; acc.w += tw*sp.w*vv.w;
    }
    *(float4*)&g_av[base] = acc;
}

// ---------------- new_out ----------------
__global__ void newout_k(const unsigned char* __restrict__ mask, float* __restrict__ out)
{
    int i = blockIdx.x*blockDim.x + threadIdx.x;
    if (i >= BN*CHW/4) return;
    int base = i<<2;
    int b = base>>17;
    float4 v = mask_at(mask, b) ? *(const float4*)&g_att[base]
                                : make_float4(0.f,0.f,0.f,0.f);
    *(float4*)&out[(size_t)2*BN*CHW + base] = v;
}

// ---------------- SE block ----------------
__global__ void semean_k()
{
    int b = blockIdx.x;
    int w = threadIdx.x>>5, lane = threadIdx.x&31;
    for (int c=w; c<128; c+=8){
        const float* p = g_o + ((size_t)b*128 + c)*1024;
        float s = 0.f;
        for (int i=lane; i<1024; i+=32) s += p[i];
        #pragma unroll
        for (int o=16;o;o>>=1) s += __shfl_down_sync(0xffffffffu, s, o);
        if (!lane) g_se1[b*128+c] = s*(1.f/1024.f);
    }
}

__global__ void sefc1_k(const float* __restrict__ w1, const float* __restrict__ b1)
{
    int t = threadIdx.x;
    int b = t>>5, j = t&31;
    float acc = b1[j];
    #pragma unroll 4
    for (int c=0;c<128;c++) acc += g_se1[b*128+c]*w1[j*128+c];
    g_se2[b*32+j] = fmaxf(acc, 0.f);
}

__global__ void sefc2_k(const float* __restrict__ w2, const float* __restrict__ b2)
{
    int i = blockIdx.x*blockDim.x + threadIdx.x;
    if (i >= BN*CH) return;
    int b = i>>7, c = i&127;
    float acc = b2[c];
    #pragma unroll
    for (int j=0;j<32;j++) acc += g_se2[b*32+j]*w2[c*32+j];
    g_se3[i] = sigmf(acc);
}

// ---------------- final ----------------
__global__ void final_k(float* __restrict__ out)
{
    int i = blockIdx.x*blockDim.x + threadIdx.x;
    if (i >= BN*CHW/4) return;
    int base = i<<2;
    int b = base>>17; int c = (base>>10)&127;
    float g = 1.f + g_se3[b*128+c];
    float4 o4 = *(const float4*)&g_o[base];
    o4.x*=g; o4.y*=g; o4.z*=g; o4.w*=g;
    *(float4*)&out[base] = o4;
    *(float4*)&out[(size_t)BN*CHW + base] = *(const float4*)&g_ht[base];
}

// ---------------- host launcher ----------------
extern "C" void kernel_launch(void* const* d_in, const int* in_sizes, int n_in,
                              void* d_out, int out_size)
{
    (void)in_sizes; (void)n_in; (void)out_size;
    const float* inputs  = (const float*)d_in[0];
    const float* hidden  = (const float*)d_in[1];
    const float* outq    = (const float*)d_in[2];
    const unsigned char* mask = (const unsigned char*)d_in[3];
    const float* enc_w   = (const float*)d_in[4];
    const float* enc_gw  = (const float*)d_in[5];
    const float* enc_gb  = (const float*)d_in[6];
    const float* qpre_w  = (const float*)d_in[7];
    const float* qpre_gw = (const float*)d_in[8];
    const float* qpre_gb = (const float*)d_in[9];
    const float* kpre_w  = (const float*)d_in[10];
    const float* kpre_gw = (const float*)d_in[11];
    const float* kpre_gb = (const float*)d_in[12];
    const float* vpre_w  = (const float*)d_in[13];
    const float* vpre_gw = (const float*)d_in[14];
    const float* vpre_gb = (const float*)d_in[15];
    const float* qsa_w   = (const float*)d_in[16];
    const float* qsa_b   = (const float*)d_in[17];
    const float* ksa_w   = (const float*)d_in[18];
    const float* ksa_b   = (const float*)d_in[19];
    const float* vpost_w = (const float*)d_in[20];
    const float* vpost_gw= (const float*)d_in[21];
    const float* vpost_gb= (const float*)d_in[22];
    const float* pos_emb = (const float*)d_in[23];
    const float* outt_w  = (const float*)d_in[24];
    const float* outt_gw = (const float*)d_in[25];
    const float* outt_gb = (const float*)d_in[26];
    const float* se_w1   = (const float*)d_in[27];
    const float* se_b1   = (const float*)d_in[28];
    const float* se_w2   = (const float*)d_in[29];
    const float* se_b2   = (const float*)d_in[30];
    float* out = (float*)d_out;

    float *ht,*q,*k,*v,*av,*att,*o,*stats,*pool,*qsa,*ksa,*peN,*wT;
    cudaGetSymbolAddress((void**)&ht,   g_ht);
    cudaGetSymbolAddress((void**)&q,    g_q);
    cudaGetSymbolAddress((void**)&k,    g_k);
    cudaGetSymbolAddress((void**)&v,    g_v);
    cudaGetSymbolAddress((void**)&av,   g_av);
    cudaGetSymbolAddress((void**)&att,  g_att);
    cudaGetSymbolAddress((void**)&o,    g_o);
    cudaGetSymbolAddress((void**)&stats,g_stats);
    cudaGetSymbolAddress((void**)&pool, g_pool);
    cudaGetSymbolAddress((void**)&qsa,  g_qsa);
    cudaGetSymbolAddress((void**)&ksa,  g_ksa);
    cudaGetSymbolAddress((void**)&peN,  g_peN);
    cudaGetSymbolAddress((void**)&wT,   g_wT);

    // wT offsets
    const int OFF_ENC   = 0;        // 64*9*128   = 73728
    const int OFF_QPRE  = 73728;    // 128*9*128  = 147456
    const int OFF_KPRE  = 221184;   // 256*9*128  = 294912
    const int OFF_VPRE  = 516096;   // 256*9*128  = 294912
    const int OFF_OUTT  = 811008;   // 192*9*128  = 221184
    const int OFF_VPOST = 1032192;  // 128*1*128  = 16384

    transw_k<<<128,256>>>(enc_w,  wT+OFF_ENC,  64, 9);
    transw_k<<<256,256>>>(qpre_w, wT+OFF_QPRE, 128, 9);
    transw_k<<<512,256>>>(kpre_w, wT+OFF_KPRE, 256, 9);
    transw_k<<<512,256>>>(vpre_w, wT+OFF_VPRE, 256, 9);
    transw_k<<<384,256>>>(outt_w, wT+OFF_OUTT, 192, 9);
    transw_k<<<64,256>>>(vpost_w, wT+OFF_VPOST, 128, 1);
    pe_norm_k<<<8,256>>>(pos_emb, peN);

    // ht = silu(gn(conv(inputs, enc_w)))
    conv3x3f2_k<<<BN*4,256>>>(inputs, nullptr, nullptr, wT+OFF_ENC, ht, 64, 0);
    gn_reduce_k<<<BN,256>>>(ht, stats);
    gn_apply_k<<<2048,256>>>(ht, stats, enc_gw, enc_gb, BN, 1);

    // q = gn(conv(ht, qpre_w))
    conv3x3f2_k<<<BN*4,256>>>(ht, nullptr, nullptr, wT+OFF_QPRE, q, 128, 0);
    gn_reduce_k<<<BN,256>>>(q, stats);
    gn_apply_k<<<2048,256>>>(q, stats, qpre_gw, qpre_gb, BN, 0);

    // k = gn(conv(kv, kpre_w))
    conv3x3f2_k<<<SBN*4,256>>>(hidden, outq, nullptr, wT+OFF_KPRE, k, 256, 1);
    gn_reduce_k<<<SBN,256>>>(k, stats);
    gn_apply_k<<<4096,256>>>(k, stats, kpre_gw, kpre_gb, SBN, 0);

    // v = gn(conv(kv + pe, vpre_w))
    conv3x3f2_k<<<SBN*4,256>>>(hidden, outq, peN, wT+OFF_VPRE, v, 256, 2);
    gn_reduce_k<<<SBN,256>>>(v, stats);
    gn_apply_k<<<4096,256>>>(v, stats, vpre_gw, vpre_gb, SBN, 0);

    // spatial filters
    pool_k<<<(BN*HWN+255)/256,256>>>(q, pool, BN);
    saconv_k<<<(BN*HWN+255)/256,256>>>(pool, qsa_w, qsa_b, qsa, BN);
    pool_k<<<(SBN*HWN+255)/256,256>>>(k, pool, SBN);
    saconv_k<<<(SBN*HWN+255)/256,256>>>(pool, ksa_w, ksa_b, ksa, SBN);

    // attention pieces
    qfg_k<<<2048,256>>>();
    sprob_k<<<SBN,256>>>();
    tlogit_k<<<SBN,256>>>();
    tprob_k<<<1,32>>>();
    av_k<<<2048,256>>>();

    // att = silu(gn(conv1x1(av, vpost_w)))
    conv1x1_k<<<BN*8,256>>>(av, wT+OFF_VPOST, att);
    gn_reduce_k<<<BN,256>>>(att, stats);
    gn_apply_k<<<2048,256>>>(att, stats, vpost_gw, vpost_gb, BN, 1);

    // new_out (output region 2)
    newout_k<<<2048,256>>>(mask, out);

    // o = silu(gn(conv(concat(inputs, att+ht), outt_w)))
    conv3x3f2_k<<<BN*4,256>>>(inputs, att, ht, wT+OFF_OUTT, o, 192, 3);
    gn_reduce_k<<<BN,256>>>(o, stats);
    gn_apply_k<<<2048,256>>>(o, stats, outt_gw, outt_gb, BN, 1);

    // SE + final outputs
    semean_k<<<BN,256>>>();
    sefc1_k<<<1,512>>>(se_w1, se_b1);
    sefc2_k<<<8,256>>>(se_w2, se_b2);
    final_k<<<2048,256>>>(out);
}

// round 3
// speedup vs baseline: 1.0070x; 1.0070x over previous
#include <cuda_runtime.h>

// ---------------- problem constants ----------------
#define BN   16
#define CH   128
#define HWN  1024
#define SN   8
#define SBN  128
#define CHW  131072        // CH*HWN

// ---------------- device scratch ----------------
__device__ float g_ht [BN*CHW];
__device__ float g_q  [BN*CHW];
__device__ float g_k  [SBN*CHW];
__device__ float g_v  [SBN*CHW];
__device__ float g_av [BN*CHW];
__device__ float g_att[BN*CHW];
__device__ float g_o  [BN*CHW];
__device__ float g_stats[2*SBN];
__device__ float g_pool[SBN*2*HWN];
__device__ float g_qsa[BN*HWN];
__device__ float g_ksa[SBN*HWN];
__device__ float g_qfg[SN*BN*CH];
__device__ float g_sprob[SBN*HWN];
__device__ float g_tl[SN*BN];
__device__ float g_tp[SN*BN];
__device__ float g_peN[SN*2*CH];
__device__ float g_se1[BN*CH];
__device__ float g_se2[BN*32];
__device__ float g_se3[BN*CH];
__device__ float g_wT[1048576];   // transposed weights, see offsets in host code

__device__ __forceinline__ float sigmf(float x){ return 1.f/(1.f + __expf(-x)); }

__device__ __forceinline__ bool mask_at(const unsigned char* m, int b){
    if (m[1] != 0) return m[b] != 0;                 // 1-byte bools
    const unsigned int* w = (const unsigned int*)m;  // 4-byte elements
    return w[b] != 0;
}

// packed fp32x2 helpers (sm_100+)
__device__ __forceinline__ void fma2(unsigned long long &d, unsigned long long a, unsigned long long b){
    asm("fma.rn.f32x2 %0, %1, %2, %0;" : "+l"(d) : "l"(a), "l"(b));
}
__device__ __forceinline__ unsigned long long bcast2(float v){
    unsigned long long r;
    asm("mov.b64 %0, {%1, %1};" : "=l"(r) : "f"(v));
    return r;
}
__device__ __forceinline__ void unpack2(unsigned long long p, float &lo, float &hi){
    asm("mov.b64 {%0, %1}, %2;" : "=f"(lo), "=f"(hi) : "l"(p));
}

// ---------------- weight transpose: (Cout,Cin,kh,kw) -> [c][tap][co] ----------------
__global__ void transw_k(const float* __restrict__ w, float* __restrict__ wT,
                         int cin, int ktaps)
{
    int n = cin*ktaps*128;
    for (int i = blockIdx.x*blockDim.x + threadIdx.x; i < n; i += gridDim.x*blockDim.x){
        int co = i & 127;
        int r  = i >> 7;
        int tap = r % ktaps;
        int c   = r / ktaps;
        wT[i] = w[(co*cin + c)*ktaps + tap];
    }
}

// ---------------- pos_emb row normalization ----------------
__global__ void pe_norm_k(const float* __restrict__ pe, float* __restrict__ peN)
{
    int s = blockIdx.x;
    int t = threadIdx.x;
    float v = pe[s*256 + t];
    float q = v*v;
    #pragma unroll
    for (int o=16;o;o>>=1) q += __shfl_down_sync(0xffffffffu, q, o);
    __shared__ float a[8];
    __shared__ float fac;
    if ((t&31)==0) a[t>>5] = q;
    __syncthreads();
    if (t==0){
        float S=0.f;
        #pragma unroll
        for (int i=0;i<8;i++) S += a[i];
        float n = sqrtf(S);
        fac = fminf(1.f, 1.f/fmaxf(n, 1e-7f));
    }
    __syncthreads();
    peN[s*256 + t] = v*fac;
}

// ---------------- 3x3 conv, pad=1, Cout=128, f32x2 pipe ----------------
// block: 256 thr = 32 x-lanes * 8 co-groups(16 co). Each thread: 8 y-rows x 16 couts.
// grid: nimg*4 (8-row tiles).
// modes: 0 single src; 1 concat(s0,s1); 2 concat+pe(s2); 3 concat(inputs64, s1+s2)
__global__ __launch_bounds__(256,1)
void conv3x3f2_k(const float* __restrict__ s0, const float* __restrict__ s1,
                 const float* __restrict__ s2, const float* __restrict__ wT,
                 float* __restrict__ dst, int cin, int mode)
{
    __shared__ float sIn[8*10*34];   // 2720 floats: 8 ci x (8+2 halo rows) x 34
    __shared__ float sW [8*9*128];   // 9216 floats
    const int t   = threadIdx.x;
    const int img = blockIdx.x >> 2;
    const int y0  = (blockIdx.x & 3) << 3;
    const int x   = t & 31;
    const int cg  = t >> 5;

    unsigned long long acc[64];      // [y][co-pair] packed f32x2
    #pragma unroll
    for (int i=0;i<64;i++) acc[i]=0ull;

    const int nchunk = cin >> 3;
    for (int cc=0; cc<nchunk; cc++){
        // stage weights: 9216 floats = 2304 float4
        {
            const float4* wp = (const float4*)(wT + cc*9216);
            #pragma unroll
            for (int e=0;e<9;e++) ((float4*)sW)[t + (e<<8)] = wp[t + (e<<8)];
        }
        // stage inputs: 8 ci x 10 rows x 34
        for (int e=t; e<2720; e+=256){
            int ci = e/340; int rem = e - ci*340;
            int r  = rem/34; int xx = rem - r*34;
            int y  = y0 - 1 + r; int xg = xx - 1;
            float val = 0.f;
            if ((unsigned)y < 32u && (unsigned)xg < 32u){
                int c = (cc<<3) + ci;
                int p = (y<<5) + xg;
                if (mode == 0){
                    val = s0[((size_t)img*cin + c)*1024 + p];
                } else if (mode == 1){
                    val = (c < 128) ? s0[((size_t)img*128 + c)*1024 + p]
                                    : s1[((size_t)img*128 + (c-128))*1024 + p];
                } else if (mode == 2){
                    float bv = (c < 128) ? s0[((size_t)img*128 + c)*1024 + p]
                                         : s1[((size_t)img*128 + (c-128))*1024 + p];
                    val = bv + s2[(img>>4)*256 + c];
                } else {
                    val = (c < 64) ? s0[((size_t)img*64 + c)*1024 + p]
                                   : s1[((size_t)img*128 + (c-64))*1024 + p]
                                   + s2[((size_t)img*128 + (c-64))*1024 + p];
                }
            }
            sIn[(ci*10 + r)*34 + xx] = val;
        }
        __syncthreads();
        #pragma unroll 1
        for (int ci=0; ci<8; ci++){
            float inr[30];
            #pragma unroll
            for (int r=0;r<10;r++){
                #pragma unroll
                for (int d=0;d<3;d++) inr[r*3+d] = sIn[(ci*10+r)*34 + x + d];
            }
            #pragma unroll
            for (int tap=0; tap<9; tap++){
                const int dy = tap/3, dx = tap - dy*3;
                const ulonglong2* wq = (const ulonglong2*)&sW[(ci*9+tap)*128 + (cg<<4)];
                ulonglong2 wa = wq[0], wb = wq[1], wc = wq[2], wd = wq[3];
                #pragma unroll
                for (int y=0;y<8;y++){
                    unsigned long long iv2 = bcast2(inr[(y+dy)*3 + dx]);
                    unsigned long long* a = &acc[y*8];
                    fma2(a[0], iv2, wa.x); fma2(a[1], iv2, wa.y);
                    fma2(a[2], iv2, wb.x); fma2(a[3], iv2, wb.y);
                    fma2(a[4], iv2, wc.x); fma2(a[5], iv2, wc.y);
                    fma2(a[6], iv2, wd.x); fma2(a[7], iv2, wd.y);
                }
            }
        }
        __syncthreads();
    }
    // store: acc[y*8+j] -> co = cg*16 + 2j, 2j+1
    #pragma unroll
    for (int j=0;j<8;j++){
        int co = (cg<<4) + (j<<1);
        float* d0 = dst + ((size_t)img*128 + co)*1024 + (y0<<5) + x;
        float* d1 = d0 + 1024;
        #pragma unroll
        for (int y=0;y<8;y++){
            float lo, hi;
            unpack2(acc[y*8+j], lo, hi);
            d0[y<<5] = lo;
            d1[y<<5] = hi;
        }
    }
}

// ---------------- 1x1 conv (vpost), 128->128 ----------------
__global__ __launch_bounds__(256,2)
void conv1x1_k(const float* __restrict__ src, const float* __restrict__ wT,
               float* __restrict__ dst)
{
    __shared__ float sIn[8*128];
    __shared__ float sW [8*128];
    const int t   = threadIdx.x;
    const int img = blockIdx.x >> 3;
    const int p0  = (blockIdx.x & 7) << 7;
    const int xl  = t & 31;
    const int cg  = t >> 5;
    float acc[64];
    #pragma unroll
    for (int i=0;i<64;i++) acc[i]=0.f;

    for (int cc=0; cc<16; cc++){
        for (int e=t; e<1024; e+=256){
            int ci = e>>7, i = e&127;
            sIn[e] = src[((size_t)img*128 + (cc<<3)+ci)*1024 + p0 + i];
            sW [e] = wT[(cc<<10) + e];
        }
        __syncthreads();
        #pragma unroll
        for (int ci=0;ci<8;ci++){
            float inr[4];
            #pragma unroll
            for (int y=0;y<4;y++) inr[y] = sIn[ci*128 + (y<<5) + xl];
            const float4* wq = (const float4*)&sW[ci*128 + (cg<<4)];
            float4 w0=wq[0], w1=wq[1], w2=wq[2], w3=wq[3];
            #pragma unroll
            for (int y=0;y<4;y++){
                float iv = inr[y];
                float* a = &acc[y*16];
                a[0]  += iv*w0.x; a[1]  += iv*w0.y; a[2]  += iv*w0.z; a[3]  += iv*w0.w;
                a[4]  += iv*w1.x; a[5]  += iv*w1.y; a[6]  += iv*w1.z; a[7]  += iv*w1.w;
                a[8]  += iv*w2.x; a[9]  += iv*w2.y; a[10] += iv*w2.z; a[11] += iv*w2.w;
                a[12] += iv*w3.x; a[13] += iv*w3.y; a[14] += iv*w3.z; a[15] += iv*w3.w;
            }
        }
        __syncthreads();
    }
    #pragma unroll
    for (int j=0;j<16;j++){
        int co = (cg<<4)+j;
        #pragma unroll
        for (int y=0;y<4;y++)
            dst[((size_t)img*128+co)*1024 + p0 + (y<<5) + xl] = acc[y*16+j];
    }
}

// ---------------- GroupNorm(groups=1) ----------------
__global__ void gn_reduce_k(const float* __restrict__ x, float* __restrict__ stats)
{
    const int img = blockIdx.x;
    const float4* p = (const float4*)(x + (size_t)img*CHW);
    float s=0.f, s2=0.f;
    for (int i=threadIdx.x; i<32768; i+=blockDim.x){
        float4 v = p[i];
        s  += v.x+v.y+v.z+v.w;
        s2 += v.x*v.x+v.y*v.y+v.z*v.z+v.w*v.w;
    }
    #pragma unroll
    for (int o=16;o;o>>=1){
        s  += __shfl_down_sync(0xffffffffu, s , o);
        s2 += __shfl_down_sync(0xffffffffu, s2, o);
    }
    __shared__ float sa[8], sb[8];
    if ((threadIdx.x&31)==0){ sa[threadIdx.x>>5]=s; sb[threadIdx.x>>5]=s2; }
    __syncthreads();
    if (threadIdx.x==0){
        float S=0.f, S2=0.f;
        #pragma unroll
        for (int i=0;i<8;i++){ S+=sa[i]; S2+=sb[i]; }
        float mu  = S*(1.f/131072.f);
        float var = S2*(1.f/131072.f) - mu*mu;
        stats[img*2]   = mu;
        stats[img*2+1] = rsqrtf(var + 1e-5f);
    }
}

__global__ void gn_apply_k(float* __restrict__ x, const float* __restrict__ stats,
                           const float* __restrict__ gw, const float* __restrict__ gb,
                           int nimg, int act)
{
    int n4 = nimg*32768;
    for (int i = blockIdx.x*blockDim.x + threadIdx.x; i < n4; i += gridDim.x*blockDim.x){
        int base = i<<2;
        int img = base>>17; int c = (base>>10)&127;
        float mu = stats[2*img], rs = stats[2*img+1];
        float sc = rs*gw[c];
        float sh = gb[c] - mu*sc;
        float4 v = ((float4*)x)[i];
        v.x = v.x*sc+sh; v.y = v.y*sc+sh; v.z = v.z*sc+sh; v.w = v.w*sc+sh;
        if (act){
            v.x *= sigmf(v.x); v.y *= sigmf(v.y); v.z *= sigmf(v.z); v.w *= sigmf(v.w);
        }
        ((float4*)x)[i] = v;
    }
}

// ---------------- channel mean/max pooling ----------------
__global__ void pool_k(const float* __restrict__ x, float* __restrict__ pool, int nimg)
{
    int i = blockIdx.x*blockDim.x + threadIdx.x;
    if (i >= nimg*HWN) return;
    int img = i>>10, p = i&1023;
    const float* base = x + (size_t)img*CHW + p;
    float s = 0.f, m = -3.402823466e38f;
    #pragma unroll 4
    for (int c=0;c<128;c++){
        float v = base[(size_t)c<<10];
        s += v; m = fmaxf(m, v);
    }
    pool[img*2048 + p]        = s*(1.f/128.f);
    pool[img*2048 + 1024 + p] = m;
}

// ---------------- 2->1 3x3 conv + sigmoid ----------------
__global__ void saconv_k(const float* __restrict__ pool, const float* __restrict__ w,
                         const float* __restrict__ b, float* __restrict__ sa, int nimg)
{
    int i = blockIdx.x*blockDim.x + threadIdx.x;
    if (i >= nimg*HWN) return;
    int img = i>>10, p = i&1023, y = p>>5, x = p&31;
    float acc = b[0];
    #pragma unroll
    for (int c2=0;c2<2;c2++){
        #pragma unroll
        for (int dy=-1;dy<=1;dy++){
            #pragma unroll
            for (int dx=-1;dx<=1;dx++){
                int yy=y+dy, xx=x+dx;
                if ((unsigned)yy<32u && (unsigned)xx<32u)
                    acc += pool[img*2048 + c2*1024 + (yy<<5)+xx] * w[c2*9 + (dy+1)*3 + (dx+1)];
            }
        }
    }
    sa[i] = sigmf(acc);
}

// ---------------- q_fg ----------------
__global__ void qfg_k()
{
    int wid  = (blockIdx.x*blockDim.x + threadIdx.x) >> 5;
    int lane = threadIdx.x & 31;
    if (wid >= SN*BN*CH) return;
    int c = wid & 127, b = (wid>>7)&15, s = wid>>11;
    const float* qp = g_q   + ((size_t)b*128 + c)*1024;
    const float* kp = g_ksa + (size_t)(s*16+b)*1024;
    float acc = 0.f;
    for (int p=lane; p<1024; p+=32) acc += qp[p]*kp[p];
    #pragma unroll
    for (int o=16;o;o>>=1) acc += __shfl_down_sync(0xffffffffu, acc, o);
    if (!lane) g_qfg[wid] = acc*(1.f/1024.f);
}

// ---------------- s_prob ----------------
__global__ void sprob_k()
{
    int img = blockIdx.x;
    __shared__ float fq[128];
    int t = threadIdx.x;
    if (t < 128) fq[t] = g_qfg[img*128 + t];
    __syncthreads();
    for (int p=t; p<1024; p+=256){
        const float* kp = g_k + (size_t)img*CHW + p;
        float acc = 0.f;
        #pragma unroll 4
        for (int c=0;c<128;c++) acc += fq[c]*kp[(size_t)c<<10];
        g_sprob[img*1024 + p] = sigmf(acc);
    }
}

// ---------------- t logits ----------------
__global__ void tlogit_k()
{
    int img = blockIdx.x, b = img & 15;
    float acc = 0.f;
    for (int i=threadIdx.x; i<CHW; i+=256){
        int p = i & 1023;
        acc += g_q[(size_t)b*CHW + i]*g_qsa[b*1024+p]
             * g_k[(size_t)img*CHW + i]*g_ksa[img*1024+p];
    }
    #pragma unroll
    for (int o=16;o;o>>=1) acc += __shfl_down_sync(0xffffffffu, acc, o);
    __shared__ float sh[8];
    if ((threadIdx.x&31)==0) sh[threadIdx.x>>5] = acc;
    __syncthreads();
    if (threadIdx.x==0){
        float S=0.f;
        #pragma unroll
        for (int i=0;i<8;i++) S += sh[i];
        g_tl[img] = S * rsqrtf(131072.f);
    }
}

__global__ void tprob_k()
{
    int b = threadIdx.x;
    if (b >= 16) return;
    float m = -3.402823466e38f;
    #pragma unroll
    for (int s=0;s<8;s++) m = fmaxf(m, g_tl[s*16+b]);
    float e[8]; float sum = 0.f;
    #pragma unroll
    for (int s=0;s<8;s++){ e[s] = __expf(g_tl[s*16+b] - m); sum += e[s]; }
    float inv = 1.f/sum;
    #pragma unroll
    for (int s=0;s<8;s++) g_tp[s*16+b] = e[s]*inv;
}

// ---------------- av ----------------
__global__ void av_k()
{
    int i = blockIdx.x*blockDim.x + threadIdx.x;
    if (i >= BN*CHW/4) return;
    int base = i<<2;
    int b = base>>17; int c = (base>>10)&127; int p = base&1023;
    float4 acc = make_float4(0.f,0.f,0.f,0.f);
    #pragma unroll
    for (int s=0;s<8;s++){
        int img = s*16 + b;
        float tw = g_tp[img];
        float4 sp = *(const float4*)&g_sprob[img*1024 + p];
        float4 vv = *(const float4*)&g_v[((size_t)img*128 + c)*1024 + p];
        acc.x += tw*sp.x*vv.x; acc.y += tw*sp.y*vv.y;
        acc.z += tw*sp.z*vv.z; acc.w += tw*sp.w*vv.w;
    }
    *(float4*)&g_av[base] = acc;
}

// ---------------- new_out ----------------
__global__ void newout_k(const unsigned char* __restrict__ mask, float* __restrict__ out)
{
    int i = blockIdx.x*blockDim.x + threadIdx.x;
    if (i >= BN*CHW/4) return;
    int base = i<<2;
    int b = base>>17;
    float4 v = mask_at(mask, b) ? *(const float4*)&g_att[base]
                                : make_float4(0.f,0.f,0.f,0.f);
    *(float4*)&out[(size_t)2*BN*CHW + base] = v;
}

// ---------------- SE block ----------------
__global__ void semean_k()
{
    int b = blockIdx.x;
    int w = threadIdx.x>>5, lane = threadIdx.x&31;
    for (int c=w; c<128; c+=8){
        const float* p = g_o + ((size_t)b*128 + c)*1024;
        float s = 0.f;
        for (int i=lane; i<1024; i+=32) s += p[i];
        #pragma unroll
        for (int o=16;o;o>>=1) s += __shfl_down_sync(0xffffffffu, s, o);
        if (!lane) g_se1[b*128+c] = s*(1.f/1024.f);
    }
}

__global__ void sefc1_k(const float* __restrict__ w1, const float* __restrict__ b1)
{
    int t = threadIdx.x;
    int b = t>>5, j = t&31;
    float acc = b1[j];
    #pragma unroll 4
    for (int c=0;c<128;c++) acc += g_se1[b*128+c]*w1[j*128+c];
    g_se2[b*32+j] = fmaxf(acc, 0.f);
}

__global__ void sefc2_k(const float* __restrict__ w2, const float* __restrict__ b2)
{
    int i = blockIdx.x*blockDim.x + threadIdx.x;
    if (i >= BN*CH) return;
    int b = i>>7, c = i&127;
    float acc = b2[c];
    #pragma unroll
    for (int j=0;j<32;j++) acc += g_se2[b*32+j]*w2[c*32+j];
    g_se3[i] = sigmf(acc);
}

// ---------------- final ----------------
__global__ void final_k(float* __restrict__ out)
{
    int i = blockIdx.x*blockDim.x + threadIdx.x;
    if (i >= BN*CHW/4) return;
    int base = i<<2;
    int b = base>>17; int c = (base>>10)&127;
    float g = 1.f + g_se3[b*128+c];
    float4 o4 = *(const float4*)&g_o[base];
    o4.x*=g; o4.y*=g; o4.z*=g; o4.w*=g;
    *(float4*)&out[base] = o4;
    *(float4*)&out[(size_t)BN*CHW + base] = *(const float4*)&g_ht[base];
}

// ---------------- host launcher ----------------
extern "C" void kernel_launch(void* const* d_in, const int* in_sizes, int n_in,
                              void* d_out, int out_size)
{
    (void)in_sizes; (void)n_in; (void)out_size;
    const float* inputs  = (const float*)d_in[0];
    const float* hidden  = (const float*)d_in[1];
    const float* outq    = (const float*)d_in[2];
    const unsigned char* mask = (const unsigned char*)d_in[3];
    const float* enc_w   = (const float*)d_in[4];
    const float* enc_gw  = (const float*)d_in[5];
    const float* enc_gb  = (const float*)d_in[6];
    const float* qpre_w  = (const float*)d_in[7];
    const float* qpre_gw = (const float*)d_in[8];
    const float* qpre_gb = (const float*)d_in[9];
    const float* kpre_w  = (const float*)d_in[10];
    const float* kpre_gw = (const float*)d_in[11];
    const float* kpre_gb = (const float*)d_in[12];
    const float* vpre_w  = (const float*)d_in[13];
    const float* vpre_gw = (const float*)d_in[14];
    const float* vpre_gb = (const float*)d_in[15];
    const float* qsa_w   = (const float*)d_in[16];
    const float* qsa_b   = (const float*)d_in[17];
    const float* ksa_w   = (const float*)d_in[18];
    const float* ksa_b   = (const float*)d_in[19];
    const float* vpost_w = (const float*)d_in[20];
    const float* vpost_gw= (const float*)d_in[21];
    const float* vpost_gb= (const float*)d_in[22];
    const float* pos_emb = (const float*)d_in[23];
    const float* outt_w  = (const float*)d_in[24];
    const float* outt_gw = (const float*)d_in[25];
    const float* outt_gb = (const float*)d_in[26];
    const float* se_w1   = (const float*)d_in[27];
    const float* se_b1   = (const float*)d_in[28];
    const float* se_w2   = (const float*)d_in[29];
    const float* se_b2   = (const float*)d_in[30];
    float* out = (float*)d_out;

    float *ht,*q,*k,*v,*av,*att,*o,*stats,*pool,*qsa,*ksa,*peN,*wT;
    cudaGetSymbolAddress((void**)&ht,   g_ht);
    cudaGetSymbolAddress((void**)&q,    g_q);
    cudaGetSymbolAddress((void**)&k,    g_k);
    cudaGetSymbolAddress((void**)&v,    g_v);
    cudaGetSymbolAddress((void**)&av,   g_av);
    cudaGetSymbolAddress((void**)&att,  g_att);
    cudaGetSymbolAddress((void**)&o,    g_o);
    cudaGetSymbolAddress((void**)&stats,g_stats);
    cudaGetSymbolAddress((void**)&pool, g_pool);
    cudaGetSymbolAddress((void**)&qsa,  g_qsa);
    cudaGetSymbolAddress((void**)&ksa,  g_ksa);
    cudaGetSymbolAddress((void**)&peN,  g_peN);
    cudaGetSymbolAddress((void**)&wT,   g_wT);

    // wT offsets
    const int OFF_ENC   = 0;        // 64*9*128   = 73728
    const int OFF_QPRE  = 73728;    // 128*9*128  = 147456
    const int OFF_KPRE  = 221184;   // 256*9*128  = 294912
    const int OFF_VPRE  = 516096;   // 256*9*128  = 294912
    const int OFF_OUTT  = 811008;   // 192*9*128  = 221184
    const int OFF_VPOST = 1032192;  // 128*1*128  = 16384

    transw_k<<<128,256>>>(enc_w,  wT+OFF_ENC,  64, 9);
    transw_k<<<256,256>>>(qpre_w, wT+OFF_QPRE, 128, 9);
    transw_k<<<512,256>>>(kpre_w, wT+OFF_KPRE, 256, 9);
    transw_k<<<512,256>>>(vpre_w, wT+OFF_VPRE, 256, 9);
    transw_k<<<384,256>>>(outt_w, wT+OFF_OUTT, 192, 9);
    transw_k<<<64,256>>>(vpost_w, wT+OFF_VPOST, 128, 1);
    pe_norm_k<<<8,256>>>(pos_emb, peN);

    // ht = silu(gn(conv(inputs, enc_w)))
    conv3x3f2_k<<<BN*4,256>>>(inputs, nullptr, nullptr, wT+OFF_ENC, ht, 64, 0);
    gn_reduce_k<<<BN,256>>>(ht, stats);
    gn_apply_k<<<2048,256>>>(ht, stats, enc_gw, enc_gb, BN, 1);

    // q = gn(conv(ht, qpre_w))
    conv3x3f2_k<<<BN*4,256>>>(ht, nullptr, nullptr, wT+OFF_QPRE, q, 128, 0);
    gn_reduce_k<<<BN,256>>>(q, stats);
    gn_apply_k<<<2048,256>>>(q, stats, qpre_gw, qpre_gb, BN, 0);

    // k = gn(conv(kv, kpre_w))
    conv3x3f2_k<<<SBN*4,256>>>(hidden, outq, nullptr, wT+OFF_KPRE, k, 256, 1);
    gn_reduce_k<<<SBN,256>>>(k, stats);
    gn_apply_k<<<4096,256>>>(k, stats, kpre_gw, kpre_gb, SBN, 0);

    // v = gn(conv(kv + pe, vpre_w))
    conv3x3f2_k<<<SBN*4,256>>>(hidden, outq, peN, wT+OFF_VPRE, v, 256, 2);
    gn_reduce_k<<<SBN,256>>>(v, stats);
    gn_apply_k<<<4096,256>>>(v, stats, vpre_gw, vpre_gb, SBN, 0);

    // spatial filters
    pool_k<<<(BN*HWN+255)/256,256>>>(q, pool, BN);
    saconv_k<<<(BN*HWN+255)/256,256>>>(pool, qsa_w, qsa_b, qsa, BN);
    pool_k<<<(SBN*HWN+255)/256,256>>>(k, pool, SBN);
    saconv_k<<<(SBN*HWN+255)/256,256>>>(pool, ksa_w, ksa_b, ksa, SBN);

    // attention pieces
    qfg_k<<<2048,256>>>();
    sprob_k<<<SBN,256>>>();
    tlogit_k<<<SBN,256>>>();
    tprob_k<<<1,32>>>();
    av_k<<<2048,256>>>();

    // att = silu(gn(conv1x1(av, vpost_w)))
    conv1x1_k<<<BN*8,256>>>(av, wT+OFF_VPOST, att);
    gn_reduce_k<<<BN,256>>>(att, stats);
    gn_apply_k<<<2048,256>>>(att, stats, vpost_gw, vpost_gb, BN, 1);

    // new_out (output region 2)
    newout_k<<<2048,256>>>(mask, out);

    // o = silu(gn(conv(concat(inputs, att+ht), outt_w)))
    conv3x3f2_k<<<BN*4,256>>>(inputs, att, ht, wT+OFF_OUTT, o, 192, 3);
    gn_reduce_k<<<BN,256>>>(o, stats);
    gn_apply_k<<<2048,256>>>(o, stats, outt_gw, outt_gb, BN, 1);

    // SE + final outputs
    semean_k<<<BN,256>>>();
    sefc1_k<<<1,512>>>(se_w1, se_b1);
    sefc2_k<<<8,256>>>(se_w2, se_b2);
    final_k<<<2048,256>>>(out);
}

// round 5
// speedup vs baseline: 1.3713x; 1.3617x over previous
#include <cuda_runtime.h>
#include <cuda_bf16.h>
#include <cstdint>

#define BN   16
#define CH   128
#define HWN  1024
#define SN   8
#define SBN  128
#define CHW  131072

#define GUARD   64
#define RPI     1344
#define TOTROWS (GUARD + 128*RPI)

// smem layout for mmaconv (bf16 units): A stride 136/row, X stride 136/row
#define SA_H 0
#define SA_L 17408
#define SX_H 34816
#define SX_L 69632
#define DSMEM_TOTAL 208896   // 104448 bf16 * 2B

__device__ float g_ht [BN*CHW];
__device__ float g_q  [BN*CHW];
__device__ float g_k  [SBN*CHW];
__device__ float g_v  [SBN*CHW];
__device__ float g_av [BN*CHW];
__device__ float g_att[BN*CHW];
__device__ float g_o  [BN*CHW];
__device__ float g_stats[2*SBN];
__device__ float g_pool[SBN*2*HWN];
__device__ float g_qsa[BN*HWN];
__device__ float g_ksa[SBN*HWN];
__device__ float g_qfg[SN*BN*CH];
__device__ float g_sprob[SBN*HWN];
__device__ float g_tl[SN*BN];
__device__ float g_tp[SN*BN];
__device__ float g_peN[SN*2*CH];
__device__ float g_se1[BN*CH];
__device__ float g_se2[BN*32];
__device__ float g_se3[BN*CH];
__device__ float g_Pb[SN*CH*9];
__device__ float g_wT[524288];
__device__ __nv_bfloat16 g_nhwc[(size_t)2*TOTROWS*256];
__device__ __nv_bfloat16 g_wrep[1179648];  // 2 convs x [sp][tap][kc][co][128]

__device__ __forceinline__ float sigmf(float x){ return 1.f/(1.f + __expf(-x)); }
__device__ __forceinline__ bool mask_at(const unsigned char* m, int b){
    if (m[1] != 0) return m[b] != 0;
    const unsigned int* w = (const unsigned int*)m;
    return w[b] != 0;
}

__device__ __forceinline__ void mma16816(float* d, uint32_t a0, uint32_t a1, uint32_t a2,
                                         uint32_t a3, uint32_t b0, uint32_t b1){
    asm volatile("mma.sync.aligned.m16n8k16.row.col.f32.bf16.bf16.f32 "
        "{%0,%1,%2,%3}, {%4,%5,%6,%7}, {%8,%9}, {%0,%1,%2,%3};"
        : "+f"(d[0]),"+f"(d[1]),"+f"(d[2]),"+f"(d[3])
        : "r"(a0),"r"(a1),"r"(a2),"r"(a3),"r"(b0),"r"(b1));
}
__device__ __forceinline__ uint32_t lds32(const __nv_bfloat16* p, int off){
    return *(const uint32_t*)(p + off);
}

// ---- weight transpose for FFMA convs ----
__global__ void transw_k(const float* __restrict__ w, float* __restrict__ wT,
                         int cin, int ktaps)
{
    int n = cin*ktaps*128;
    for (int i = blockIdx.x*blockDim.x + threadIdx.x; i < n; i += gridDim.x*blockDim.x){
        int co = i & 127;
        int r  = i >> 7;
        int tap = r % ktaps;
        int c   = r / ktaps;
        wT[i] = w[(co*cin + c)*ktaps + tap];
    }
}

__global__ void pe_norm_k(const float* __restrict__ pe, float* __restrict__ peN)
{
    int s = blockIdx.x, t = threadIdx.x;
    float v = pe[s*256 + t];
    float q = v*v;
    #pragma unroll
    for (int o=16;o;o>>=1) q += __shfl_down_sync(0xffffffffu, q, o);
    __shared__ float a[8];
    __shared__ float fac;
    if ((t&31)==0) a[t>>5] = q;
    __syncthreads();
    if (t==0){
        float S=0.f;
        #pragma unroll
        for (int i=0;i<8;i++) S += a[i];
        float n = sqrtf(S);
        fac = fminf(1.f, 1.f/fmaxf(n, 1e-7f));
    }
    __syncthreads();
    peN[s*256 + t] = v*fac;
}

// ---- NHWC bf16 hi/lo repack ----
__global__ void zero_nhwc_k()
{
    size_t n = ((size_t)2*TOTROWS*256*2)/16;
    uint4 z = make_uint4(0,0,0,0);
    uint4* p = (uint4*)g_nhwc;
    for (size_t i = (size_t)blockIdx.x*blockDim.x + threadIdx.x; i < n;
         i += (size_t)gridDim.x*blockDim.x) p[i] = z;
}

__global__ void fill_nhwc_k(const float* __restrict__ hid, const float* __restrict__ oq)
{
    __shared__ float s[8][33];
    int t = threadIdx.x;
    int img = blockIdx.x>>5, y = blockIdx.x&31;
    int xg = t&31, cg = t>>5;
    int xs = t>>3, cl = t&7;
    size_t rb = GUARD + (size_t)img*RPI + (size_t)(y+1)*34;
    for (int cc=0; cc<32; cc++){
        int c = cc*8 + cg;
        const float* src = (c<128) ? hid + ((size_t)img*128 + c)*1024
                                   : oq  + ((size_t)img*128 + (c-128))*1024;
        s[cg][xg] = src[y*32 + xg];
        __syncthreads();
        float v = s[cl][xs];
        __nv_bfloat16 h = __float2bfloat16(v);
        __nv_bfloat16 l = __float2bfloat16(v - __bfloat162float(h));
        size_t off = (rb + xs + 1)*256 + cc*8 + cl;
        g_nhwc[off] = h;
        g_nhwc[(size_t)TOTROWS*256 + off] = l;
        __syncthreads();
    }
}

// ---- weight repack: [sp][tap][kc][co][128k] bf16 hi/lo ----
__global__ void wrep_k(const float* __restrict__ w, __nv_bfloat16* __restrict__ dst)
{
    int i = blockIdx.x*blockDim.x + threadIdx.x;
    if (i >= 294912) return;
    int kl = i & 127;
    int r = i >> 7;
    int co = r & 127; r >>= 7;
    int kc = r & 1;   r >>= 1;
    int tap = r;
    int cin = kc*128 + kl;
    float val = w[((size_t)co*256 + cin)*9 + tap];
    __nv_bfloat16 h = __float2bfloat16(val);
    int o = ((tap*2+kc)*128 + co)*128 + kl;
    dst[o] = h;
    dst[294912 + o] = __float2bfloat16(val - __bfloat162float(h));
}

// ---- pe correction with border masks: Pb[s][co][yc*3+xc] ----
__global__ void pbconv_k(const float* __restrict__ w)
{
    int s = blockIdx.x, co = threadIdx.x;
    float P[9];
    #pragma unroll
    for (int tap=0;tap<9;tap++){
        float acc = 0.f;
        for (int c=0;c<256;c++)
            acc += g_peN[s*256 + c] * w[((size_t)co*256 + c)*9 + tap];
        P[tap] = acc;
    }
    #pragma unroll
    for (int yc=0;yc<3;yc++){
        #pragma unroll
        for (int xc=0;xc<3;xc++){
            float tot = 0.f;
            #pragma unroll
            for (int dy=0;dy<3;dy++){
                if ((yc==0 && dy==0) || (yc==2 && dy==2)) continue;
                float rs = P[dy*3+1];
                if (xc!=0) rs += P[dy*3+0];
                if (xc!=2) rs += P[dy*3+2];
                tot += rs;
            }
            g_Pb[(s*128+co)*9 + yc*3+xc] = tot;
        }
    }
}

// ---- mma.sync bf16 implicit conv: D[128co,256px] ----
__global__ __launch_bounds__(256,1)
void mmaconv_k(const __nv_bfloat16* __restrict__ wrep,
               const float* __restrict__ Pb,
               float* __restrict__ dst)
{
    extern __shared__ __nv_bfloat16 sm[];
    const int t = threadIdx.x;
    const int wid = t>>5, lane = t&31;
    const int img = blockIdx.x/5;
    const int p0  = (blockIdx.x%5)*256;
    const int s   = img>>4;
    const int g   = lane>>2;
    const int t2  = (lane&3)*2;
    const int cob = (wid&1)*64;
    const int pxb = (wid>>1)*64;

    float acc[4][8][4];
    #pragma unroll
    for (int mi=0;mi<4;mi++)
    #pragma unroll
    for (int ni=0;ni<8;ni++)
    #pragma unroll
    for (int e=0;e<4;e++) acc[mi][ni][e]=0.f;

    for (int kc=0;kc<2;kc++)
    for (int tap=0;tap<9;tap++){
        // stage A (weights): 2 splits x 128co x 128k
        #pragma unroll
        for (int sp=0;sp<2;sp++){
            const __nv_bfloat16* src = wrep + (size_t)sp*294912 + (size_t)(tap*2+kc)*16384;
            __nv_bfloat16* db = sm + sp*17408;
            #pragma unroll
            for (int r=0;r<8;r++){
                int idx = r*256 + t;
                int row = idx>>4, seg = idx&15;
                uint4 val = *(const uint4*)(src + row*128 + seg*8);
                *(uint4*)(db + row*136 + seg*8) = val;
            }
        }
        // stage X (pixels, tap-shifted rows): 2 splits x 256px x 128k
        {
            int dy = tap/3, dx = tap - dy*3;
            long rowbase = GUARD + (long)img*RPI + p0 + (dy-1)*34 + (dx-1);
            #pragma unroll
            for (int sp=0;sp<2;sp++){
                const __nv_bfloat16* src = g_nhwc + ((size_t)sp*TOTROWS + rowbase)*256 + kc*128;
                __nv_bfloat16* db = sm + SX_H + sp*34816;
                #pragma unroll
                for (int r=0;r<16;r++){
                    int idx = r*256 + t;
                    int row = idx>>4, seg = idx&15;
                    uint4 val = *(const uint4*)(src + (size_t)row*256 + seg*8);
                    *(uint4*)(db + row*136 + seg*8) = val;
                }
            }
        }
        __syncthreads();
        // 3 products: (Ah,Xh), (Al,Xh), (Ah,Xl)
        #pragma unroll
        for (int pr=0;pr<3;pr++){
            const __nv_bfloat16* sa = sm + ((pr==1) ? SA_L : SA_H);
            const __nv_bfloat16* sx = sm + ((pr==2) ? SX_L : SX_H);
            #pragma unroll
            for (int k8=0;k8<8;k8++){
                int k = k8*16 + t2;
                uint32_t af[4][4];
                #pragma unroll
                for (int mi=0;mi<4;mi++){
                    int r0 = (cob + mi*16 + g)*136;
                    af[mi][0] = lds32(sa, r0 + k);
                    af[mi][1] = lds32(sa, r0 + 8*136 + k);
                    af[mi][2] = lds32(sa, r0 + k + 8);
                    af[mi][3] = lds32(sa, r0 + 8*136 + k + 8);
                }
                #pragma unroll
                for (int ni=0;ni<8;ni++){
                    int n0 = (pxb + ni*8 + g)*136;
                    uint32_t b0 = lds32(sx, n0 + k);
                    uint32_t b1 = lds32(sx, n0 + k + 8);
                    #pragma unroll
                    for (int mi=0;mi<4;mi++)
                        mma16816(acc[mi][ni], af[mi][0],af[mi][1],af[mi][2],af[mi][3], b0,b1);
                }
            }
        }
        __syncthreads();
    }

    // epilogue: direct register -> global stores with border mask + Pb correction
    #pragma unroll
    for (int mi=0;mi<4;mi++){
        #pragma unroll
        for (int ni=0;ni<8;ni++){
            #pragma unroll
            for (int e=0;e<4;e++){
                int co  = cob + mi*16 + g + ((e>>1)<<3);
                int col = pxb + ni*8 + t2 + (e&1);
                int pp  = p0 + col;
                int q34 = pp/34;
                int yy  = q34 - 1;
                int xx  = pp - q34*34 - 1;
                if ((unsigned)yy < 32u && (unsigned)xx < 32u){
                    float v = acc[mi][ni][e];
                    if (Pb){
                        int yc = (yy==0)?0:((yy==31)?2:1);
                        int xc = (xx==0)?0:((xx==31)?2:1);
                        v += Pb[(s*128+co)*9 + yc*3+xc];
                    }
                    dst[((size_t)img*128+co)*1024 + (yy<<5)+xx] = v;
                }
            }
        }
    }
}

// ---- FFMA 3x3 conv: modes 0 single, 3 concat(inputs64, s1+s2) ----
__global__ __launch_bounds__(256,2)
void conv3x3_k(const float* __restrict__ s0, const float* __restrict__ s1,
               const float* __restrict__ s2, const float* __restrict__ wT,
               float* __restrict__ dst, int cin, int mode)
{
    __shared__ float sIn[8*6*34];
    __shared__ float sW [8*9*128];
    const int t   = threadIdx.x;
    const int img = blockIdx.x >> 3;
    const int y0  = (blockIdx.x & 7) << 2;
    const int x   = t & 31;
    const int cg  = t >> 5;
    float acc[64];
    #pragma unroll
    for (int i=0;i<64;i++) acc[i]=0.f;

    const int nchunk = cin >> 3;
    for (int cc=0; cc<nchunk; cc++){
        const float* wp = wT + cc*9216;
        for (int e=t; e<9216; e+=256) sW[e] = wp[e];
        for (int e=t; e<1632; e+=256){
            int ci = e/204; int rem = e - ci*204;
            int r  = rem/34; int xx = rem - r*34;
            int y  = y0 - 1 + r; int xg = xx - 1;
            float val = 0.f;
            if ((unsigned)y < 32u && (unsigned)xg < 32u){
                int c = (cc<<3) + ci;
                int p = (y<<5) + xg;
                if (mode == 0){
                    val = s0[((size_t)img*cin + c)*1024 + p];
                } else {
                    val = (c < 64) ? s0[((size_t)img*64 + c)*1024 + p]
                                   : s1[((size_t)img*128 + (c-64))*1024 + p]
                                   + s2[((size_t)img*128 + (c-64))*1024 + p];
                }
            }
            sIn[(ci*6 + r)*34 + xx] = val;
        }
        __syncthreads();
        #pragma unroll 1
        for (int ci=0; ci<8; ci++){
            float inr[18];
            #pragma unroll
            for (int r=0;r<6;r++){
                #pragma unroll
                for (int d=0;d<3;d++) inr[r*3+d] = sIn[(ci*6+r)*34 + x + d];
            }
            #pragma unroll
            for (int tap=0; tap<9; tap++){
                const int dy = tap/3, dx = tap - dy*3;
                const float4* wq = (const float4*)&sW[(ci*9+tap)*128 + (cg<<4)];
                float4 w0 = wq[0], w1 = wq[1], w2 = wq[2], w3 = wq[3];
                #pragma unroll
                for (int y=0;y<4;y++){
                    float iv = inr[(y+dy)*3 + dx];
                    float* a = &acc[y*16];
                    a[0]+=iv*w0.x; a[1]+=iv*w0.y; a[2]+=iv*w0.z; a[3]+=iv*w0.w;
                    a[4]+=iv*w1.x; a[5]+=iv*w1.y; a[6]+=iv*w1.z; a[7]+=iv*w1.w;
                    a[8]+=iv*w2.x; a[9]+=iv*w2.y; a[10]+=iv*w2.z; a[11]+=iv*w2.w;
                    a[12]+=iv*w3.x; a[13]+=iv*w3.y; a[14]+=iv*w3.z; a[15]+=iv*w3.w;
                }
            }
        }
        __syncthreads();
    }
    #pragma unroll
    for (int j=0;j<16;j++){
        int co = (cg<<4) + j;
        #pragma unroll
        for (int y=0;y<4;y++)
            dst[((size_t)img*128 + co)*1024 + ((y0+y)<<5) + x] = acc[y*16+j];
    }
}

// ---- 1x1 conv (vpost) ----
__global__ __launch_bounds__(256,2)
void conv1x1_k(const float* __restrict__ src, const float* __restrict__ wT,
               float* __restrict__ dst)
{
    __shared__ float sIn[8*128];
    __shared__ float sW [8*128];
    const int t   = threadIdx.x;
    const int img = blockIdx.x >> 3;
    const int p0  = (blockIdx.x & 7) << 7;
    const int xl  = t & 31;
    const int cg  = t >> 5;
    float acc[64];
    #pragma unroll
    for (int i=0;i<64;i++) acc[i]=0.f;

    for (int cc=0; cc<16; cc++){
        for (int e=t; e<1024; e+=256){
            int ci = e>>7, i = e&127;
            sIn[e] = src[((size_t)img*128 + (cc<<3)+ci)*1024 + p0 + i];
            sW [e] = wT[(cc<<10) + e];
        }
        __syncthreads();
        #pragma unroll
        for (int ci=0;ci<8;ci++){
            float inr[4];
            #pragma unroll
            for (int y=0;y<4;y++) inr[y] = sIn[ci*128 + (y<<5) + xl];
            const float4* wq = (const float4*)&sW[ci*128 + (cg<<4)];
            float4 w0=wq[0], w1=wq[1], w2=wq[2], w3=wq[3];
            #pragma unroll
            for (int y=0;y<4;y++){
                float iv = inr[y];
                float* a = &acc[y*16];
                a[0]+=iv*w0.x; a[1]+=iv*w0.y; a[2]+=iv*w0.z; a[3]+=iv*w0.w;
                a[4]+=iv*w1.x; a[5]+=iv*w1.y; a[6]+=iv*w1.z; a[7]+=iv*w1.w;
                a[8]+=iv*w2.x; a[9]+=iv*w2.y; a[10]+=iv*w2.z; a[11]+=iv*w2.w;
                a[12]+=iv*w3.x; a[13]+=iv*w3.y; a[14]+=iv*w3.z; a[15]+=iv*w3.w;
            }
        }
        __syncthreads();
    }
    #pragma unroll
    for (int j=0;j<16;j++){
        int co = (cg<<4)+j;
        #pragma unroll
        for (int y=0;y<4;y++)
            dst[((size_t)img*128+co)*1024 + p0 + (y<<5) + xl] = acc[y*16+j];
    }
}

// ---- GroupNorm ----
__global__ void gn_reduce_k(const float* __restrict__ x, float* __restrict__ stats)
{
    const int img = blockIdx.x;
    const float4* p = (const float4*)(x + (size_t)img*CHW);
    float s=0.f, s2=0.f;
    for (int i=threadIdx.x; i<32768; i+=blockDim.x){
        float4 v = p[i];
        s  += v.x+v.y+v.z+v.w;
        s2 += v.x*v.x+v.y*v.y+v.z*v.z+v.w*v.w;
    }
    #pragma unroll
    for (int o=16;o;o>>=1){
        s  += __shfl_down_sync(0xffffffffu, s , o);
        s2 += __shfl_down_sync(0xffffffffu, s2, o);
    }
    __shared__ float sa[8], sb[8];
    if ((threadIdx.x&31)==0){ sa[threadIdx.x>>5]=s; sb[threadIdx.x>>5]=s2; }
    __syncthreads();
    if (threadIdx.x==0){
        float S=0.f, S2=0.f;
        #pragma unroll
        for (int i=0;i<8;i++){ S+=sa[i]; S2+=sb[i]; }
        float mu  = S*(1.f/131072.f);
        float var = S2*(1.f/131072.f) - mu*mu;
        stats[img*2]   = mu;
        stats[img*2+1] = rsqrtf(var + 1e-5f);
    }
}

__global__ void gn_apply_k(float* __restrict__ x, const float* __restrict__ stats,
                           const float* __restrict__ gw, const float* __restrict__ gb,
                           int nimg, int act)
{
    int n4 = nimg*32768;
    for (int i = blockIdx.x*blockDim.x + threadIdx.x; i < n4; i += gridDim.x*blockDim.x){
        int base = i<<2;
        int img = base>>17; int c = (base>>10)&127;
        float mu = stats[2*img], rs = stats[2*img+1];
        float sc = rs*gw[c];
        float sh = gb[c] - mu*sc;
        float4 v = ((float4*)x)[i];
        v.x = v.x*sc+sh; v.y = v.y*sc+sh; v.z = v.z*sc+sh; v.w = v.w*sc+sh;
        if (act){
            v.x *= sigmf(v.x); v.y *= sigmf(v.y); v.z *= sigmf(v.z); v.w *= sigmf(v.w);
        }
        ((float4*)x)[i] = v;
    }
}

// ---- pooling / spatial filter ----
__global__ void pool_k(const float* __restrict__ x, float* __restrict__ pool, int nimg)
{
    int i = blockIdx.x*blockDim.x + threadIdx.x;
    if (i >= nimg*HWN) return;
    int img = i>>10, p = i&1023;
    const float* base = x + (size_t)img*CHW + p;
    float s = 0.f, m = -3.402823466e38f;
    #pragma unroll 4
    for (int c=0;c<128;c++){
        float v = base[(size_t)c<<10];
        s += v; m = fmaxf(m, v);
    }
    pool[img*2048 + p]        = s*(1.f/128.f);
    pool[img*2048 + 1024 + p] = m;
}

__global__ void saconv_k(const float* __restrict__ pool, const float* __restrict__ w,
                         const float* __restrict__ b, float* __restrict__ sa, int nimg)
{
    int i = blockIdx.x*blockDim.x + threadIdx.x;
    if (i >= nimg*HWN) return;
    int img = i>>10, p = i&1023, y = p>>5, x = p&31;
    float acc = b[0];
    #pragma unroll
    for (int c2=0;c2<2;c2++)
    #pragma unroll
    for (int dy=-1;dy<=1;dy++)
    #pragma unroll
    for (int dx=-1;dx<=1;dx++){
        int yy=y+dy, xx=x+dx;
        if ((unsigned)yy<32u && (unsigned)xx<32u)
            acc += pool[img*2048 + c2*1024 + (yy<<5)+xx] * w[c2*9 + (dy+1)*3 + (dx+1)];
    }
    sa[i] = sigmf(acc);
}

// ---- attention pieces ----
__global__ void qfg_k()
{
    int wid  = (blockIdx.x*blockDim.x + threadIdx.x) >> 5;
    int lane = threadIdx.x & 31;
    if (wid >= SN*BN*CH) return;
    int c = wid & 127, b = (wid>>7)&15, s = wid>>11;
    const float* qp = g_q   + ((size_t)b*128 + c)*1024;
    const float* kp = g_ksa + (size_t)(s*16+b)*1024;
    float acc = 0.f;
    for (int p=lane; p<1024; p+=32) acc += qp[p]*kp[p];
    #pragma unroll
    for (int o=16;o;o>>=1) acc += __shfl_down_sync(0xffffffffu, acc, o);
    if (!lane) g_qfg[wid] = acc*(1.f/1024.f);
}

__global__ void sprob_k()
{
    int img = blockIdx.x;
    __shared__ float fq[128];
    int t = threadIdx.x;
    if (t < 128) fq[t] = g_qfg[img*128 + t];
    __syncthreads();
    for (int p=t; p<1024; p+=256){
        const float* kp = g_k + (size_t)img*CHW + p;
        float acc = 0.f;
        #pragma unroll 4
        for (int c=0;c<128;c++) acc += fq[c]*kp[(size_t)c<<10];
        g_sprob[img*1024 + p] = sigmf(acc);
    }
}

__global__ void tlogit_k()
{
    int img = blockIdx.x, b = img & 15;
    float acc = 0.f;
    for (int i=threadIdx.x; i<CHW; i+=256){
        int p = i & 1023;
        acc += g_q[(size_t)b*CHW + i]*g_qsa[b*1024+p]
             * g_k[(size_t)img*CHW + i]*g_ksa[img*1024+p];
    }
    #pragma unroll
    for (int o=16;o;o>>=1) acc += __shfl_down_sync(0xffffffffu, acc, o);
    __shared__ float sh[8];
    if ((threadIdx.x&31)==0) sh[threadIdx.x>>5] = acc;
    __syncthreads();
    if (threadIdx.x==0){
        float S=0.f;
        #pragma unroll
        for (int i=0;i<8;i++) S += sh[i];
        g_tl[img] = S * rsqrtf(131072.f);
    }
}

__global__ void tprob_k()
{
    int b = threadIdx.x;
    if (b >= 16) return;
    float m = -3.402823466e38f;
    #pragma unroll
    for (int s=0;s<8;s++) m = fmaxf(m, g_tl[s*16+b]);
    float e[8]; float sum = 0.f;
    #pragma unroll
    for (int s=0;s<8;s++){ e[s] = __expf(g_tl[s*16+b] - m); sum += e[s]; }
    float inv = 1.f/sum;
    #pragma unroll
    for (int s=0;s<8;s++) g_tp[s*16+b] = e[s]*inv;
}

__global__ void av_k()
{
    int i = blockIdx.x*blockDim.x + threadIdx.x;
    if (i >= BN*CHW/4) return;
    int base = i<<2;
    int b = base>>17; int c = (base>>10)&127; int p = base&1023;
    float4 acc = make_float4(0.f,0.f,0.f,0.f);
    #pragma unroll
    for (int s=0;s<8;s++){
        int img = s*16 + b;
        float tw = g_tp[img];
        float4 sp = *(const float4*)&g_sprob[img*1024 + p];
        float4 vv = *(const float4*)&g_v[((size_t)img*128 + c)*1024 + p];
        acc.x += tw*sp.x*vv.x; acc.y += tw*sp.y*vv.y;
        acc.z += tw*sp.z*vv.z; acc.w += tw*sp.w*vv.w;
    }
    *(float4*)&g_av[base] = acc;
}

__global__ void newout_k(const unsigned char* __restrict__ mask, float* __restrict__ out)
{
    int i = blockIdx.x*blockDim.x + threadIdx.x;
    if (i >= BN*CHW/4) return;
    int base = i<<2;
    int b = base>>17;
    float4 v = mask_at(mask, b) ? *(const float4*)&g_att[base]
                                : make_float4(0.f,0.f,0.f,0.f);
    *(float4*)&out[(size_t)2*BN*CHW + base] = v;
}

__global__ void semean_k()
{
    int b = blockIdx.x;
    int w = threadIdx.x>>5, lane = threadIdx.x&31;
    for (int c=w; c<128; c+=8){
        const float* p = g_o + ((size_t)b*128 + c)*1024;
        float s = 0.f;
        for (int i=lane; i<1024; i+=32) s += p[i];
        #pragma unroll
        for (int o=16;o;o>>=1) s += __shfl_down_sync(0xffffffffu, s, o);
        if (!lane) g_se1[b*128+c] = s*(1.f/1024.f);
    }
}

__global__ void sefc1_k(const float* __restrict__ w1, const float* __restrict__ b1)
{
    int t = threadIdx.x;
    int b = t>>5, j = t&31;
    float acc = b1[j];
    #pragma unroll 4
    for (int c=0;c<128;c++) acc += g_se1[b*128+c]*w1[j*128+c];
    g_se2[b*32+j] = fmaxf(acc, 0.f);
}

__global__ void sefc2_k(const float* __restrict__ w2, const float* __restrict__ b2)
{
    int i = blockIdx.x*blockDim.x + threadIdx.x;
    if (i >= BN*CH) return;
    int b = i>>7, c = i&127;
    float acc = b2[c];
    #pragma unroll
    for (int j=0;j<32;j++) acc += g_se2[b*32+j]*w2[c*32+j];
    g_se3[i] = sigmf(acc);
}

__global__ void final_k(float* __restrict__ out)
{
    int i = blockIdx.x*blockDim.x + threadIdx.x;
    if (i >= BN*CHW/4) return;
    int base = i<<2;
    int b = base>>17; int c = (base>>10)&127;
    float g = 1.f + g_se3[b*128+c];
    float4 o4 = *(const float4*)&g_o[base];
    o4.x*=g; o4.y*=g; o4.z*=g; o4.w*=g;
    *(float4*)&out[base] = o4;
    *(float4*)&out[(size_t)BN*CHW + base] = *(const float4*)&g_ht[base];
}

// ---- host launcher ----
extern "C" void kernel_launch(void* const* d_in, const int* in_sizes, int n_in,
                              void* d_out, int out_size)
{
    (void)in_sizes; (void)n_in; (void)out_size;
    const float* inputs  = (const float*)d_in[0];
    const float* hidden  = (const float*)d_in[1];
    const float* outq    = (const float*)d_in[2];
    const unsigned char* mask = (const unsigned char*)d_in[3];
    const float* enc_w   = (const float*)d_in[4];
    const float* enc_gw  = (const float*)d_in[5];
    const float* enc_gb  = (const float*)d_in[6];
    const float* qpre_w  = (const float*)d_in[7];
    const float* qpre_gw = (const float*)d_in[8];
    const float* qpre_gb = (const float*)d_in[9];
    const float* kpre_w  = (const float*)d_in[10];
    const float* kpre_gw = (const float*)d_in[11];
    const float* kpre_gb = (const float*)d_in[12];
    const float* vpre_w  = (const float*)d_in[13];
    const float* vpre_gw = (const float*)d_in[14];
    const float* vpre_gb = (const float*)d_in[15];
    const float* qsa_w   = (const float*)d_in[16];
    const float* qsa_b   = (const float*)d_in[17];
    const float* ksa_w   = (const float*)d_in[18];
    const float* ksa_b   = (const float*)d_in[19];
    const float* vpost_w = (const float*)d_in[20];
    const float* vpost_gw= (const float*)d_in[21];
    const float* vpost_gb= (const float*)d_in[22];
    const float* pos_emb = (const float*)d_in[23];
    const float* outt_w  = (const float*)d_in[24];
    const float* outt_gw = (const float*)d_in[25];
    const float* outt_gb = (const float*)d_in[26];
    const float* se_w1   = (const float*)d_in[27];
    const float* se_b1   = (const float*)d_in[28];
    const float* se_w2   = (const float*)d_in[29];
    const float* se_b2   = (const float*)d_in[30];
    float* out = (float*)d_out;

    float *ht,*q,*k,*v,*av,*att,*o,*stats,*pool,*qsa,*ksa,*peN,*wT,*Pb;
    __nv_bfloat16 *wrep;
    cudaGetSymbolAddress((void**)&ht,   g_ht);
    cudaGetSymbolAddress((void**)&q,    g_q);
    cudaGetSymbolAddress((void**)&k,    g_k);
    cudaGetSymbolAddress((void**)&v,    g_v);
    cudaGetSymbolAddress((void**)&av,   g_av);
    cudaGetSymbolAddress((void**)&att,  g_att);
    cudaGetSymbolAddress((void**)&o,    g_o);
    cudaGetSymbolAddress((void**)&stats,g_stats);
    cudaGetSymbolAddress((void**)&pool, g_pool);
    cudaGetSymbolAddress((void**)&qsa,  g_qsa);
    cudaGetSymbolAddress((void**)&ksa,  g_ksa);
    cudaGetSymbolAddress((void**)&peN,  g_peN);
    cudaGetSymbolAddress((void**)&wT,   g_wT);
    cudaGetSymbolAddress((void**)&Pb,   g_Pb);
    cudaGetSymbolAddress((void**)&wrep, g_wrep);

    const int OFF_ENC   = 0;
    const int OFF_QPRE  = 73728;
    const int OFF_OUTT  = 221184;
    const int OFF_VPOST = 442368;

    cudaFuncSetAttribute(mmaconv_k, cudaFuncAttributeMaxDynamicSharedMemorySize, DSMEM_TOTAL);

    transw_k<<<128,256>>>(enc_w,  wT+OFF_ENC,  64, 9);
    transw_k<<<256,256>>>(qpre_w, wT+OFF_QPRE, 128, 9);
    transw_k<<<384,256>>>(outt_w, wT+OFF_OUTT, 192, 9);
    transw_k<<<64,256>>>(vpost_w, wT+OFF_VPOST, 128, 1);
    pe_norm_k<<<8,256>>>(pos_emb, peN);
    wrep_k<<<1152,256>>>(kpre_w, wrep);
    wrep_k<<<1152,256>>>(vpre_w, wrep + 589824);
    pbconv_k<<<8,128>>>(vpre_w);
    zero_nhwc_k<<<2048,256>>>();
    fill_nhwc_k<<<4096,256>>>(hidden, outq);

    // ht = silu(gn(conv(inputs, enc_w)))
    conv3x3_k<<<BN*8,256>>>(inputs, nullptr, nullptr, wT+OFF_ENC, ht, 64, 0);
    gn_reduce_k<<<BN,256>>>(ht, stats);
    gn_apply_k<<<2048,256>>>(ht, stats, enc_gw, enc_gb, BN, 1);

    // q = gn(conv(ht, qpre_w))
    conv3x3_k<<<BN*8,256>>>(ht, nullptr, nullptr, wT+OFF_QPRE, q, 128, 0);
    gn_reduce_k<<<BN,256>>>(q, stats);
    gn_apply_k<<<2048,256>>>(q, stats, qpre_gw, qpre_gb, BN, 0);

    // k = gn(mmaconv(kv, kpre_w))
    mmaconv_k<<<640,256,DSMEM_TOTAL>>>(wrep, nullptr, k);
    gn_reduce_k<<<SBN,256>>>(k, stats);
    gn_apply_k<<<4096,256>>>(k, stats, kpre_gw, kpre_gb, SBN, 0);

    // v = gn(mmaconv(kv, vpre_w) + Pb)
    mmaconv_k<<<640,256,DSMEM_TOTAL>>>(wrep + 589824, Pb, v);
    gn_reduce_k<<<SBN,256>>>(v, stats);
    gn_apply_k<<<4096,256>>>(v, stats, vpre_gw, vpre_gb, SBN, 0);

    // spatial filters
    pool_k<<<(BN*HWN+255)/256,256>>>(q, pool, BN);
    saconv_k<<<(BN*HWN+255)/256,256>>>(pool, qsa_w, qsa_b, qsa, BN);
    pool_k<<<(SBN*HWN+255)/256,256>>>(k, pool, SBN);
    saconv_k<<<(SBN*HWN+255)/256,256>>>(pool, ksa_w, ksa_b, ksa, SBN);

    // attention
    qfg_k<<<2048,256>>>();
    sprob_k<<<SBN,256>>>();
    tlogit_k<<<SBN,256>>>();
    tprob_k<<<1,32>>>();
    av_k<<<2048,256>>>();

    // att = silu(gn(conv1x1(av)))
    conv1x1_k<<<BN*8,256>>>(av, wT+OFF_VPOST, att);
    gn_reduce_k<<<BN,256>>>(att, stats);
    gn_apply_k<<<2048,256>>>(att, stats, vpost_gw, vpost_gb, BN, 1);

    newout_k<<<2048,256>>>(mask, out);

    // o = silu(gn(conv(concat(inputs, att+ht))))
    conv3x3_k<<<BN*8,256>>>(inputs, att, ht, wT+OFF_OUTT, o, 192, 3);
    gn_reduce_k<<<BN,256>>>(o, stats);
    gn_apply_k<<<2048,256>>>(o, stats, outt_gw, outt_gb, BN, 1);

    semean_k<<<BN,256>>>();
    sefc1_k<<<1,512>>>(se_w1, se_b1);
    sefc2_k<<<8,256>>>(se_w2, se_b2);
    final_k<<<2048,256>>>(out);
}

// round 6
// speedup vs baseline: 1.9774x; 1.4419x over previous
#include <cuda_runtime.h>
#include <cuda_bf16.h>
#include <cstdint>

#define BN   16
#define CH   128
#define HWN  1024
#define SN   8
#define SBN  128
#define CHW  131072

#define GUARD   64
#define RPI     1344
#define TOTROWS (GUARD + 128*RPI)

// mmaconv smem layout (bytes): X window 336 rows x 256B, then 2 A buffers 64KB each
#define XWIN_ROWS 336
#define XB_OFF 0
#define AB0_OFF 86016
#define AB1_OFF 151552
#define DSMEM_TOTAL 217088

__device__ float g_ht [BN*CHW];
__device__ float g_q  [BN*CHW];
__device__ float g_k  [SBN*CHW];
__device__ float g_v  [SBN*CHW];
__device__ float g_av [BN*CHW];
__device__ float g_att[BN*CHW];
__device__ float g_o  [BN*CHW];
__device__ float g_stats[2*SBN];
__device__ float g_pool[SBN*2*HWN];
__device__ float g_qsa[BN*HWN];
__device__ float g_ksa[SBN*HWN];
__device__ float g_qfg[SN*BN*CH];
__device__ float g_sprob[SBN*HWN];
__device__ float g_tl[SN*BN];
__device__ float g_tp[SN*BN];
__device__ float g_peN[SN*2*CH];
__device__ float g_se1[BN*CH];
__device__ float g_se2[BN*32];
__device__ float g_se3[BN*CH];
__device__ float g_Pb[SN*CH*9];
__device__ float g_wT[524288];
__device__ __nv_bfloat16 g_nhwc[(size_t)2*TOTROWS*256];
__device__ __nv_bfloat16 g_wrep[1179648];  // 2 convs x [sp][tap*2+kc][co][128]

__device__ __forceinline__ float sigmf(float x){ return 1.f/(1.f + __expf(-x)); }
__device__ __forceinline__ bool mask_at(const unsigned char* m, int b){
    if (m[1] != 0) return m[b] != 0;
    const unsigned int* w = (const unsigned int*)m;
    return w[b] != 0;
}

__device__ __forceinline__ uint32_t smem_u32(const void* p){
    uint32_t a;
    asm("{ .reg .u64 t; cvta.to.shared.u64 t, %1; cvt.u32.u64 %0, t; }" : "=r"(a) : "l"(p));
    return a;
}
__device__ __forceinline__ void mma16816(float* d, uint32_t a0, uint32_t a1, uint32_t a2,
                                         uint32_t a3, uint32_t b0, uint32_t b1){
    asm volatile("mma.sync.aligned.m16n8k16.row.col.f32.bf16.bf16.f32 "
        "{%0,%1,%2,%3}, {%4,%5,%6,%7}, {%8,%9}, {%0,%1,%2,%3};"
        : "+f"(d[0]),"+f"(d[1]),"+f"(d[2]),"+f"(d[3])
        : "r"(a0),"r"(a1),"r"(a2),"r"(a3),"r"(b0),"r"(b1));
}
__device__ __forceinline__ void ldsm4(uint32_t& r0,uint32_t& r1,uint32_t& r2,uint32_t& r3,
                                      uint32_t addr){
    asm volatile("ldmatrix.sync.aligned.m8n8.x4.shared.b16 {%0,%1,%2,%3}, [%4];"
        : "=r"(r0),"=r"(r1),"=r"(r2),"=r"(r3) : "r"(addr));
}
__device__ __forceinline__ void cpa16(uint32_t d, const void* s){
    asm volatile("cp.async.cg.shared.global [%0], [%1], 16;" :: "r"(d), "l"(s));
}
__device__ __forceinline__ void cp_commit(){ asm volatile("cp.async.commit_group;" ::: "memory"); }
__device__ __forceinline__ void cp_wait0(){ asm volatile("cp.async.wait_group 0;" ::: "memory"); }

// ---- weight transpose for FFMA convs ----
__global__ void transw_k(const float* __restrict__ w, float* __restrict__ wT,
                         int cin, int ktaps)
{
    int n = cin*ktaps*128;
    for (int i = blockIdx.x*blockDim.x + threadIdx.x; i < n; i += gridDim.x*blockDim.x){
        int co = i & 127;
        int r  = i >> 7;
        int tap = r % ktaps;
        int c   = r / ktaps;
        wT[i] = w[(co*cin + c)*ktaps + tap];
    }
}

__global__ void pe_norm_k(const float* __restrict__ pe, float* __restrict__ peN)
{
    int s = blockIdx.x, t = threadIdx.x;
    float v = pe[s*256 + t];
    float q = v*v;
    #pragma unroll
    for (int o=16;o;o>>=1) q += __shfl_down_sync(0xffffffffu, q, o);
    __shared__ float a[8];
    __shared__ float fac;
    if ((t&31)==0) a[t>>5] = q;
    __syncthreads();
    if (t==0){
        float S=0.f;
        #pragma unroll
        for (int i=0;i<8;i++) S += a[i];
        float n = sqrtf(S);
        fac = fminf(1.f, 1.f/fmaxf(n, 1e-7f));
    }
    __syncthreads();
    peN[s*256 + t] = v*fac;
}

// ---- NHWC bf16 hi/lo repack ----
__global__ void zero_nhwc_k()
{
    size_t n = ((size_t)2*TOTROWS*256*2)/16;
    uint4 z = make_uint4(0,0,0,0);
    uint4* p = (uint4*)g_nhwc;
    for (size_t i = (size_t)blockIdx.x*blockDim.x + threadIdx.x; i < n;
         i += (size_t)gridDim.x*blockDim.x) p[i] = z;
}

__global__ void fill_nhwc_k(const float* __restrict__ hid, const float* __restrict__ oq)
{
    __shared__ float s[8][33];
    int t = threadIdx.x;
    int img = blockIdx.x>>5, y = blockIdx.x&31;
    int xg = t&31, cg = t>>5;
    int xs = t>>3, cl = t&7;
    size_t rb = GUARD + (size_t)img*RPI + (size_t)(y+1)*34;
    for (int cc=0; cc<32; cc++){
        int c = cc*8 + cg;
        const float* src = (c<128) ? hid + ((size_t)img*128 + c)*1024
                                   : oq  + ((size_t)img*128 + (c-128))*1024;
        s[cg][xg] = src[y*32 + xg];
        __syncthreads();
        float v = s[cl][xs];
        __nv_bfloat16 h = __float2bfloat16(v);
        __nv_bfloat16 l = __float2bfloat16(v - __bfloat162float(h));
        size_t off = (rb + xs + 1)*256 + cc*8 + cl;
        g_nhwc[off] = h;
        g_nhwc[(size_t)TOTROWS*256 + off] = l;
        __syncthreads();
    }
}

// ---- weight repack: [sp][tap*2+kc][co][128k] bf16 hi/lo ----
__global__ void wrep_k(const float* __restrict__ w, __nv_bfloat16* __restrict__ dst)
{
    int i = blockIdx.x*blockDim.x + threadIdx.x;
    if (i >= 294912) return;
    int kl = i & 127;
    int r = i >> 7;
    int co = r & 127; r >>= 7;
    int kc = r & 1;   r >>= 1;
    int tap = r;
    int cin = kc*128 + kl;
    float val = w[((size_t)co*256 + cin)*9 + tap];
    __nv_bfloat16 h = __float2bfloat16(val);
    int o = ((tap*2+kc)*128 + co)*128 + kl;
    dst[o] = h;
    dst[294912 + o] = __float2bfloat16(val - __bfloat162float(h));
}

// ---- pe correction with border masks: Pb[s][co][yc*3+xc] ----
__global__ void pbconv_k(const float* __restrict__ w)
{
    int s = blockIdx.x, co = threadIdx.x;
    float P[9];
    #pragma unroll
    for (int tap=0;tap<9;tap++){
        float acc = 0.f;
        for (int c=0;c<256;c++)
            acc += g_peN[s*256 + c] * w[((size_t)co*256 + c)*9 + tap];
        P[tap] = acc;
    }
    #pragma unroll
    for (int yc=0;yc<3;yc++){
        #pragma unroll
        for (int xc=0;xc<3;xc++){
            float tot = 0.f;
            #pragma unroll
            for (int dy=0;dy<3;dy++){
                if ((yc==0 && dy==0) || (yc==2 && dy==2)) continue;
                float rs = P[dy*3+1];
                if (xc!=0) rs += P[dy*3+0];
                if (xc!=2) rs += P[dy*3+2];
                tot += rs;
            }
            g_Pb[(s*128+co)*9 + yc*3+xc] = tot;
        }
    }
}

// ---- staging helpers for mmaconv ----
__device__ __forceinline__ void stageA(uint32_t ab, const __nv_bfloat16* wrep,
                                       int tap, int kc, int nsp, int t)
{
    #pragma unroll
    for (int sp=0;sp<2;sp++){
        if (sp >= nsp) break;
        const char* src = (const char*)(wrep + (size_t)sp*294912 + (size_t)(tap*2+kc)*16384);
        #pragma unroll
        for (int j=0;j<8;j++){
            int i = j*256 + t;
            uint32_t r = (uint32_t)(i>>4), sg = (uint32_t)(i&15);
            cpa16(ab + sp*32768 + r*256 + ((sg^(r&7))<<4), src + (size_t)i*16);
        }
    }
}

template<int NSP>
__device__ __forceinline__ void conv_tap_mma(uint32_t xb, uint32_t ab, int tap,
                                             int lane, int cob, int pxb,
                                             float acc[4][8][4])
{
    const int lr   = lane & 7;
    const int hsA  = lane >> 4;          // A k-half per lane
    const int hsB  = (lane >> 3) & 1;    // B k-half per lane
    const int dy = tap/3, dx = tap - dy*3;
    const int dlt = (dy-1)*34 + (dx-1);

    uint32_t rowA[4], rsA[4];
    #pragma unroll
    for (int mi=0;mi<4;mi++){
        int r = cob + mi*16 + lr + ((lane>>3)&1)*8;
        rowA[mi] = (uint32_t)r*256u; rsA[mi] = (uint32_t)(r&7);
    }
    uint32_t rowB[4], rsB[4];
    #pragma unroll
    for (int nn=0;nn<4;nn++){
        int r = 36 + dlt + pxb + nn*16 + lr + (lane>>4)*8;
        rowB[nn] = (uint32_t)r*256u; rsB[nn] = (uint32_t)(r&7);
    }
    #pragma unroll
    for (int k8=0;k8<8;k8++){
        uint32_t a[NSP][4][4];
        #pragma unroll
        for (int sp=0;sp<NSP;sp++){
            #pragma unroll
            for (int mi=0;mi<4;mi++){
                uint32_t sgi = (uint32_t)(k8*2 + hsA);
                uint32_t ad = ab + (uint32_t)sp*32768u + rowA[mi] + ((sgi ^ rsA[mi])<<4);
                ldsm4(a[sp][mi][0],a[sp][mi][1],a[sp][mi][2],a[sp][mi][3], ad);
            }
        }
        #pragma unroll
        for (int nn=0;nn<4;nn++){
            uint32_t sgi = (uint32_t)(k8*2 + hsB);
            uint32_t ad = xb + rowB[nn] + ((sgi ^ rsB[nn])<<4);
            uint32_t b0,b1,b2,b3;
            ldsm4(b0,b1,b2,b3, ad);
            #pragma unroll
            for (int mi=0;mi<4;mi++){
                #pragma unroll
                for (int sp=0;sp<NSP;sp++){
                    mma16816(acc[mi][2*nn],   a[sp][mi][0],a[sp][mi][1],a[sp][mi][2],a[sp][mi][3], b0,b1);
                    mma16816(acc[mi][2*nn+1], a[sp][mi][0],a[sp][mi][1],a[sp][mi][2],a[sp][mi][3], b2,b3);
                }
            }
        }
    }
}

// ---- mma.sync bf16 implicit conv: D[128co,256px], X window resident ----
__global__ __launch_bounds__(256,1)
void mmaconv_k(const __nv_bfloat16* __restrict__ wrep,
               const float* __restrict__ Pb,
               float* __restrict__ dst)
{
    extern __shared__ char dsm[];
    const uint32_t sb  = smem_u32(dsm);
    const uint32_t XB  = sb + XB_OFF;
    const uint32_t AB0 = sb + AB0_OFF;
    const uint32_t AB1 = sb + AB1_OFF;
    const int t = threadIdx.x;
    const int wid = t>>5, lane = t&31;
    const int img = blockIdx.x/5;
    const int p0  = (blockIdx.x%5)*256;
    const int s   = img>>4;
    const int cob = (wid&1)*64;
    const int pxb = (wid>>1)*64;

    float acc[4][8][4];
    #pragma unroll
    for (int mi=0;mi<4;mi++)
    #pragma unroll
    for (int ni=0;ni<8;ni++)
    #pragma unroll
    for (int e=0;e<4;e++) acc[mi][ni][e]=0.f;

    // ps=0: (Ah+Al)·Xh ; ps=1: Ah·Xl
    #pragma unroll
    for (int ps=0; ps<2; ps++){
        const int nsp = (ps==0) ? 2 : 1;
        for (int kc=0; kc<2; kc++){
            // stage X window: 336 rows x 128k (one split, one kc)
            {
                const char* src = (const char*)(g_nhwc
                    + ((size_t)ps*TOTROWS + GUARD + (size_t)img*RPI + p0 - 36)*256 + kc*128);
                #pragma unroll
                for (int j=0;j<21;j++){
                    int i = j*256 + t;
                    uint32_t r = (uint32_t)(i>>4), sg = (uint32_t)(i&15);
                    cpa16(XB + r*256 + ((sg^(r&7))<<4), src + (size_t)r*512 + sg*16);
                }
                cp_commit();
            }
            stageA(AB0, wrep, 0, kc, nsp, t);
            cp_commit();
            cp_wait0(); __syncthreads();
            for (int tap=0; tap<9; tap++){
                uint32_t abuf = (tap&1) ? AB1 : AB0;
                if (tap < 8){
                    stageA((tap&1) ? AB0 : AB1, wrep, tap+1, kc, nsp, t);
                    cp_commit();
                }
                if (ps==0) conv_tap_mma<2>(XB, abuf, tap, lane, cob, pxb, acc);
                else       conv_tap_mma<1>(XB, abuf, tap, lane, cob, pxb, acc);
                cp_wait0(); __syncthreads();
            }
        }
    }

    // epilogue: direct register -> global stores with border mask + Pb correction
    const int g  = lane>>2;
    const int t2 = (lane&3)*2;
    #pragma unroll
    for (int mi=0;mi<4;mi++){
        #pragma unroll
        for (int ni=0;ni<8;ni++){
            #pragma unroll
            for (int e=0;e<4;e++){
                int co  = cob + mi*16 + g + ((e>>1)<<3);
                int col = pxb + ni*8 + t2 + (e&1);
                int pp  = p0 + col;
                int q34 = pp/34;
                int yy  = q34 - 1;
                int xx  = pp - q34*34 - 1;
                if ((unsigned)yy < 32u && (unsigned)xx < 32u){
                    float v = acc[mi][ni][e];
                    if (Pb){
                        int yc = (yy==0)?0:((yy==31)?2:1);
                        int xc = (xx==0)?0:((xx==31)?2:1);
                        v += Pb[(s*128+co)*9 + yc*3+xc];
                    }
                    dst[((size_t)img*128+co)*1024 + (yy<<5)+xx] = v;
                }
            }
        }
    }
}

// ---- FFMA 3x3 conv: modes 0 single, 3 concat(inputs64, s1+s2) ----
__global__ __launch_bounds__(256,2)
void conv3x3_k(const float* __restrict__ s0, const float* __restrict__ s1,
               const float* __restrict__ s2, const float* __restrict__ wT,
               float* __restrict__ dst, int cin, int mode)
{
    __shared__ float sIn[8*6*34];
    __shared__ float sW [8*9*128];
    const int t   = threadIdx.x;
    const int img = blockIdx.x >> 3;
    const int y0  = (blockIdx.x & 7) << 2;
    const int x   = t & 31;
    const int cg  = t >> 5;
    float acc[64];
    #pragma unroll
    for (int i=0;i<64;i++) acc[i]=0.f;

    const int nchunk = cin >> 3;
    for (int cc=0; cc<nchunk; cc++){
        const float* wp = wT + cc*9216;
        for (int e=t; e<9216; e+=256) sW[e] = wp[e];
        for (int e=t; e<1632; e+=256){
            int ci = e/204; int rem = e - ci*204;
            int r  = rem/34; int xx = rem - r*34;
            int y  = y0 - 1 + r; int xg = xx - 1;
            float val = 0.f;
            if ((unsigned)y < 32u && (unsigned)xg < 32u){
                int c = (cc<<3) + ci;
                int p = (y<<5) + xg;
                if (mode == 0){
                    val = s0[((size_t)img*cin + c)*1024 + p];
                } else {
                    val = (c < 64) ? s0[((size_t)img*64 + c)*1024 + p]
                                   : s1[((size_t)img*128 + (c-64))*1024 + p]
                                   + s2[((size_t)img*128 + (c-64))*1024 + p];
                }
            }
            sIn[(ci*6 + r)*34 + xx] = val;
        }
        __syncthreads();
        #pragma unroll 1
        for (int ci=0; ci<8; ci++){
            float inr[18];
            #pragma unroll
            for (int r=0;r<6;r++){
                #pragma unroll
                for (int d=0;d<3;d++) inr[r*3+d] = sIn[(ci*6+r)*34 + x + d];
            }
            #pragma unroll
            for (int tap=0; tap<9; tap++){
                const int dy = tap/3, dx = tap - dy*3;
                const float4* wq = (const float4*)&sW[(ci*9+tap)*128 + (cg<<4)];
                float4 w0 = wq[0], w1 = wq[1], w2 = wq[2], w3 = wq[3];
                #pragma unroll
                for (int y=0;y<4;y++){
                    float iv = inr[(y+dy)*3 + dx];
                    float* a = &acc[y*16];
                    a[0]+=iv*w0.x; a[1]+=iv*w0.y; a[2]+=iv*w0.z; a[3]+=iv*w0.w;
                    a[4]+=iv*w1.x; a[5]+=iv*w1.y; a[6]+=iv*w1.z; a[7]+=iv*w1.w;
                    a[8]+=iv*w2.x; a[9]+=iv*w2.y; a[10]+=iv*w2.z; a[11]+=iv*w2.w;
                    a[12]+=iv*w3.x; a[13]+=iv*w3.y; a[14]+=iv*w3.z; a[15]+=iv*w3.w;
                }
            }
        }
        __syncthreads();
    }
    #pragma unroll
    for (int j=0;j<16;j++){
        int co = (cg<<4) + j;
        #pragma unroll
        for (int y=0;y<4;y++)
            dst[((size_t)img*128 + co)*1024 + ((y0+y)<<5) + x] = acc[y*16+j];
    }
}

// ---- 1x1 conv (vpost) ----
__global__ __launch_bounds__(256,2)
void conv1x1_k(const float* __restrict__ src, const float* __restrict__ wT,
               float* __restrict__ dst)
{
    __shared__ float sIn[8*128];
    __shared__ float sW [8*128];
    const int t   = threadIdx.x;
    const int img = blockIdx.x >> 3;
    const int p0  = (blockIdx.x & 7) << 7;
    const int xl  = t & 31;
    const int cg  = t >> 5;
    float acc[64];
    #pragma unroll
    for (int i=0;i<64;i++) acc[i]=0.f;

    for (int cc=0; cc<16; cc++){
        for (int e=t; e<1024; e+=256){
            int ci = e>>7, i = e&127;
            sIn[e] = src[((size_t)img*128 + (cc<<3)+ci)*1024 + p0 + i];
            sW [e] = wT[(cc<<10) + e];
        }
        __syncthreads();
        #pragma unroll
        for (int ci=0;ci<8;ci++){
            float inr[4];
            #pragma unroll
            for (int y=0;y<4;y++) inr[y] = sIn[ci*128 + (y<<5) + xl];
            const float4* wq = (const float4*)&sW[ci*128 + (cg<<4)];
            float4 w0=wq[0], w1=wq[1], w2=wq[2], w3=wq[3];
            #pragma unroll
            for (int y=0;y<4;y++){
                float iv = inr[y];
                float* a = &acc[y*16];
                a[0]+=iv*w0.x; a[1]+=iv*w0.y; a[2]+=iv*w0.z; a[3]+=iv*w0.w;
                a[4]+=iv*w1.x; a[5]+=iv*w1.y; a[6]+=iv*w1.z; a[7]+=iv*w1.w;
                a[8]+=iv*w2.x; a[9]+=iv*w2.y; a[10]+=iv*w2.z; a[11]+=iv*w2.w;
                a[12]+=iv*w3.x; a[13]+=iv*w3.y; a[14]+=iv*w3.z; a[15]+=iv*w3.w;
            }
        }
        __syncthreads();
    }
    #pragma unroll
    for (int j=0;j<16;j++){
        int co = (cg<<4)+j;
        #pragma unroll
        for (int y=0;y<4;y++)
            dst[((size_t)img*128+co)*1024 + p0 + (y<<5) + xl] = acc[y*16+j];
    }
}

// ---- GroupNorm ----
__global__ void gn_reduce_k(const float* __restrict__ x, float* __restrict__ stats)
{
    const int img = blockIdx.x;
    const float4* p = (const float4*)(x + (size_t)img*CHW);
    float s=0.f, s2=0.f;
    for (int i=threadIdx.x; i<32768; i+=blockDim.x){
        float4 v = p[i];
        s  += v.x+v.y+v.z+v.w;
        s2 += v.x*v.x+v.y*v.y+v.z*v.z+v.w*v.w;
    }
    #pragma unroll
    for (int o=16;o;o>>=1){
        s  += __shfl_down_sync(0xffffffffu, s , o);
        s2 += __shfl_down_sync(0xffffffffu, s2, o);
    }
    __shared__ float sa[8], sb[8];
    if ((threadIdx.x&31)==0){ sa[threadIdx.x>>5]=s; sb[threadIdx.x>>5]=s2; }
    __syncthreads();
    if (threadIdx.x==0){
        float S=0.f, S2=0.f;
        #pragma unroll
        for (int i=0;i<8;i++){ S+=sa[i]; S2+=sb[i]; }
        float mu  = S*(1.f/131072.f);
        float var = S2*(1.f/131072.f) - mu*mu;
        stats[img*2]   = mu;
        stats[img*2+1] = rsqrtf(var + 1e-5f);
    }
}

__global__ void gn_apply_k(float* __restrict__ x, const float* __restrict__ stats,
                           const float* __restrict__ gw, const float* __restrict__ gb,
                           int nimg, int act)
{
    int n4 = nimg*32768;
    for (int i = blockIdx.x*blockDim.x + threadIdx.x; i < n4; i += gridDim.x*blockDim.x){
        int base = i<<2;
        int img = base>>17; int c = (base>>10)&127;
        float mu = stats[2*img], rs = stats[2*img+1];
        float sc = rs*gw[c];
        float sh = gb[c] - mu*sc;
        float4 v = ((float4*)x)[i];
        v.x = v.x*sc+sh; v.y = v.y*sc+sh; v.z = v.z*sc+sh; v.w = v.w*sc+sh;
        if (act){
            v.x *= sigmf(v.x); v.y *= sigmf(v.y); v.z *= sigmf(v.z); v.w *= sigmf(v.w);
        }
        ((float4*)x)[i] = v;
    }
}

// ---- pooling / spatial filter ----
__global__ void pool_k(const float* __restrict__ x, float* __restrict__ pool, int nimg)
{
    int i = blockIdx.x*blockDim.x + threadIdx.x;
    if (i >= nimg*HWN) return;
    int img = i>>10, p = i&1023;
    const float* base = x + (size_t)img*CHW + p;
    float s = 0.f, m = -3.402823466e38f;
    #pragma unroll 4
    for (int c=0;c<128;c++){
        float v = base[(size_t)c<<10];
        s += v; m = fmaxf(m, v);
    }
    pool[img*2048 + p]        = s*(1.f/128.f);
    pool[img*2048 + 1024 + p] = m;
}

__global__ void saconv_k(const float* __restrict__ pool, const float* __restrict__ w,
                         const float* __restrict__ b, float* __restrict__ sa, int nimg)
{
    int i = blockIdx.x*blockDim.x + threadIdx.x;
    if (i >= nimg*HWN) return;
    int img = i>>10, p = i&1023, y = p>>5, x = p&31;
    float acc = b[0];
    #pragma unroll
    for (int c2=0;c2<2;c2++)
    #pragma unroll
    for (int dy=-1;dy<=1;dy++)
    #pragma unroll
    for (int dx=-1;dx<=1;dx++){
        int yy=y+dy, xx=x+dx;
        if ((unsigned)yy<32u && (unsigned)xx<32u)
            acc += pool[img*2048 + c2*1024 + (yy<<5)+xx] * w[c2*9 + (dy+1)*3 + (dx+1)];
    }
    sa[i] = sigmf(acc);
}

// ---- attention pieces ----
__global__ void qfg_k()
{
    int wid  = (blockIdx.x*blockDim.x + threadIdx.x) >> 5;
    int lane = threadIdx.x & 31;
    if (wid >= SN*BN*CH) return;
    int c = wid & 127, b = (wid>>7)&15, s = wid>>11;
    const float* qp = g_q   + ((size_t)b*128 + c)*1024;
    const float* kp = g_ksa + (size_t)(s*16+b)*1024;
    float acc = 0.f;
    for (int p=lane; p<1024; p+=32) acc += qp[p]*kp[p];
    #pragma unroll
    for (int o=16;o;o>>=1) acc += __shfl_down_sync(0xffffffffu, acc, o);
    if (!lane) g_qfg[wid] = acc*(1.f/1024.f);
}

__global__ void sprob_k()
{
    int img = blockIdx.x;
    __shared__ float fq[128];
    int t = threadIdx.x;
    if (t < 128) fq[t] = g_qfg[img*128 + t];
    __syncthreads();
    for (int p=t; p<1024; p+=256){
        const float* kp = g_k + (size_t)img*CHW + p;
        float acc = 0.f;
        #pragma unroll 4
        for (int c=0;c<128;c++) acc += fq[c]*kp[(size_t)c<<10];
        g_sprob[img*1024 + p] = sigmf(acc);
    }
}

__global__ void tlogit_k()
{
    int img = blockIdx.x, b = img & 15;
    float acc = 0.f;
    for (int i=threadIdx.x; i<CHW; i+=256){
        int p = i & 1023;
        acc += g_q[(size_t)b*CHW + i]*g_qsa[b*1024+p]
             * g_k[(size_t)img*CHW + i]*g_ksa[img*1024+p];
    }
    #pragma unroll
    for (int o=16;o;o>>=1) acc += __shfl_down_sync(0xffffffffu, acc, o);
    __shared__ float sh[8];
    if ((threadIdx.x&31)==0) sh[threadIdx.x>>5] = acc;
    __syncthreads();
    if (threadIdx.x==0){
        float S=0.f;
        #pragma unroll
        for (int i=0;i<8;i++) S += sh[i];
        g_tl[img] = S * rsqrtf(131072.f);
    }
}

__global__ void tprob_k()
{
    int b = threadIdx.x;
    if (b >= 16) return;
    float m = -3.402823466e38f;
    #pragma unroll
    for (int s=0;s<8;s++) m = fmaxf(m, g_tl[s*16+b]);
    float e[8]; float sum = 0.f;
    #pragma unroll
    for (int s=0;s<8;s++){ e[s] = __expf(g_tl[s*16+b] - m); sum += e[s]; }
    float inv = 1.f/sum;
    #pragma unroll
    for (int s=0;s<8;s++) g_tp[s*16+b] = e[s]*inv;
}

__global__ void av_k()
{
    int i = blockIdx.x*blockDim.x + threadIdx.x;
    if (i >= BN*CHW/4) return;
    int base = i<<2;
    int b = base>>17; int c = (base>>10)&127; int p = base&1023;
    float4 acc = make_float4(0.f,0.f,0.f,0.f);
    #pragma unroll
    for (int s=0;s<8;s++){
        int img = s*16 + b;
        float tw = g_tp[img];
        float4 sp = *(const float4*)&g_sprob[img*1024 + p];
        float4 vv = *(const float4*)&g_v[((size_t)img*128 + c)*1024 + p];
        acc.x += tw*sp.x*vv.x; acc.y += tw*sp.y*vv.y;
        acc.z += tw*sp.z*vv.z; acc.w += tw*sp.w*vv.w;
    }
    *(float4*)&g_av[base] = acc;
}

__global__ void newout_k(const unsigned char* __restrict__ mask, float* __restrict__ out)
{
    int i = blockIdx.x*blockDim.x + threadIdx.x;
    if (i >= BN*CHW/4) return;
    int base = i<<2;
    int b = base>>17;
    float4 v = mask_at(mask, b) ? *(const float4*)&g_att[base]
                                : make_float4(0.f,0.f,0.f,0.f);
    *(float4*)&out[(size_t)2*BN*CHW + base] = v;
}

__global__ void semean_k()
{
    int b = blockIdx.x;
    int w = threadIdx.x>>5, lane = threadIdx.x&31;
    for (int c=w; c<128; c+=8){
        const float* p = g_o + ((size_t)b*128 + c)*1024;
        float s = 0.f;
        for (int i=lane; i<1024; i+=32) s += p[i];
        #pragma unroll
        for (int o=16;o;o>>=1) s += __shfl_down_sync(0xffffffffu, s, o);
        if (!lane) g_se1[b*128+c] = s*(1.f/1024.f);
    }
}

__global__ void sefc1_k(const float* __restrict__ w1, const float* __restrict__ b1)
{
    int t = threadIdx.x;
    int b = t>>5, j = t&31;
    float acc = b1[j];
    #pragma unroll 4
    for (int c=0;c<128;c++) acc += g_se1[b*128+c]*w1[j*128+c];
    g_se2[b*32+j] = fmaxf(acc, 0.f);
}

__global__ void sefc2_k(const float* __restrict__ w2, const float* __restrict__ b2)
{
    int i = blockIdx.x*blockDim.x + threadIdx.x;
    if (i >= BN*CH) return;
    int b = i>>7, c = i&127;
    float acc = b2[c];
    #pragma unroll
    for (int j=0;j<32;j++) acc += g_se2[b*32+j]*w2[c*32+j];
    g_se3[i] = sigmf(acc);
}

__global__ void final_k(float* __restrict__ out)
{
    int i = blockIdx.x*blockDim.x + threadIdx.x;
    if (i >= BN*CHW/4) return;
    int base = i<<2;
    int b = base>>17; int c = (base>>10)&127;
    float g = 1.f + g_se3[b*128+c];
    float4 o4 = *(const float4*)&g_o[base];
    o4.x*=g; o4.y*=g; o4.z*=g; o4.w*=g;
    *(float4*)&out[base] = o4;
    *(float4*)&out[(size_t)BN*CHW + base] = *(const float4*)&g_ht[base];
}

// ---- host launcher ----
extern "C" void kernel_launch(void* const* d_in, const int* in_sizes, int n_in,
                              void* d_out, int out_size)
{
    (void)in_sizes; (void)n_in; (void)out_size;
    const float* inputs  = (const float*)d_in[0];
    const float* hidden  = (const float*)d_in[1];
    const float* outq    = (const float*)d_in[2];
    const unsigned char* mask = (const unsigned char*)d_in[3];
    const float* enc_w   = (const float*)d_in[4];
    const float* enc_gw  = (const float*)d_in[5];
    const float* enc_gb  = (const float*)d_in[6];
    const float* qpre_w  = (const float*)d_in[7];
    const float* qpre_gw = (const float*)d_in[8];
    const float* qpre_gb = (const float*)d_in[9];
    const float* kpre_w  = (const float*)d_in[10];
    const float* kpre_gw = (const float*)d_in[11];
    const float* kpre_gb = (const float*)d_in[12];
    const float* vpre_w  = (const float*)d_in[13];
    const float* vpre_gw = (const float*)d_in[14];
    const float* vpre_gb = (const float*)d_in[15];
    const float* qsa_w   = (const float*)d_in[16];
    const float* qsa_b   = (const float*)d_in[17];
    const float* ksa_w   = (const float*)d_in[18];
    const float* ksa_b   = (const float*)d_in[19];
    const float* vpost_w = (const float*)d_in[20];
    const float* vpost_gw= (const float*)d_in[21];
    const float* vpost_gb= (const float*)d_in[22];
    const float* pos_emb = (const float*)d_in[23];
    const float* outt_w  = (const float*)d_in[24];
    const float* outt_gw = (const float*)d_in[25];
    const float* outt_gb = (const float*)d_in[26];
    const float* se_w1   = (const float*)d_in[27];
    const float* se_b1   = (const float*)d_in[28];
    const float* se_w2   = (const float*)d_in[29];
    const float* se_b2   = (const float*)d_in[30];
    float* out = (float*)d_out;

    float *ht,*q,*k,*v,*av,*att,*o,*stats,*pool,*qsa,*ksa,*peN,*wT,*Pb;
    __nv_bfloat16 *wrep;
    cudaGetSymbolAddress((void**)&ht,   g_ht);
    cudaGetSymbolAddress((void**)&q,    g_q);
    cudaGetSymbolAddress((void**)&k,    g_k);
    cudaGetSymbolAddress((void**)&v,    g_v);
    cudaGetSymbolAddress((void**)&av,   g_av);
    cudaGetSymbolAddress((void**)&att,  g_att);
    cudaGetSymbolAddress((void**)&o,    g_o);
    cudaGetSymbolAddress((void**)&stats,g_stats);
    cudaGetSymbolAddress((void**)&pool, g_pool);
    cudaGetSymbolAddress((void**)&qsa,  g_qsa);
    cudaGetSymbolAddress((void**)&ksa,  g_ksa);
    cudaGetSymbolAddress((void**)&peN,  g_peN);
    cudaGetSymbolAddress((void**)&wT,   g_wT);
    cudaGetSymbolAddress((void**)&Pb,   g_Pb);
    cudaGetSymbolAddress((void**)&wrep, g_wrep);

    const int OFF_ENC   = 0;
    const int OFF_QPRE  = 73728;
    const int OFF_OUTT  = 221184;
    const int OFF_VPOST = 442368;

    cudaFuncSetAttribute(mmaconv_k, cudaFuncAttributeMaxDynamicSharedMemorySize, DSMEM_TOTAL);

    transw_k<<<128,256>>>(enc_w,  wT+OFF_ENC,  64, 9);
    transw_k<<<256,256>>>(qpre_w, wT+OFF_QPRE, 128, 9);
    transw_k<<<384,256>>>(outt_w, wT+OFF_OUTT, 192, 9);
    transw_k<<<64,256>>>(vpost_w, wT+OFF_VPOST, 128, 1);
    pe_norm_k<<<8,256>>>(pos_emb, peN);
    wrep_k<<<1152,256>>>(kpre_w, wrep);
    wrep_k<<<1152,256>>>(vpre_w, wrep + 589824);
    pbconv_k<<<8,128>>>(vpre_w);
    zero_nhwc_k<<<2048,256>>>();
    fill_nhwc_k<<<4096,256>>>(hidden, outq);

    // ht = silu(gn(conv(inputs, enc_w)))
    conv3x3_k<<<BN*8,256>>>(inputs, nullptr, nullptr, wT+OFF_ENC, ht, 64, 0);
    gn_reduce_k<<<BN,256>>>(ht, stats);
    gn_apply_k<<<2048,256>>>(ht, stats, enc_gw, enc_gb, BN, 1);

    // q = gn(conv(ht, qpre_w))
    conv3x3_k<<<BN*8,256>>>(ht, nullptr, nullptr, wT+OFF_QPRE, q, 128, 0);
    gn_reduce_k<<<BN,256>>>(q, stats);
    gn_apply_k<<<2048,256>>>(q, stats, qpre_gw, qpre_gb, BN, 0);

    // k = gn(mmaconv(kv, kpre_w))
    mmaconv_k<<<640,256,DSMEM_TOTAL>>>(wrep, nullptr, k);
    gn_reduce_k<<<SBN,256>>>(k, stats);
    gn_apply_k<<<4096,256>>>(k, stats, kpre_gw, kpre_gb, SBN, 0);

    // v = gn(mmaconv(kv, vpre_w) + Pb)
    mmaconv_k<<<640,256,DSMEM_TOTAL>>>(wrep + 589824, Pb, v);
    gn_reduce_k<<<SBN,256>>>(v, stats);
    gn_apply_k<<<4096,256>>>(v, stats, vpre_gw, vpre_gb, SBN, 0);

    // spatial filters
    pool_k<<<(BN*HWN+255)/256,256>>>(q, pool, BN);
    saconv_k<<<(BN*HWN+255)/256,256>>>(pool, qsa_w, qsa_b, qsa, BN);
    pool_k<<<(SBN*HWN+255)/256,256>>>(k, pool, SBN);
    saconv_k<<<(SBN*HWN+255)/256,256>>>(pool, ksa_w, ksa_b, ksa, SBN);

    // attention
    qfg_k<<<2048,256>>>();
    sprob_k<<<SBN,256>>>();
    tlogit_k<<<SBN,256>>>();
    tprob_k<<<1,32>>>();
    av_k<<<2048,256>>>();

    // att = silu(gn(conv1x1(av)))
    conv1x1_k<<<BN*8,256>>>(av, wT+OFF_VPOST, att);
    gn_reduce_k<<<BN,256>>>(att, stats);
    gn_apply_k<<<2048,256>>>(att, stats, vpost_gw, vpost_gb, BN, 1);

    newout_k<<<2048,256>>>(mask, out);

    // o = silu(gn(conv(concat(inputs, att+ht))))
    conv3x3_k<<<BN*8,256>>>(inputs, att, ht, wT+OFF_OUTT, o, 192, 3);
    gn_reduce_k<<<BN,256>>>(o, stats);
    gn_apply_k<<<2048,256>>>(o, stats, outt_gw, outt_gb, BN, 1);

    semean_k<<<BN,256>>>();
    sefc1_k<<<1,512>>>(se_w1, se_b1);
    sefc2_k<<<8,256>>>(se_w2, se_b2);
    final_k<<<2048,256>>>(out);
}

// round 7
// speedup vs baseline: 2.4330x; 1.2304x over previous
#include <cuda_runtime.h>
#include <cuda_fp16.h>
#include <cstdint>

#define BN   16
#define CH   128
#define HWN  1024
#define SN   8
#define SBN  128
#define CHW  131072

#define GUARD   64
#define RPI     1344
#define TOTROWS (GUARD + 128*RPI)

// mmaconv smem layout (bytes): X window 336 rows x 256B, then 2 A buffers 64KB each
#define XB_OFF 0
#define AB0_OFF 86016
#define AB1_OFF 151552
#define DSMEM_TOTAL 217088

__device__ float g_ht [BN*CHW];
__device__ float g_q  [BN*CHW];
__device__ float g_k  [SBN*CHW];
__device__ float g_v  [SBN*CHW];
__device__ float g_av [BN*CHW];
__device__ float g_att[BN*CHW];
__device__ float g_o  [BN*CHW];
__device__ float g_stats[2*SBN];
__device__ float g_pool[SBN*2*HWN];
__device__ float g_qsa[BN*HWN];
__device__ float g_ksa[SBN*HWN];
__device__ float g_qfg[SN*BN*CH];
__device__ float g_sprob[SBN*HWN];
__device__ float g_tl[SN*BN];
__device__ float g_tp[SN*BN];
__device__ float g_peN[SN*2*CH];
__device__ float g_se1[BN*CH];
__device__ float g_se2[BN*32];
__device__ float g_se3[BN*CH];
__device__ float g_Pb[SN*CH*9];
__device__ float g_wT[524288];
__device__ __half g_nhwc[(size_t)TOTROWS*256];
__device__ __half g_wrep[1179648];  // 2 convs x [sp][tap*2+kc][co][128] fp16 hi/lo

__device__ __forceinline__ float sigmf(float x){ return 1.f/(1.f + __expf(-x)); }
__device__ __forceinline__ bool mask_at(const unsigned char* m, int b){
    if (m[1] != 0) return m[b] != 0;
    const unsigned int* w = (const unsigned int*)m;
    return w[b] != 0;
}

__device__ __forceinline__ uint32_t smem_u32(const void* p){
    uint32_t a;
    asm("{ .reg .u64 t; cvta.to.shared.u64 t, %1; cvt.u32.u64 %0, t; }" : "=r"(a) : "l"(p));
    return a;
}
__device__ __forceinline__ void mma16816(float* d, uint32_t a0, uint32_t a1, uint32_t a2,
                                         uint32_t a3, uint32_t b0, uint32_t b1){
    asm volatile("mma.sync.aligned.m16n8k16.row.col.f32.f16.f16.f32 "
        "{%0,%1,%2,%3}, {%4,%5,%6,%7}, {%8,%9}, {%0,%1,%2,%3};"
        : "+f"(d[0]),"+f"(d[1]),"+f"(d[2]),"+f"(d[3])
        : "r"(a0),"r"(a1),"r"(a2),"r"(a3),"r"(b0),"r"(b1));
}
__device__ __forceinline__ void ldsm4(uint32_t& r0,uint32_t& r1,uint32_t& r2,uint32_t& r3,
                                      uint32_t addr){
    asm volatile("ldmatrix.sync.aligned.m8n8.x4.shared.b16 {%0,%1,%2,%3}, [%4];"
        : "=r"(r0),"=r"(r1),"=r"(r2),"=r"(r3) : "r"(addr));
}
__device__ __forceinline__ void cpa16(uint32_t d, const void* s){
    asm volatile("cp.async.cg.shared.global [%0], [%1], 16;" :: "r"(d), "l"(s));
}
__device__ __forceinline__ void cp_commit(){ asm volatile("cp.async.commit_group;" ::: "memory"); }
__device__ __forceinline__ void cp_wait0(){ asm volatile("cp.async.wait_group 0;" ::: "memory"); }

// ---- weight transpose for FFMA convs ----
__global__ void transw_k(const float* __restrict__ w, float* __restrict__ wT,
                         int cin, int ktaps)
{
    int n = cin*ktaps*128;
    for (int i = blockIdx.x*blockDim.x + threadIdx.x; i < n; i += gridDim.x*blockDim.x){
        int co = i & 127;
        int r  = i >> 7;
        int tap = r % ktaps;
        int c   = r / ktaps;
        wT[i] = w[(co*cin + c)*ktaps + tap];
    }
}

__global__ void pe_norm_k(const float* __restrict__ pe, float* __restrict__ peN)
{
    int s = blockIdx.x, t = threadIdx.x;
    float v = pe[s*256 + t];
    float q = v*v;
    #pragma unroll
    for (int o=16;o;o>>=1) q += __shfl_down_sync(0xffffffffu, q, o);
    __shared__ float a[8];
    __shared__ float fac;
    if ((t&31)==0) a[t>>5] = q;
    __syncthreads();
    if (t==0){
        float S=0.f;
        #pragma unroll
        for (int i=0;i<8;i++) S += a[i];
        float n = sqrtf(S);
        fac = fminf(1.f, 1.f/fmaxf(n, 1e-7f));
    }
    __syncthreads();
    peN[s*256 + t] = v*fac;
}

// ---- NHWC fp16 repack ----
__global__ void zero_nhwc_k()
{
    size_t n = ((size_t)TOTROWS*256*2)/16;
    uint4 z = make_uint4(0,0,0,0);
    uint4* p = (uint4*)g_nhwc;
    for (size_t i = (size_t)blockIdx.x*blockDim.x + threadIdx.x; i < n;
         i += (size_t)gridDim.x*blockDim.x) p[i] = z;
}

__global__ void fill_nhwc_k(const float* __restrict__ hid, const float* __restrict__ oq)
{
    __shared__ float s[8][33];
    int t = threadIdx.x;
    int img = blockIdx.x>>5, y = blockIdx.x&31;
    int xg = t&31, cg = t>>5;
    int xs = t>>3, cl = t&7;
    size_t rb = GUARD + (size_t)img*RPI + (size_t)(y+1)*34;
    for (int cc=0; cc<32; cc++){
        int c = cc*8 + cg;
        const float* src = (c<128) ? hid + ((size_t)img*128 + c)*1024
                                   : oq  + ((size_t)img*128 + (c-128))*1024;
        s[cg][xg] = src[y*32 + xg];
        __syncthreads();
        g_nhwc[(rb + xs + 1)*256 + cc*8 + cl] = __float2half(s[cl][xs]);
        __syncthreads();
    }
}

// ---- weight repack: [sp][tap*2+kc][co][128k] fp16 hi/lo ----
__global__ void wrep_k(const float* __restrict__ w, __half* __restrict__ dst)
{
    int i = blockIdx.x*blockDim.x + threadIdx.x;
    if (i >= 294912) return;
    int kl = i & 127;
    int r = i >> 7;
    int co = r & 127; r >>= 7;
    int kc = r & 1;   r >>= 1;
    int tap = r;
    int cin = kc*128 + kl;
    float val = w[((size_t)co*256 + cin)*9 + tap];
    __half h = __float2half(val);
    int o = ((tap*2+kc)*128 + co)*128 + kl;
    dst[o] = h;
    dst[294912 + o] = __float2half(val - __half2float(h));
}

// ---- pe correction with border masks: Pb[s][co][yc*3+xc] ----
__global__ void pbconv_k(const float* __restrict__ w)
{
    int s = blockIdx.x, co = threadIdx.x;
    float P[9];
    #pragma unroll
    for (int tap=0;tap<9;tap++){
        float acc = 0.f;
        for (int c=0;c<256;c++)
            acc += g_peN[s*256 + c] * w[((size_t)co*256 + c)*9 + tap];
        P[tap] = acc;
    }
    #pragma unroll
    for (int yc=0;yc<3;yc++){
        #pragma unroll
        for (int xc=0;xc<3;xc++){
            float tot = 0.f;
            #pragma unroll
            for (int dy=0;dy<3;dy++){
                if ((yc==0 && dy==0) || (yc==2 && dy==2)) continue;
                float rs = P[dy*3+1];
                if (xc!=0) rs += P[dy*3+0];
                if (xc!=2) rs += P[dy*3+2];
                tot += rs;
            }
            g_Pb[(s*128+co)*9 + yc*3+xc] = tot;
        }
    }
}

// ---- staging helpers for mmaconv ----
__device__ __forceinline__ void stageA(uint32_t ab, const __half* wrep,
                                       int tap, int kc, int t)
{
    #pragma unroll
    for (int sp=0;sp<2;sp++){
        const char* src = (const char*)(wrep + (size_t)sp*294912 + (size_t)(tap*2+kc)*16384);
        #pragma unroll
        for (int j=0;j<8;j++){
            int i = j*256 + t;
            uint32_t r = (uint32_t)(i>>4), sg = (uint32_t)(i&15);
            cpa16(ab + sp*32768 + r*256 + ((sg^(r&7))<<4), src + (size_t)i*16);
        }
    }
}

__device__ __forceinline__ void conv_tap_mma(uint32_t xb, uint32_t ab, int tap,
                                             int lane, int cob, int pxb,
                                             float acc[4][8][4])
{
    const int lr   = lane & 7;
    const int hsA  = lane >> 4;
    const int hsB  = (lane >> 3) & 1;
    const int dy = tap/3, dx = tap - dy*3;
    const int dlt = (dy-1)*34 + (dx-1);

    uint32_t rowA[4], rsA[4];
    #pragma unroll
    for (int mi=0;mi<4;mi++){
        int r = cob + mi*16 + lr + ((lane>>3)&1)*8;
        rowA[mi] = (uint32_t)r*256u; rsA[mi] = (uint32_t)(r&7);
    }
    uint32_t rowB[4], rsB[4];
    #pragma unroll
    for (int nn=0;nn<4;nn++){
        int r = 36 + dlt + pxb + nn*16 + lr + (lane>>4)*8;
        rowB[nn] = (uint32_t)r*256u; rsB[nn] = (uint32_t)(r&7);
    }
    #pragma unroll
    for (int k8=0;k8<8;k8++){
        uint32_t a[2][4][4];
        #pragma unroll
        for (int sp=0;sp<2;sp++){
            #pragma unroll
            for (int mi=0;mi<4;mi++){
                uint32_t sgi = (uint32_t)(k8*2 + hsA);
                uint32_t ad = ab + (uint32_t)sp*32768u + rowA[mi] + ((sgi ^ rsA[mi])<<4);
                ldsm4(a[sp][mi][0],a[sp][mi][1],a[sp][mi][2],a[sp][mi][3], ad);
            }
        }
        #pragma unroll
        for (int nn=0;nn<4;nn++){
            uint32_t sgi = (uint32_t)(k8*2 + hsB);
            uint32_t ad = xb + rowB[nn] + ((sgi ^ rsB[nn])<<4);
            uint32_t b0,b1,b2,b3;
            ldsm4(b0,b1,b2,b3, ad);
            #pragma unroll
            for (int mi=0;mi<4;mi++){
                #pragma unroll
                for (int sp=0;sp<2;sp++){
                    mma16816(acc[mi][2*nn],   a[sp][mi][0],a[sp][mi][1],a[sp][mi][2],a[sp][mi][3], b0,b1);
                    mma16816(acc[mi][2*nn+1], a[sp][mi][0],a[sp][mi][1],a[sp][mi][2],a[sp][mi][3], b2,b3);
                }
            }
        }
    }
}

// ---- mma.sync fp16 implicit conv: D[128co,256px], X window resident ----
__global__ __launch_bounds__(256,1)
void mmaconv_k(const __half* __restrict__ wrep,
               const float* __restrict__ Pb,
               float* __restrict__ dst)
{
    extern __shared__ char dsm[];
    const uint32_t sb  = smem_u32(dsm);
    const uint32_t XB  = sb + XB_OFF;
    const uint32_t AB0 = sb + AB0_OFF;
    const uint32_t AB1 = sb + AB1_OFF;
    const int t = threadIdx.x;
    const int wid = t>>5, lane = t&31;
    const int img = blockIdx.x/5;
    const int p0  = (blockIdx.x%5)*256;
    const int s   = img>>4;
    const int cob = (wid&1)*64;
    const int pxb = (wid>>1)*64;

    float acc[4][8][4];
    #pragma unroll
    for (int mi=0;mi<4;mi++)
    #pragma unroll
    for (int ni=0;ni<8;ni++)
    #pragma unroll
    for (int e=0;e<4;e++) acc[mi][ni][e]=0.f;

    for (int kc=0; kc<2; kc++){
        // stage X window: 336 rows x 128k fp16 (one kc half)
        {
            const char* src = (const char*)(g_nhwc
                + ((size_t)GUARD + (size_t)img*RPI + p0 - 36)*256 + kc*128);
            #pragma unroll
            for (int j=0;j<21;j++){
                int i = j*256 + t;
                uint32_t r = (uint32_t)(i>>4), sg = (uint32_t)(i&15);
                cpa16(XB + r*256 + ((sg^(r&7))<<4), src + (size_t)r*512 + sg*16);
            }
            cp_commit();
        }
        stageA(AB0, wrep, 0, kc, t);
        cp_commit();
        cp_wait0(); __syncthreads();
        for (int tap=0; tap<9; tap++){
            uint32_t abuf = (tap&1) ? AB1 : AB0;
            if (tap < 8){
                stageA((tap&1) ? AB0 : AB1, wrep, tap+1, kc, t);
                cp_commit();
            }
            conv_tap_mma(XB, abuf, tap, lane, cob, pxb, acc);
            cp_wait0(); __syncthreads();
        }
    }

    // epilogue: direct register -> global stores with border mask + Pb correction
    const int g  = lane>>2;
    const int t2 = (lane&3)*2;
    #pragma unroll
    for (int mi=0;mi<4;mi++){
        #pragma unroll
        for (int ni=0;ni<8;ni++){
            #pragma unroll
            for (int e=0;e<4;e++){
                int co  = cob + mi*16 + g + ((e>>1)<<3);
                int col = pxb + ni*8 + t2 + (e&1);
                int pp  = p0 + col;
                int q34 = pp/34;
                int yy  = q34 - 1;
                int xx  = pp - q34*34 - 1;
                if ((unsigned)yy < 32u && (unsigned)xx < 32u){
                    float v = acc[mi][ni][e];
                    if (Pb){
                        int yc = (yy==0)?0:((yy==31)?2:1);
                        int xc = (xx==0)?0:((xx==31)?2:1);
                        v += Pb[(s*128+co)*9 + yc*3+xc];
                    }
                    dst[((size_t)img*128+co)*1024 + (yy<<5)+xx] = v;
                }
            }
        }
    }
}

// ---- FFMA 3x3 conv: modes 0 single, 3 concat(inputs64, s1+s2) ----
__global__ __launch_bounds__(256,2)
void conv3x3_k(const float* __restrict__ s0, const float* __restrict__ s1,
               const float* __restrict__ s2, const float* __restrict__ wT,
               float* __restrict__ dst, int cin, int mode)
{
    __shared__ float sIn[8*6*34];
    __shared__ float sW [8*9*128];
    const int t   = threadIdx.x;
    const int img = blockIdx.x >> 3;
    const int y0  = (blockIdx.x & 7) << 2;
    const int x   = t & 31;
    const int cg  = t >> 5;
    float acc[64];
    #pragma unroll
    for (int i=0;i<64;i++) acc[i]=0.f;

    const int nchunk = cin >> 3;
    for (int cc=0; cc<nchunk; cc++){
        const float* wp = wT + cc*9216;
        for (int e=t; e<9216; e+=256) sW[e] = wp[e];
        for (int e=t; e<1632; e+=256){
            int ci = e/204; int rem = e - ci*204;
            int r  = rem/34; int xx = rem - r*34;
            int y  = y0 - 1 + r; int xg = xx - 1;
            float val = 0.f;
            if ((unsigned)y < 32u && (unsigned)xg < 32u){
                int c = (cc<<3) + ci;
                int p = (y<<5) + xg;
                if (mode == 0){
                    val = s0[((size_t)img*cin + c)*1024 + p];
                } else {
                    val = (c < 64) ? s0[((size_t)img*64 + c)*1024 + p]
                                   : s1[((size_t)img*128 + (c-64))*1024 + p]
                                   + s2[((size_t)img*128 + (c-64))*1024 + p];
                }
            }
            sIn[(ci*6 + r)*34 + xx] = val;
        }
        __syncthreads();
        #pragma unroll 1
        for (int ci=0; ci<8; ci++){
            float inr[18];
            #pragma unroll
            for (int r=0;r<6;r++){
                #pragma unroll
                for (int d=0;d<3;d++) inr[r*3+d] = sIn[(ci*6+r)*34 + x + d];
            }
            #pragma unroll
            for (int tap=0; tap<9; tap++){
                const int dy = tap/3, dx = tap - dy*3;
                const float4* wq = (const float4*)&sW[(ci*9+tap)*128 + (cg<<4)];
                float4 w0 = wq[0], w1 = wq[1], w2 = wq[2], w3 = wq[3];
                #pragma unroll
                for (int y=0;y<4;y++){
                    float iv = inr[(y+dy)*3 + dx];
                    float* a = &acc[y*16];
                    a[0]+=iv*w0.x; a[1]+=iv*w0.y; a[2]+=iv*w0.z; a[3]+=iv*w0.w;
                    a[4]+=iv*w1.x; a[5]+=iv*w1.y; a[6]+=iv*w1.z; a[7]+=iv*w1.w;
                    a[8]+=iv*w2.x; a[9]+=iv*w2.y; a[10]+=iv*w2.z; a[11]+=iv*w2.w;
                    a[12]+=iv*w3.x; a[13]+=iv*w3.y; a[14]+=iv*w3.z; a[15]+=iv*w3.w;
                }
            }
        }
        __syncthreads();
    }
    #pragma unroll
    for (int j=0;j<16;j++){
        int co = (cg<<4) + j;
        #pragma unroll
        for (int y=0;y<4;y++)
            dst[((size_t)img*128 + co)*1024 + ((y0+y)<<5) + x] = acc[y*16+j];
    }
}

// ---- 1x1 conv (vpost) ----
__global__ __launch_bounds__(256,2)
void conv1x1_k(const float* __restrict__ src, const float* __restrict__ wT,
               float* __restrict__ dst)
{
    __shared__ float sIn[8*128];
    __shared__ float sW [8*128];
    const int t   = threadIdx.x;
    const int img = blockIdx.x >> 3;
    const int p0  = (blockIdx.x & 7) << 7;
    const int xl  = t & 31;
    const int cg  = t >> 5;
    float acc[64];
    #pragma unroll
    for (int i=0;i<64;i++) acc[i]=0.f;

    for (int cc=0; cc<16; cc++){
        for (int e=t; e<1024; e+=256){
            int ci = e>>7, i = e&127;
            sIn[e] = src[((size_t)img*128 + (cc<<3)+ci)*1024 + p0 + i];
            sW [e] = wT[(cc<<10) + e];
        }
        __syncthreads();
        #pragma unroll
        for (int ci=0;ci<8;ci++){
            float inr[4];
            #pragma unroll
            for (int y=0;y<4;y++) inr[y] = sIn[ci*128 + (y<<5) + xl];
            const float4* wq = (const float4*)&sW[ci*128 + (cg<<4)];
            float4 w0=wq[0], w1=wq[1], w2=wq[2], w3=wq[3];
            #pragma unroll
            for (int y=0;y<4;y++){
                float iv = inr[y];
                float* a = &acc[y*16];
                a[0]+=iv*w0.x; a[1]+=iv*w0.y; a[2]+=iv*w0.z; a[3]+=iv*w0.w;
                a[4]+=iv*w1.x; a[5]+=iv*w1.y; a[6]+=iv*w1.z; a[7]+=iv*w1.w;
                a[8]+=iv*w2.x; a[9]+=iv*w2.y; a[10]+=iv*w2.z; a[11]+=iv*w2.w;
                a[12]+=iv*w3.x; a[13]+=iv*w3.y; a[14]+=iv*w3.z; a[15]+=iv*w3.w;
            }
        }
        __syncthreads();
    }
    #pragma unroll
    for (int j=0;j<16;j++){
        int co = (cg<<4)+j;
        #pragma unroll
        for (int y=0;y<4;y++)
            dst[((size_t)img*128+co)*1024 + p0 + (y<<5) + xl] = acc[y*16+j];
    }
}

// ---- GroupNorm ----
__global__ void gn_reduce_k(const float* __restrict__ x, float* __restrict__ stats)
{
    const int img = blockIdx.x;
    const float4* p = (const float4*)(x + (size_t)img*CHW);
    float s=0.f, s2=0.f;
    for (int i=threadIdx.x; i<32768; i+=blockDim.x){
        float4 v = p[i];
        s  += v.x+v.y+v.z+v.w;
        s2 += v.x*v.x+v.y*v.y+v.z*v.z+v.w*v.w;
    }
    #pragma unroll
    for (int o=16;o;o>>=1){
        s  += __shfl_down_sync(0xffffffffu, s , o);
        s2 += __shfl_down_sync(0xffffffffu, s2, o);
    }
    __shared__ float sa[8], sb[8];
    if ((threadIdx.x&31)==0){ sa[threadIdx.x>>5]=s; sb[threadIdx.x>>5]=s2; }
    __syncthreads();
    if (threadIdx.x==0){
        float S=0.f, S2=0.f;
        #pragma unroll
        for (int i=0;i<8;i++){ S+=sa[i]; S2+=sb[i]; }
        float mu  = S*(1.f/131072.f);
        float var = S2*(1.f/131072.f) - mu*mu;
        stats[img*2]   = mu;
        stats[img*2+1] = rsqrtf(var + 1e-5f);
    }
}

__global__ void gn_apply_k(float* __restrict__ x, const float* __restrict__ stats,
                           const float* __restrict__ gw, const float* __restrict__ gb,
                           int nimg, int act)
{
    int n4 = nimg*32768;
    for (int i = blockIdx.x*blockDim.x + threadIdx.x; i < n4; i += gridDim.x*blockDim.x){
        int base = i<<2;
        int img = base>>17; int c = (base>>10)&127;
        float mu = stats[2*img], rs = stats[2*img+1];
        float sc = rs*gw[c];
        float sh = gb[c] - mu*sc;
        float4 v = ((float4*)x)[i];
        v.x = v.x*sc+sh; v.y = v.y*sc+sh; v.z = v.z*sc+sh; v.w = v.w*sc+sh;
        if (act){
            v.x *= sigmf(v.x); v.y *= sigmf(v.y); v.z *= sigmf(v.z); v.w *= sigmf(v.w);
        }
        ((float4*)x)[i] = v;
    }
}

// ---- pooling / spatial filter ----
__global__ void pool_k(const float* __restrict__ x, float* __restrict__ pool, int nimg)
{
    int i = blockIdx.x*blockDim.x + threadIdx.x;
    if (i >= nimg*HWN) return;
    int img = i>>10, p = i&1023;
    const float* base = x + (size_t)img*CHW + p;
    float s = 0.f, m = -3.402823466e38f;
    #pragma unroll 4
    for (int c=0;c<128;c++){
        float v = base[(size_t)c<<10];
        s += v; m = fmaxf(m, v);
    }
    pool[img*2048 + p]        = s*(1.f/128.f);
    pool[img*2048 + 1024 + p] = m;
}

__global__ void saconv_k(const float* __restrict__ pool, const float* __restrict__ w,
                         const float* __restrict__ b, float* __restrict__ sa, int nimg)
{
    int i = blockIdx.x*blockDim.x + threadIdx.x;
    if (i >= nimg*HWN) return;
    int img = i>>10, p = i&1023, y = p>>5, x = p&31;
    float acc = b[0];
    #pragma unroll
    for (int c2=0;c2<2;c2++)
    #pragma unroll
    for (int dy=-1;dy<=1;dy++)
    #pragma unroll
    for (int dx=-1;dx<=1;dx++){
        int yy=y+dy, xx=x+dx;
        if ((unsigned)yy<32u && (unsigned)xx<32u)
            acc += pool[img*2048 + c2*1024 + (yy<<5)+xx] * w[c2*9 + (dy+1)*3 + (dx+1)];
    }
    sa[i] = sigmf(acc);
}

// ---- attention pieces ----
__global__ void qfg_k()
{
    int wid  = (blockIdx.x*blockDim.x + threadIdx.x) >> 5;
    int lane = threadIdx.x & 31;
    if (wid >= SN*BN*CH) return;
    int c = wid & 127, b = (wid>>7)&15, s = wid>>11;
    const float* qp = g_q   + ((size_t)b*128 + c)*1024;
    const float* kp = g_ksa + (size_t)(s*16+b)*1024;
    float acc = 0.f;
    for (int p=lane; p<1024; p+=32) acc += qp[p]*kp[p];
    #pragma unroll
    for (int o=16;o;o>>=1) acc += __shfl_down_sync(0xffffffffu, acc, o);
    if (!lane) g_qfg[wid] = acc*(1.f/1024.f);
}

__global__ void sprob_k()
{
    int img = blockIdx.x;
    __shared__ float fq[128];
    int t = threadIdx.x;
    if (t < 128) fq[t] = g_qfg[img*128 + t];
    __syncthreads();
    for (int p=t; p<1024; p+=256){
        const float* kp = g_k + (size_t)img*CHW + p;
        float acc = 0.f;
        #pragma unroll 4
        for (int c=0;c<128;c++) acc += fq[c]*kp[(size_t)c<<10];
        g_sprob[img*1024 + p] = sigmf(acc);
    }
}

__global__ void tlogit_k()
{
    int img = blockIdx.x, b = img & 15;
    float acc = 0.f;
    for (int i=threadIdx.x; i<CHW; i+=256){
        int p = i & 1023;
        acc += g_q[(size_t)b*CHW + i]*g_qsa[b*1024+p]
             * g_k[(size_t)img*CHW + i]*g_ksa[img*1024+p];
    }
    #pragma unroll
    for (int o=16;o;o>>=1) acc += __shfl_down_sync(0xffffffffu, acc, o);
    __shared__ float sh[8];
    if ((threadIdx.x&31)==0) sh[threadIdx.x>>5] = acc;
    __syncthreads();
    if (threadIdx.x==0){
        float S=0.f;
        #pragma unroll
        for (int i=0;i<8;i++) S += sh[i];
        g_tl[img] = S * rsqrtf(131072.f);
    }
}

__global__ void tprob_k()
{
    int b = threadIdx.x;
    if (b >= 16) return;
    float m = -3.402823466e38f;
    #pragma unroll
    for (int s=0;s<8;s++) m = fmaxf(m, g_tl[s*16+b]);
    float e[8]; float sum = 0.f;
    #pragma unroll
    for (int s=0;s<8;s++){ e[s] = __expf(g_tl[s*16+b] - m); sum += e[s]; }
    float inv = 1.f/sum;
    #pragma unroll
    for (int s=0;s<8;s++) g_tp[s*16+b] = e[s]*inv;
}

__global__ void av_k()
{
    int i = blockIdx.x*blockDim.x + threadIdx.x;
    if (i >= BN*CHW/4) return;
    int base = i<<2;
    int b = base>>17; int c = (base>>10)&127; int p = base&1023;
    float4 acc = make_float4(0.f,0.f,0.f,0.f);
    #pragma unroll
    for (int s=0;s<8;s++){
        int img = s*16 + b;
        float tw = g_tp[img];
        float4 sp = *(const float4*)&g_sprob[img*1024 + p];
        float4 vv = *(const float4*)&g_v[((size_t)img*128 + c)*1024 + p];
        acc.x += tw*sp.x*vv.x; acc.y += tw*sp.y*vv.y;
        acc.z += tw*sp.z*vv.z; acc.w += tw*sp.w*vv.w;
    }
    *(float4*)&g_av[base] = acc;
}

__global__ void newout_k(const unsigned char* __restrict__ mask, float* __restrict__ out)
{
    int i = blockIdx.x*blockDim.x + threadIdx.x;
    if (i >= BN*CHW/4) return;
    int base = i<<2;
    int b = base>>17;
    float4 v = mask_at(mask, b) ? *(const float4*)&g_att[base]
                                : make_float4(0.f,0.f,0.f,0.f);
    *(float4*)&out[(size_t)2*BN*CHW + base] = v;
}

__global__ void semean_k()
{
    int b = blockIdx.x;
    int w = threadIdx.x>>5, lane = threadIdx.x&31;
    for (int c=w; c<128; c+=8){
        const float* p = g_o + ((size_t)b*128 + c)*1024;
        float s = 0.f;
        for (int i=lane; i<1024; i+=32) s += p[i];
        #pragma unroll
        for (int o=16;o;o>>=1) s += __shfl_down_sync(0xffffffffu, s, o);
        if (!lane) g_se1[b*128+c] = s*(1.f/1024.f);
    }
}

__global__ void sefc1_k(const float* __restrict__ w1, const float* __restrict__ b1)
{
    int t = threadIdx.x;
    int b = t>>5, j = t&31;
    float acc = b1[j];
    #pragma unroll 4
    for (int c=0;c<128;c++) acc += g_se1[b*128+c]*w1[j*128+c];
    g_se2[b*32+j] = fmaxf(acc, 0.f);
}

__global__ void sefc2_k(const float* __restrict__ w2, const float* __restrict__ b2)
{
    int i = blockIdx.x*blockDim.x + threadIdx.x;
    if (i >= BN*CH) return;
    int b = i>>7, c = i&127;
    float acc = b2[c];
    #pragma unroll
    for (int j=0;j<32;j++) acc += g_se2[b*32+j]*w2[c*32+j];
    g_se3[i] = sigmf(acc);
}

__global__ void final_k(float* __restrict__ out)
{
    int i = blockIdx.x*blockDim.x + threadIdx.x;
    if (i >= BN*CHW/4) return;
    int base = i<<2;
    int b = base>>17; int c = (base>>10)&127;
    float g = 1.f + g_se3[b*128+c];
    float4 o4 = *(const float4*)&g_o[base];
    o4.x*=g; o4.y*=g; o4.z*=g; o4.w*=g;
    *(float4*)&out[base] = o4;
    *(float4*)&out[(size_t)BN*CHW + base] = *(const float4*)&g_ht[base];
}

// ---- host launcher ----
extern "C" void kernel_launch(void* const* d_in, const int* in_sizes, int n_in,
                              void* d_out, int out_size)
{
    (void)in_sizes; (void)n_in; (void)out_size;
    const float* inputs  = (const float*)d_in[0];
    const float* hidden  = (const float*)d_in[1];
    const float* outq    = (const float*)d_in[2];
    const unsigned char* mask = (const unsigned char*)d_in[3];
    const float* enc_w   = (const float*)d_in[4];
    const float* enc_gw  = (const float*)d_in[5];
    const float* enc_gb  = (const float*)d_in[6];
    const float* qpre_w  = (const float*)d_in[7];
    const float* qpre_gw = (const float*)d_in[8];
    const float* qpre_gb = (const float*)d_in[9];
    const float* kpre_w  = (const float*)d_in[10];
    const float* kpre_gw = (const float*)d_in[11];
    const float* kpre_gb = (const float*)d_in[12];
    const float* vpre_w  = (const float*)d_in[13];
    const float* vpre_gw = (const float*)d_in[14];
    const float* vpre_gb = (const float*)d_in[15];
    const float* qsa_w   = (const float*)d_in[16];
    const float* qsa_b   = (const float*)d_in[17];
    const float* ksa_w   = (const float*)d_in[18];
    const float* ksa_b   = (const float*)d_in[19];
    const float* vpost_w = (const float*)d_in[20];
    const float* vpost_gw= (const float*)d_in[21];
    const float* vpost_gb= (const float*)d_in[22];
    const float* pos_emb = (const float*)d_in[23];
    const float* outt_w  = (const float*)d_in[24];
    const float* outt_gw = (const float*)d_in[25];
    const float* outt_gb = (const float*)d_in[26];
    const float* se_w1   = (const float*)d_in[27];
    const float* se_b1   = (const float*)d_in[28];
    const float* se_w2   = (const float*)d_in[29];
    const float* se_b2   = (const float*)d_in[30];
    float* out = (float*)d_out;

    float *ht,*q,*k,*v,*av,*att,*o,*stats,*pool,*qsa,*ksa,*peN,*wT,*Pb;
    __half *wrep;
    cudaGetSymbolAddress((void**)&ht,   g_ht);
    cudaGetSymbolAddress((void**)&q,    g_q);
    cudaGetSymbolAddress((void**)&k,    g_k);
    cudaGetSymbolAddress((void**)&v,    g_v);
    cudaGetSymbolAddress((void**)&av,   g_av);
    cudaGetSymbolAddress((void**)&att,  g_att);
    cudaGetSymbolAddress((void**)&o,    g_o);
    cudaGetSymbolAddress((void**)&stats,g_stats);
    cudaGetSymbolAddress((void**)&pool, g_pool);
    cudaGetSymbolAddress((void**)&qsa,  g_qsa);
    cudaGetSymbolAddress((void**)&ksa,  g_ksa);
    cudaGetSymbolAddress((void**)&peN,  g_peN);
    cudaGetSymbolAddress((void**)&wT,   g_wT);
    cudaGetSymbolAddress((void**)&Pb,   g_Pb);
    cudaGetSymbolAddress((void**)&wrep, g_wrep);

    const int OFF_ENC   = 0;
    const int OFF_QPRE  = 73728;
    const int OFF_OUTT  = 221184;
    const int OFF_VPOST = 442368;

    cudaFuncSetAttribute(mmaconv_k, cudaFuncAttributeMaxDynamicSharedMemorySize, DSMEM_TOTAL);

    // launch order arranged so the profiled launch (#4) is mmaconv_k
    zero_nhwc_k<<<2048,256>>>();                              // 1
    fill_nhwc_k<<<4096,256>>>(hidden, outq);                  // 2
    wrep_k<<<1152,256>>>(kpre_w, wrep);                       // 3
    mmaconv_k<<<640,256,DSMEM_TOTAL>>>(wrep, nullptr, k);     // 4  <- profiled
    wrep_k<<<1152,256>>>(vpre_w, wrep + 589824);              // 5
    pe_norm_k<<<8,256>>>(pos_emb, peN);                       // 6
    pbconv_k<<<8,128>>>(vpre_w);                              // 7
    mmaconv_k<<<640,256,DSMEM_TOTAL>>>(wrep + 589824, Pb, v); // 8

    transw_k<<<128,256>>>(enc_w,  wT+OFF_ENC,  64, 9);
    transw_k<<<256,256>>>(qpre_w, wT+OFF_QPRE, 128, 9);
    transw_k<<<384,256>>>(outt_w, wT+OFF_OUTT, 192, 9);
    transw_k<<<64,256>>>(vpost_w, wT+OFF_VPOST, 128, 1);

    // ht = silu(gn(conv(inputs, enc_w)))
    conv3x3_k<<<BN*8,256>>>(inputs, nullptr, nullptr, wT+OFF_ENC, ht, 64, 0);
    gn_reduce_k<<<BN,256>>>(ht, stats);
    gn_apply_k<<<2048,256>>>(ht, stats, enc_gw, enc_gb, BN, 1);

    // q = gn(conv(ht, qpre_w))
    conv3x3_k<<<BN*8,256>>>(ht, nullptr, nullptr, wT+OFF_QPRE, q, 128, 0);
    gn_reduce_k<<<BN,256>>>(q, stats);
    gn_apply_k<<<2048,256>>>(q, stats, qpre_gw, qpre_gb, BN, 0);

    // gn for k and v
    gn_reduce_k<<<SBN,256>>>(k, stats);
    gn_apply_k<<<4096,256>>>(k, stats, kpre_gw, kpre_gb, SBN, 0);
    gn_reduce_k<<<SBN,256>>>(v, stats);
    gn_apply_k<<<4096,256>>>(v, stats, vpre_gw, vpre_gb, SBN, 0);

    // spatial filters
    pool_k<<<(BN*HWN+255)/256,256>>>(q, pool, BN);
    saconv_k<<<(BN*HWN+255)/256,256>>>(pool, qsa_w, qsa_b, qsa, BN);
    pool_k<<<(SBN*HWN+255)/256,256>>>(k, pool, SBN);
    saconv_k<<<(SBN*HWN+255)/256,256>>>(pool, ksa_w, ksa_b, ksa, SBN);

    // attention
    qfg_k<<<2048,256>>>();
    sprob_k<<<SBN,256>>>();
    tlogit_k<<<SBN,256>>>();
    tprob_k<<<1,32>>>();
    av_k<<<2048,256>>>();

    // att = silu(gn(conv1x1(av)))
    conv1x1_k<<<BN*8,256>>>(av, wT+OFF_VPOST, att);
    gn_reduce_k<<<BN,256>>>(att, stats);
    gn_apply_k<<<2048,256>>>(att, stats, vpost_gw, vpost_gb, BN, 1);

    newout_k<<<2048,256>>>(mask, out);

    // o = silu(gn(conv(concat(inputs, att+ht))))
    conv3x3_k<<<BN*8,256>>>(inputs, att, ht, wT+OFF_OUTT, o, 192, 3);
    gn_reduce_k<<<BN,256>>>(o, stats);
    gn_apply_k<<<2048,256>>>(o, stats, outt_gw, outt_gb, BN, 1);

    semean_k<<<BN,256>>>();
    sefc1_k<<<1,512>>>(se_w1, se_b1);
    sefc2_k<<<8,256>>>(se_w2, se_b2);
    final_k<<<2048,256>>>(out);
}

// round 8
// speedup vs baseline: 2.5729x; 1.0575x over previous
#include <cuda_runtime.h>
#include <cuda_fp16.h>
#include <cstdint>

#define BN   16
#define CH   128
#define HWN  1024
#define SN   8
#define SBN  128
#define CHW  131072

#define GUARD   64
#define RPI     1344
#define TOTROWS (GUARD + 128*RPI + 256)   // +tail guard rows

// mmaconv smem (bytes): X window 200 rows x 256B, then one A buffer 32KB
#define AB_OFF 51200
#define DSMEM_TOTAL 83968

__device__ float g_ht [BN*CHW];
__device__ float g_q  [BN*CHW];
__device__ float g_k  [SBN*CHW];
__device__ float g_v  [SBN*CHW];
__device__ float g_av [BN*CHW];
__device__ float g_att[BN*CHW];
__device__ float g_o  [BN*CHW];
__device__ float g_stats[2*SBN];
__device__ float g_pool[SBN*2*HWN];
__device__ float g_qsa[BN*HWN];
__device__ float g_ksa[SBN*HWN];
__device__ float g_qfg[SN*BN*CH];
__device__ float g_sprob[SBN*HWN];
__device__ float g_tl[SN*BN];
__device__ float g_tp[SN*BN];
__device__ float g_peN[SN*2*CH];
__device__ float g_se1[BN*CH];
__device__ float g_se2[BN*32];
__device__ float g_se3[BN*CH];
__device__ float g_Pb[SN*CH*9];
__device__ float g_wT[524288];
__device__ __half g_nhwc[(size_t)TOTROWS*256];
__device__ __half g_wrep[1179648];  // 2 convs x [sp][tap*2+kc][co][128] fp16 hi/lo

__device__ __forceinline__ float sigmf(float x){ return 1.f/(1.f + __expf(-x)); }
__device__ __forceinline__ bool mask_at(const unsigned char* m, int b){
    if (m[1] != 0) return m[b] != 0;
    const unsigned int* w = (const unsigned int*)m;
    return w[b] != 0;
}

__device__ __forceinline__ uint32_t smem_u32(const void* p){
    uint32_t a;
    asm("{ .reg .u64 t; cvta.to.shared.u64 t, %1; cvt.u32.u64 %0, t; }" : "=r"(a) : "l"(p));
    return a;
}
__device__ __forceinline__ void mma16816(float* d, uint32_t a0, uint32_t a1, uint32_t a2,
                                         uint32_t a3, uint32_t b0, uint32_t b1){
    asm volatile("mma.sync.aligned.m16n8k16.row.col.f32.f16.f16.f32 "
        "{%0,%1,%2,%3}, {%4,%5,%6,%7}, {%8,%9}, {%0,%1,%2,%3};"
        : "+f"(d[0]),"+f"(d[1]),"+f"(d[2]),"+f"(d[3])
        : "r"(a0),"r"(a1),"r"(a2),"r"(a3),"r"(b0),"r"(b1));
}
__device__ __forceinline__ void ldsm4(uint32_t& r0,uint32_t& r1,uint32_t& r2,uint32_t& r3,
                                      uint32_t addr){
    asm volatile("ldmatrix.sync.aligned.m8n8.x4.shared.b16 {%0,%1,%2,%3}, [%4];"
        : "=r"(r0),"=r"(r1),"=r"(r2),"=r"(r3) : "r"(addr));
}
__device__ __forceinline__ void cpa16(uint32_t d, const void* s){
    asm volatile("cp.async.cg.shared.global [%0], [%1], 16;" :: "r"(d), "l"(s));
}
__device__ __forceinline__ void cp_commit(){ asm volatile("cp.async.commit_group;" ::: "memory"); }
__device__ __forceinline__ void cp_wait0(){ asm volatile("cp.async.wait_group 0;" ::: "memory"); }

// ---- weight transpose for FFMA convs ----
__global__ void transw_k(const float* __restrict__ w, float* __restrict__ wT,
                         int cin, int ktaps)
{
    int n = cin*ktaps*128;
    for (int i = blockIdx.x*blockDim.x + threadIdx.x; i < n; i += gridDim.x*blockDim.x){
        int co = i & 127;
        int r  = i >> 7;
        int tap = r % ktaps;
        int c   = r / ktaps;
        wT[i] = w[(co*cin + c)*ktaps + tap];
    }
}

__global__ void pe_norm_k(const float* __restrict__ pe, float* __restrict__ peN)
{
    int s = blockIdx.x, t = threadIdx.x;
    float v = pe[s*256 + t];
    float q = v*v;
    #pragma unroll
    for (int o=16;o;o>>=1) q += __shfl_down_sync(0xffffffffu, q, o);
    __shared__ float a[8];
    __shared__ float fac;
    if ((t&31)==0) a[t>>5] = q;
    __syncthreads();
    if (t==0){
        float S=0.f;
        #pragma unroll
        for (int i=0;i<8;i++) S += a[i];
        float n = sqrtf(S);
        fac = fminf(1.f, 1.f/fmaxf(n, 1e-7f));
    }
    __syncthreads();
    peN[s*256 + t] = v*fac;
}

// ---- NHWC fp16 repack ----
__global__ void zero_nhwc_k()
{
    size_t n = ((size_t)TOTROWS*256*2)/16;
    uint4 z = make_uint4(0,0,0,0);
    uint4* p = (uint4*)g_nhwc;
    for (size_t i = (size_t)blockIdx.x*blockDim.x + threadIdx.x; i < n;
         i += (size_t)gridDim.x*blockDim.x) p[i] = z;
}

// one block per (img, y): load 256c x 32x into smem, ONE sync, coalesced writes
__global__ void fill_nhwc_k(const float* __restrict__ hid, const float* __restrict__ oq)
{
    __shared__ float s[32][257];
    int t = threadIdx.x;
    int img = blockIdx.x>>5, y = blockIdx.x&31;
    int xg = t&31, cg = t>>5;
    size_t rb = GUARD + (size_t)img*RPI + (size_t)(y+1)*34;
    #pragma unroll
    for (int cc=0; cc<32; cc++){
        int c = cc*8 + cg;
        const float* src = (c<128) ? hid + ((size_t)img*128 + c)*1024
                                   : oq  + ((size_t)img*128 + (c-128))*1024;
        s[xg][c] = src[y*32 + xg];
    }
    __syncthreads();
    #pragma unroll
    for (int xs=0; xs<32; xs++)
        g_nhwc[(rb + xs + 1)*256 + t] = __float2half(s[xs][t]);
}

// ---- weight repack: [sp][tap*2+kc][co][128k] fp16 hi/lo ----
__global__ void wrep_k(const float* __restrict__ w, __half* __restrict__ dst)
{
    int i = blockIdx.x*blockDim.x + threadIdx.x;
    if (i >= 294912) return;
    int kl = i & 127;
    int r = i >> 7;
    int co = r & 127; r >>= 7;
    int kc = r & 1;   r >>= 1;
    int tap = r;
    int cin = kc*128 + kl;
    float val = w[((size_t)co*256 + cin)*9 + tap];
    __half h = __float2half(val);
    int o = ((tap*2+kc)*128 + co)*128 + kl;
    dst[o] = h;
    dst[294912 + o] = __float2half(val - __half2float(h));
}

// ---- pe correction with border masks: Pb[s][co][yc*3+xc] ----
__global__ void pbconv_k(const float* __restrict__ w)
{
    int s = blockIdx.x, co = threadIdx.x;
    float P[9];
    #pragma unroll
    for (int tap=0;tap<9;tap++){
        float acc = 0.f;
        for (int c=0;c<256;c++)
            acc += g_peN[s*256 + c] * w[((size_t)co*256 + c)*9 + tap];
        P[tap] = acc;
    }
    #pragma unroll
    for (int yc=0;yc<3;yc++){
        #pragma unroll
        for (int xc=0;xc<3;xc++){
            float tot = 0.f;
            #pragma unroll
            for (int dy=0;dy<3;dy++){
                if ((yc==0 && dy==0) || (yc==2 && dy==2)) continue;
                float rs = P[dy*3+1];
                if (xc!=0) rs += P[dy*3+0];
                if (xc!=2) rs += P[dy*3+2];
                tot += rs;
            }
            g_Pb[(s*128+co)*9 + yc*3+xc] = tot;
        }
    }
}

// ---- per-(tap,sp) MMA: 64co x 32px per warp ----
__device__ __forceinline__ void conv_tap_sp(uint32_t xb, uint32_t ab, int tap,
                                            int lane, int cob, int pxb,
                                            float acc[4][4][4])
{
    const int lr  = lane & 7;
    const int hsA = lane >> 4;
    const int hsB = (lane >> 3) & 1;
    const int dy = tap/3, dx = tap - dy*3;
    const int dlt = (dy-1)*34 + (dx-1);

    uint32_t rowA[4], rsA[4];
    #pragma unroll
    for (int mi=0;mi<4;mi++){
        int r = cob + mi*16 + lr + ((lane>>3)&1)*8;
        rowA[mi] = (uint32_t)r*256u; rsA[mi] = (uint32_t)(r&7);
    }
    uint32_t rowB[2], rsB[2];
    #pragma unroll
    for (int nn=0;nn<2;nn++){
        int r = 36 + dlt + pxb + nn*16 + lr + (lane>>4)*8;
        rowB[nn] = (uint32_t)r*256u; rsB[nn] = (uint32_t)(r&7);
    }
    #pragma unroll
    for (int k8=0;k8<8;k8++){
        uint32_t a[4][4];
        #pragma unroll
        for (int mi=0;mi<4;mi++){
            uint32_t sgi = (uint32_t)(k8*2 + hsA);
            uint32_t ad = ab + rowA[mi] + ((sgi ^ rsA[mi])<<4);
            ldsm4(a[mi][0],a[mi][1],a[mi][2],a[mi][3], ad);
        }
        #pragma unroll
        for (int nn=0;nn<2;nn++){
            uint32_t sgi = (uint32_t)(k8*2 + hsB);
            uint32_t ad = xb + rowB[nn] + ((sgi ^ rsB[nn])<<4);
            uint32_t b0,b1,b2,b3;
            ldsm4(b0,b1,b2,b3, ad);
            #pragma unroll
            for (int mi=0;mi<4;mi++){
                mma16816(acc[mi][2*nn],   a[mi][0],a[mi][1],a[mi][2],a[mi][3], b0,b1);
                mma16816(acc[mi][2*nn+1], a[mi][0],a[mi][1],a[mi][2],a[mi][3], b2,b3);
            }
        }
    }
}

// ---- mma.sync fp16 implicit conv: D[128co,128px], 2 CTAs/SM ----
__global__ __launch_bounds__(256,2)
void mmaconv_k(const __half* __restrict__ wrep,
               const float* __restrict__ Pb,
               float* __restrict__ dst)
{
    extern __shared__ char dsm[];
    const uint32_t sb = smem_u32(dsm);
    const uint32_t XB = sb;
    const uint32_t AB = sb + AB_OFF;
    const int t = threadIdx.x;
    const int wid = t>>5, lane = t&31;
    const int img = blockIdx.x/10;
    const int p0  = (blockIdx.x%10)*128;
    const int s   = img>>4;
    const int cob = (wid&1)*64;
    const int pxb = (wid>>1)*32;

    float acc[4][4][4];
    #pragma unroll
    for (int mi=0;mi<4;mi++)
    #pragma unroll
    for (int ni=0;ni<4;ni++)
    #pragma unroll
    for (int e=0;e<4;e++) acc[mi][ni][e]=0.f;

    for (int kc=0; kc<2; kc++){
        // stage X window: 200 rows x 128k fp16 (one kc half)
        {
            const char* src = (const char*)g_nhwc
                + ((size_t)GUARD + (size_t)img*RPI + p0 - 36)*512 + kc*256;
            #pragma unroll
            for (int j=0;j<13;j++){
                int i = j*256 + t;
                if (i < 3200){
                    uint32_t r = (uint32_t)(i>>4), sg = (uint32_t)(i&15);
                    cpa16(XB + r*256 + ((sg^(r&7))<<4), src + (size_t)r*512 + sg*16);
                }
            }
            cp_commit();
        }
        for (int tap=0; tap<9; tap++){
            #pragma unroll
            for (int sp=0; sp<2; sp++){
                const char* asrc = (const char*)(wrep + (size_t)sp*294912
                                                 + (size_t)(tap*2+kc)*16384);
                #pragma unroll
                for (int j=0;j<8;j++){
                    int i = j*256 + t;
                    uint32_t r = (uint32_t)(i>>4), sg = (uint32_t)(i&15);
                    cpa16(AB + r*256 + ((sg^(r&7))<<4), asrc + (size_t)i*16);
                }
                cp_commit(); cp_wait0(); __syncthreads();
                conv_tap_sp(XB, AB, tap, lane, cob, pxb, acc);
                __syncthreads();
            }
        }
    }

    // epilogue: register -> global stores with border mask + Pb correction
    const int g  = lane>>2;
    const int t2 = (lane&3)*2;
    #pragma unroll
    for (int mi=0;mi<4;mi++){
        #pragma unroll
        for (int n8=0;n8<4;n8++){
            #pragma unroll
            for (int e=0;e<4;e++){
                int co  = cob + mi*16 + g + ((e>>1)<<3);
                int col = pxb + n8*8 + t2 + (e&1);
                int pp  = p0 + col;
                int q34 = pp/34;
                int yy  = q34 - 1;
                int xx  = pp - q34*34 - 1;
                if ((unsigned)yy < 32u && (unsigned)xx < 32u){
                    float v = acc[mi][n8][e];
                    if (Pb){
                        int yc = (yy==0)?0:((yy==31)?2:1);
                        int xc = (xx==0)?0:((xx==31)?2:1);
                        v += Pb[(s*128+co)*9 + yc*3+xc];
                    }
                    dst[((size_t)img*128+co)*1024 + (yy<<5)+xx] = v;
                }
            }
        }
    }
}

// ---- FFMA 3x3 conv: modes 0 single, 3 concat(inputs64, s1+s2) ----
__global__ __launch_bounds__(256,2)
void conv3x3_k(const float* __restrict__ s0, const float* __restrict__ s1,
               const float* __restrict__ s2, const float* __restrict__ wT,
               float* __restrict__ dst, int cin, int mode)
{
    __shared__ float sIn[8*6*34];
    __shared__ float sW [8*9*128];
    const int t   = threadIdx.x;
    const int img = blockIdx.x >> 3;
    const int y0  = (blockIdx.x & 7) << 2;
    const int x   = t & 31;
    const int cg  = t >> 5;
    float acc[64];
    #pragma unroll
    for (int i=0;i<64;i++) acc[i]=0.f;

    const int nchunk = cin >> 3;
    for (int cc=0; cc<nchunk; cc++){
        const float* wp = wT + cc*9216;
        for (int e=t; e<9216; e+=256) sW[e] = wp[e];
        for (int e=t; e<1632; e+=256){
            int ci = e/204; int rem = e - ci*204;
            int r  = rem/34; int xx = rem - r*34;
            int y  = y0 - 1 + r; int xg = xx - 1;
            float val = 0.f;
            if ((unsigned)y < 32u && (unsigned)xg < 32u){
                int c = (cc<<3) + ci;
                int p = (y<<5) + xg;
                if (mode == 0){
                    val = s0[((size_t)img*cin + c)*1024 + p];
                } else {
                    val = (c < 64) ? s0[((size_t)img*64 + c)*1024 + p]
                                   : s1[((size_t)img*128 + (c-64))*1024 + p]
                                   + s2[((size_t)img*128 + (c-64))*1024 + p];
                }
            }
            sIn[(ci*6 + r)*34 + xx] = val;
        }
        __syncthreads();
        #pragma unroll 1
        for (int ci=0; ci<8; ci++){
            float inr[18];
            #pragma unroll
            for (int r=0;r<6;r++){
                #pragma unroll
                for (int d=0;d<3;d++) inr[r*3+d] = sIn[(ci*6+r)*34 + x + d];
            }
            #pragma unroll
            for (int tap=0; tap<9; tap++){
                const int dy = tap/3, dx = tap - dy*3;
                const float4* wq = (const float4*)&sW[(ci*9+tap)*128 + (cg<<4)];
                float4 w0 = wq[0], w1 = wq[1], w2 = wq[2], w3 = wq[3];
                #pragma unroll
                for (int y=0;y<4;y++){
                    float iv = inr[(y+dy)*3 + dx];
                    float* a = &acc[y*16];
                    a[0]+=iv*w0.x; a[1]+=iv*w0.y; a[2]+=iv*w0.z; a[3]+=iv*w0.w;
                    a[4]+=iv*w1.x; a[5]+=iv*w1.y; a[6]+=iv*w1.z; a[7]+=iv*w1.w;
                    a[8]+=iv*w2.x; a[9]+=iv*w2.y; a[10]+=iv*w2.z; a[11]+=iv*w2.w;
                    a[12]+=iv*w3.x; a[13]+=iv*w3.y; a[14]+=iv*w3.z; a[15]+=iv*w3.w;
                }
            }
        }
        __syncthreads();
    }
    #pragma unroll
    for (int j=0;j<16;j++){
        int co = (cg<<4) + j;
        #pragma unroll
        for (int y=0;y<4;y++)
            dst[((size_t)img*128 + co)*1024 + ((y0+y)<<5) + x] = acc[y*16+j];
    }
}

// ---- 1x1 conv (vpost) ----
__global__ __launch_bounds__(256,2)
void conv1x1_k(const float* __restrict__ src, const float* __restrict__ wT,
               float* __restrict__ dst)
{
    __shared__ float sIn[8*128];
    __shared__ float sW [8*128];
    const int t   = threadIdx.x;
    const int img = blockIdx.x >> 3;
    const int p0  = (blockIdx.x & 7) << 7;
    const int xl  = t & 31;
    const int cg  = t >> 5;
    float acc[64];
    #pragma unroll
    for (int i=0;i<64;i++) acc[i]=0.f;

    for (int cc=0; cc<16; cc++){
        for (int e=t; e<1024; e+=256){
            int ci = e>>7, i = e&127;
            sIn[e] = src[((size_t)img*128 + (cc<<3)+ci)*1024 + p0 + i];
            sW [e] = wT[(cc<<10) + e];
        }
        __syncthreads();
        #pragma unroll
        for (int ci=0;ci<8;ci++){
            float inr[4];
            #pragma unroll
            for (int y=0;y<4;y++) inr[y] = sIn[ci*128 + (y<<5) + xl];
            const float4* wq = (const float4*)&sW[ci*128 + (cg<<4)];
            float4 w0=wq[0], w1=wq[1], w2=wq[2], w3=wq[3];
            #pragma unroll
            for (int y=0;y<4;y++){
                float iv = inr[y];
                float* a = &acc[y*16];
                a[0]+=iv*w0.x; a[1]+=iv*w0.y; a[2]+=iv*w0.z; a[3]+=iv*w0.w;
                a[4]+=iv*w1.x; a[5]+=iv*w1.y; a[6]+=iv*w1.z; a[7]+=iv*w1.w;
                a[8]+=iv*w2.x; a[9]+=iv*w2.y; a[10]+=iv*w2.z; a[11]+=iv*w2.w;
                a[12]+=iv*w3.x; a[13]+=iv*w3.y; a[14]+=iv*w3.z; a[15]+=iv*w3.w;
            }
        }
        __syncthreads();
    }
    #pragma unroll
    for (int j=0;j<16;j++){
        int co = (cg<<4)+j;
        #pragma unroll
        for (int y=0;y<4;y++)
            dst[((size_t)img*128+co)*1024 + p0 + (y<<5) + xl] = acc[y*16+j];
    }
}

// ---- GroupNorm ----
__global__ void gn_reduce_k(const float* __restrict__ x, float* __restrict__ stats)
{
    const int img = blockIdx.x;
    const float4* p = (const float4*)(x + (size_t)img*CHW);
    float s=0.f, s2=0.f;
    for (int i=threadIdx.x; i<32768; i+=blockDim.x){
        float4 v = p[i];
        s  += v.x+v.y+v.z+v.w;
        s2 += v.x*v.x+v.y*v.y+v.z*v.z+v.w*v.w;
    }
    #pragma unroll
    for (int o=16;o;o>>=1){
        s  += __shfl_down_sync(0xffffffffu, s , o);
        s2 += __shfl_down_sync(0xffffffffu, s2, o);
    }
    __shared__ float sa[8], sb[8];
    if ((threadIdx.x&31)==0){ sa[threadIdx.x>>5]=s; sb[threadIdx.x>>5]=s2; }
    __syncthreads();
    if (threadIdx.x==0){
        float S=0.f, S2=0.f;
        #pragma unroll
        for (int i=0;i<8;i++){ S+=sa[i]; S2+=sb[i]; }
        float mu  = S*(1.f/131072.f);
        float var = S2*(1.f/131072.f) - mu*mu;
        stats[img*2]   = mu;
        stats[img*2+1] = rsqrtf(var + 1e-5f);
    }
}

__global__ void gn_apply_k(float* __restrict__ x, const float* __restrict__ stats,
                           const float* __restrict__ gw, const float* __restrict__ gb,
                           int nimg, int act)
{
    int n4 = nimg*32768;
    for (int i = blockIdx.x*blockDim.x + threadIdx.x; i < n4; i += gridDim.x*blockDim.x){
        int base = i<<2;
        int img = base>>17; int c = (base>>10)&127;
        float mu = stats[2*img], rs = stats[2*img+1];
        float sc = rs*gw[c];
        float sh = gb[c] - mu*sc;
        float4 v = ((float4*)x)[i];
        v.x = v.x*sc+sh; v.y = v.y*sc+sh; v.z = v.z*sc+sh; v.w = v.w*sc+sh;
        if (act){
            v.x *= sigmf(v.x); v.y *= sigmf(v.y); v.z *= sigmf(v.z); v.w *= sigmf(v.w);
        }
        ((float4*)x)[i] = v;
    }
}

// ---- pooling / spatial filter ----
__global__ void pool_k(const float* __restrict__ x, float* __restrict__ pool, int nimg)
{
    int i = blockIdx.x*blockDim.x + threadIdx.x;
    if (i >= nimg*HWN) return;
    int img = i>>10, p = i&1023;
    const float* base = x + (size_t)img*CHW + p;
    float s = 0.f, m = -3.402823466e38f;
    #pragma unroll 4
    for (int c=0;c<128;c++){
        float v = base[(size_t)c<<10];
        s += v; m = fmaxf(m, v);
    }
    pool[img*2048 + p]        = s*(1.f/128.f);
    pool[img*2048 + 1024 + p] = m;
}

__global__ void saconv_k(const float* __restrict__ pool, const float* __restrict__ w,
                         const float* __restrict__ b, float* __restrict__ sa, int nimg)
{
    int i = blockIdx.x*blockDim.x + threadIdx.x;
    if (i >= nimg*HWN) return;
    int img = i>>10, p = i&1023, y = p>>5, x = p&31;
    float acc = b[0];
    #pragma unroll
    for (int c2=0;c2<2;c2++)
    #pragma unroll
    for (int dy=-1;dy<=1;dy++)
    #pragma unroll
    for (int dx=-1;dx<=1;dx++){
        int yy=y+dy, xx=x+dx;
        if ((unsigned)yy<32u && (unsigned)xx<32u)
            acc += pool[img*2048 + c2*1024 + (yy<<5)+xx] * w[c2*9 + (dy+1)*3 + (dx+1)];
    }
    sa[i] = sigmf(acc);
}

// ---- attention pieces ----
__global__ void qfg_k()
{
    int wid  = (blockIdx.x*blockDim.x + threadIdx.x) >> 5;
    int lane = threadIdx.x & 31;
    if (wid >= SN*BN*CH) return;
    int c = wid & 127, b = (wid>>7)&15, s = wid>>11;
    const float* qp = g_q   + ((size_t)b*128 + c)*1024;
    const float* kp = g_ksa + (size_t)(s*16+b)*1024;
    float acc = 0.f;
    for (int p=lane; p<1024; p+=32) acc += qp[p]*kp[p];
    #pragma unroll
    for (int o=16;o;o>>=1) acc += __shfl_down_sync(0xffffffffu, acc, o);
    if (!lane) g_qfg[wid] = acc*(1.f/1024.f);
}

__global__ void sprob_k()
{
    int img = blockIdx.x;
    __shared__ float fq[128];
    int t = threadIdx.x;
    if (t < 128) fq[t] = g_qfg[img*128 + t];
    __syncthreads();
    for (int p=t; p<1024; p+=256){
        const float* kp = g_k + (size_t)img*CHW + p;
        float acc = 0.f;
        #pragma unroll 4
        for (int c=0;c<128;c++) acc += fq[c]*kp[(size_t)c<<10];
        g_sprob[img*1024 + p] = sigmf(acc);
    }
}

__global__ void tlogit_k()
{
    int img = blockIdx.x, b = img & 15;
    float acc = 0.f;
    for (int i=threadIdx.x; i<CHW; i+=256){
        int p = i & 1023;
        acc += g_q[(size_t)b*CHW + i]*g_qsa[b*1024+p]
             * g_k[(size_t)img*CHW + i]*g_ksa[img*1024+p];
    }
    #pragma unroll
    for (int o=16;o;o>>=1) acc += __shfl_down_sync(0xffffffffu, acc, o);
    __shared__ float sh[8];
    if ((threadIdx.x&31)==0) sh[threadIdx.x>>5] = acc;
    __syncthreads();
    if (threadIdx.x==0){
        float S=0.f;
        #pragma unroll
        for (int i=0;i<8;i++) S += sh[i];
        g_tl[img] = S * rsqrtf(131072.f);
    }
}

__global__ void tprob_k()
{
    int b = threadIdx.x;
    if (b >= 16) return;
    float m = -3.402823466e38f;
    #pragma unroll
    for (int s=0;s<8;s++) m = fmaxf(m, g_tl[s*16+b]);
    float e[8]; float sum = 0.f;
    #pragma unroll
    for (int s=0;s<8;s++){ e[s] = __expf(g_tl[s*16+b] - m); sum += e[s]; }
    float inv = 1.f/sum;
    #pragma unroll
    for (int s=0;s<8;s++) g_tp[s*16+b] = e[s]*inv;
}

__global__ void av_k()
{
    int i = blockIdx.x*blockDim.x + threadIdx.x;
    if (i >= BN*CHW/4) return;
    int base = i<<2;
    int b = base>>17; int c = (base>>10)&127; int p = base&1023;
    float4 acc = make_float4(0.f,0.f,0.f,0.f);
    #pragma unroll
    for (int s=0;s<8;s++){
        int img = s*16 + b;
        float tw = g_tp[img];
        float4 sp = *(const float4*)&g_sprob[img*1024 + p];
        float4 vv = *(const float4*)&g_v[((size_t)img*128 + c)*1024 + p];
        acc.x += tw*sp.x*vv.x; acc.y += tw*sp.y*vv.y;
        acc.z += tw*sp.z*vv.z; acc.w += tw*sp.w*vv.w;
    }
    *(float4*)&g_av[base] = acc;
}

__global__ void newout_k(const unsigned char* __restrict__ mask, float* __restrict__ out)
{
    int i = blockIdx.x*blockDim.x + threadIdx.x;
    if (i >= BN*CHW/4) return;
    int base = i<<2;
    int b = base>>17;
    float4 v = mask_at(mask, b) ? *(const float4*)&g_att[base]
                                : make_float4(0.f,0.f,0.f,0.f);
    *(float4*)&out[(size_t)2*BN*CHW + base] = v;
}

__global__ void semean_k()
{
    int b = blockIdx.x;
    int w = threadIdx.x>>5, lane = threadIdx.x&31;
    for (int c=w; c<128; c+=8){
        const float* p = g_o + ((size_t)b*128 + c)*1024;
        float s = 0.f;
        for (int i=lane; i<1024; i+=32) s += p[i];
        #pragma unroll
        for (int o=16;o;o>>=1) s += __shfl_down_sync(0xffffffffu, s, o);
        if (!lane) g_se1[b*128+c] = s*(1.f/1024.f);
    }
}

__global__ void sefc1_k(const float* __restrict__ w1, const float* __restrict__ b1)
{
    int t = threadIdx.x;
    int b = t>>5, j = t&31;
    float acc = b1[j];
    #pragma unroll 4
    for (int c=0;c<128;c++) acc += g_se1[b*128+c]*w1[j*128+c];
    g_se2[b*32+j] = fmaxf(acc, 0.f);
}

__global__ void sefc2_k(const float* __restrict__ w2, const float* __restrict__ b2)
{
    int i = blockIdx.x*blockDim.x + threadIdx.x;
    if (i >= BN*CH) return;
    int b = i>>7, c = i&127;
    float acc = b2[c];
    #pragma unroll
    for (int j=0;j<32;j++) acc += g_se2[b*32+j]*w2[c*32+j];
    g_se3[i] = sigmf(acc);
}

__global__ void final_k(float* __restrict__ out)
{
    int i = blockIdx.x*blockDim.x + threadIdx.x;
    if (i >= BN*CHW/4) return;
    int base = i<<2;
    int b = base>>17; int c = (base>>10)&127;
    float g = 1.f + g_se3[b*128+c];
    float4 o4 = *(const float4*)&g_o[base];
    o4.x*=g; o4.y*=g; o4.z*=g; o4.w*=g;
    *(float4*)&out[base] = o4;
    *(float4*)&out[(size_t)BN*CHW + base] = *(const float4*)&g_ht[base];
}

// ---- host launcher ----
extern "C" void kernel_launch(void* const* d_in, const int* in_sizes, int n_in,
                              void* d_out, int out_size)
{
    (void)in_sizes; (void)n_in; (void)out_size;
    const float* inputs  = (const float*)d_in[0];
    const float* hidden  = (const float*)d_in[1];
    const float* outq    = (const float*)d_in[2];
    const unsigned char* mask = (const unsigned char*)d_in[3];
    const float* enc_w   = (const float*)d_in[4];
    const float* enc_gw  = (const float*)d_in[5];
    const float* enc_gb  = (const float*)d_in[6];
    const float* qpre_w  = (const float*)d_in[7];
    const float* qpre_gw = (const float*)d_in[8];
    const float* qpre_gb = (const float*)d_in[9];
    const float* kpre_w  = (const float*)d_in[10];
    const float* kpre_gw = (const float*)d_in[11];
    const float* kpre_gb = (const float*)d_in[12];
    const float* vpre_w  = (const float*)d_in[13];
    const float* vpre_gw = (const float*)d_in[14];
    const float* vpre_gb = (const float*)d_in[15];
    const float* qsa_w   = (const float*)d_in[16];
    const float* qsa_b   = (const float*)d_in[17];
    const float* ksa_w   = (const float*)d_in[18];
    const float* ksa_b   = (const float*)d_in[19];
    const float* vpost_w = (const float*)d_in[20];
    const float* vpost_gw= (const float*)d_in[21];
    const float* vpost_gb= (const float*)d_in[22];
    const float* pos_emb = (const float*)d_in[23];
    const float* outt_w  = (const float*)d_in[24];
    const float* outt_gw = (const float*)d_in[25];
    const float* outt_gb = (const float*)d_in[26];
    const float* se_w1   = (const float*)d_in[27];
    const float* se_b1   = (const float*)d_in[28];
    const float* se_w2   = (const float*)d_in[29];
    const float* se_b2   = (const float*)d_in[30];
    float* out = (float*)d_out;

    float *ht,*q,*k,*v,*av,*att,*o,*stats,*pool,*qsa,*ksa,*peN,*wT,*Pb;
    __half *wrep;
    cudaGetSymbolAddress((void**)&ht,   g_ht);
    cudaGetSymbolAddress((void**)&q,    g_q);
    cudaGetSymbolAddress((void**)&k,    g_k);
    cudaGetSymbolAddress((void**)&v,    g_v);
    cudaGetSymbolAddress((void**)&av,   g_av);
    cudaGetSymbolAddress((void**)&att,  g_att);
    cudaGetSymbolAddress((void**)&o,    g_o);
    cudaGetSymbolAddress((void**)&stats,g_stats);
    cudaGetSymbolAddress((void**)&pool, g_pool);
    cudaGetSymbolAddress((void**)&qsa,  g_qsa);
    cudaGetSymbolAddress((void**)&ksa,  g_ksa);
    cudaGetSymbolAddress((void**)&peN,  g_peN);
    cudaGetSymbolAddress((void**)&wT,   g_wT);
    cudaGetSymbolAddress((void**)&Pb,   g_Pb);
    cudaGetSymbolAddress((void**)&wrep, g_wrep);

    const int OFF_ENC   = 0;
    const int OFF_QPRE  = 73728;
    const int OFF_OUTT  = 221184;
    const int OFF_VPOST = 442368;

    cudaFuncSetAttribute(mmaconv_k, cudaFuncAttributeMaxDynamicSharedMemorySize, DSMEM_TOTAL);

    // launch order arranged so the profiled launch (#4) is mmaconv_k
    zero_nhwc_k<<<2048,256>>>();                               // 1
    fill_nhwc_k<<<4096,256>>>(hidden, outq);                   // 2
    wrep_k<<<1152,256>>>(kpre_w, wrep);                        // 3
    mmaconv_k<<<1280,256,DSMEM_TOTAL>>>(wrep, nullptr, k);     // 4  <- profiled
    wrep_k<<<1152,256>>>(vpre_w, wrep + 589824);               // 5
    pe_norm_k<<<8,256>>>(pos_emb, peN);                        // 6
    pbconv_k<<<8,128>>>(vpre_w);                               // 7
    mmaconv_k<<<1280,256,DSMEM_TOTAL>>>(wrep + 589824, Pb, v); // 8

    transw_k<<<128,256>>>(enc_w,  wT+OFF_ENC,  64, 9);
    transw_k<<<256,256>>>(qpre_w, wT+OFF_QPRE, 128, 9);
    transw_k<<<384,256>>>(outt_w, wT+OFF_OUTT, 192, 9);
    transw_k<<<64,256>>>(vpost_w, wT+OFF_VPOST, 128, 1);

    // ht = silu(gn(conv(inputs, enc_w)))
    conv3x3_k<<<BN*8,256>>>(inputs, nullptr, nullptr, wT+OFF_ENC, ht, 64, 0);
    gn_reduce_k<<<BN,256>>>(ht, stats);
    gn_apply_k<<<2048,256>>>(ht, stats, enc_gw, enc_gb, BN, 1);

    // q = gn(conv(ht, qpre_w))
    conv3x3_k<<<BN*8,256>>>(ht, nullptr, nullptr, wT+OFF_QPRE, q, 128, 0);
    gn_reduce_k<<<BN,256>>>(q, stats);
    gn_apply_k<<<2048,256>>>(q, stats, qpre_gw, qpre_gb, BN, 0);

    // gn for k and v
    gn_reduce_k<<<SBN,256>>>(k, stats);
    gn_apply_k<<<4096,256>>>(k, stats, kpre_gw, kpre_gb, SBN, 0);
    gn_reduce_k<<<SBN,256>>>(v, stats);
    gn_apply_k<<<4096,256>>>(v, stats, vpre_gw, vpre_gb, SBN, 0);

    // spatial filters
    pool_k<<<(BN*HWN+255)/256,256>>>(q, pool, BN);
    saconv_k<<<(BN*HWN+255)/256,256>>>(pool, qsa_w, qsa_b, qsa, BN);
    pool_k<<<(SBN*HWN+255)/256,256>>>(k, pool, SBN);
    saconv_k<<<(SBN*HWN+255)/256,256>>>(pool, ksa_w, ksa_b, ksa, SBN);

    // attention
    qfg_k<<<2048,256>>>();
    sprob_k<<<SBN,256>>>();
    tlogit_k<<<SBN,256>>>();
    tprob_k<<<1,32>>>();
    av_k<<<2048,256>>>();

    // att = silu(gn(conv1x1(av)))
    conv1x1_k<<<BN*8,256>>>(av, wT+OFF_VPOST, att);
    gn_reduce_k<<<BN,256>>>(att, stats);
    gn_apply_k<<<2048,256>>>(att, stats, vpost_gw, vpost_gb, BN, 1);

    newout_k<<<2048,256>>>(mask, out);

    // o = silu(gn(conv(concat(inputs, att+ht))))
    conv3x3_k<<<BN*8,256>>>(inputs, att, ht, wT+OFF_OUTT, o, 192, 3);
    gn_reduce_k<<<BN,256>>>(o, stats);
    gn_apply_k<<<2048,256>>>(o, stats, outt_gw, outt_gb, BN, 1);

    semean_k<<<BN,256>>>();
    sefc1_k<<<1,512>>>(se_w1, se_b1);
    sefc2_k<<<8,256>>>(se_w2, se_b2);
    final_k<<<2048,256>>>(out);
}

// round 9
// speedup vs baseline: 3.0775x; 1.1961x over previous
#include <cuda_runtime.h>
#include <cuda_fp16.h>
#include <cstdint>

#define BN   16
#define CH   128
#define HWN  1024
#define SN   8
#define SBN  128
#define CHW  131072

#define GUARD   64
#define RPI     1344
#define TOTROWS  (GUARD + 128*RPI + 256)   // big buffer (kv, 128 imgs)
#define TOTROWS_S (GUARD + 16*RPI + 256)   // small buffer (16 imgs)

// mmaconv smem (bytes): X window 200 rows x 256B, then one A buffer 32KB
#define AB_OFF 51200
#define DSMEM_TOTAL 83968

__device__ float g_ht [BN*CHW];
__device__ float g_q  [BN*CHW];
__device__ float g_k  [SBN*CHW];
__device__ float g_v  [SBN*CHW];
__device__ float g_av [BN*CHW];
__device__ float g_att[BN*CHW];
__device__ float g_o  [BN*CHW];
__device__ float g_stats[2*SBN];
__device__ float g_pool[SBN*2*HWN];
__device__ float g_qsa[BN*HWN];
__device__ float g_ksa[SBN*HWN];
__device__ float g_qfg[SN*BN*CH];
__device__ float g_sprob[SBN*HWN];
__device__ float g_tl[SN*BN];
__device__ float g_tp[SN*BN];
__device__ float g_peN[SN*2*CH];
__device__ float g_se1[BN*CH];
__device__ float g_se2[BN*32];
__device__ float g_se3[BN*CH];
__device__ float g_Pb[SN*CH*9];
__device__ float g_wT[524288];
__device__ __half g_nhwc [(size_t)TOTROWS*256];
__device__ __half g_nhwcS[(size_t)TOTROWS_S*256];
// wrep: kpre(589824) | vpre(589824) | qpre(294912) | outt(589824)
__device__ __half g_wrep[2064384];

__device__ __forceinline__ float sigmf(float x){ return 1.f/(1.f + __expf(-x)); }
__device__ __forceinline__ bool mask_at(const unsigned char* m, int b){
    if (m[1] != 0) return m[b] != 0;
    const unsigned int* w = (const unsigned int*)m;
    return w[b] != 0;
}

__device__ __forceinline__ uint32_t smem_u32(const void* p){
    uint32_t a;
    asm("{ .reg .u64 t; cvta.to.shared.u64 t, %1; cvt.u32.u64 %0, t; }" : "=r"(a) : "l"(p));
    return a;
}
__device__ __forceinline__ void mma16816(float* d, uint32_t a0, uint32_t a1, uint32_t a2,
                                         uint32_t a3, uint32_t b0, uint32_t b1){
    asm volatile("mma.sync.aligned.m16n8k16.row.col.f32.f16.f16.f32 "
        "{%0,%1,%2,%3}, {%4,%5,%6,%7}, {%8,%9}, {%0,%1,%2,%3};"
        : "+f"(d[0]),"+f"(d[1]),"+f"(d[2]),"+f"(d[3])
        : "r"(a0),"r"(a1),"r"(a2),"r"(a3),"r"(b0),"r"(b1));
}
__device__ __forceinline__ void ldsm4(uint32_t& r0,uint32_t& r1,uint32_t& r2,uint32_t& r3,
                                      uint32_t addr){
    asm volatile("ldmatrix.sync.aligned.m8n8.x4.shared.b16 {%0,%1,%2,%3}, [%4];"
        : "=r"(r0),"=r"(r1),"=r"(r2),"=r"(r3) : "r"(addr));
}
__device__ __forceinline__ void cpa16(uint32_t d, const void* s){
    asm volatile("cp.async.cg.shared.global [%0], [%1], 16;" :: "r"(d), "l"(s));
}
__device__ __forceinline__ void cp_commit(){ asm volatile("cp.async.commit_group;" ::: "memory"); }
__device__ __forceinline__ void cp_wait0(){ asm volatile("cp.async.wait_group 0;" ::: "memory"); }

// ---- weight transpose for FFMA convs (enc, vpost) ----
__global__ void transw_k(const float* __restrict__ w, float* __restrict__ wT,
                         int cin, int ktaps)
{
    int n = cin*ktaps*128;
    for (int i = blockIdx.x*blockDim.x + threadIdx.x; i < n; i += gridDim.x*blockDim.x){
        int co = i & 127;
        int r  = i >> 7;
        int tap = r % ktaps;
        int c   = r / ktaps;
        wT[i] = w[(co*cin + c)*ktaps + tap];
    }
}

__global__ void pe_norm_k(const float* __restrict__ pe, float* __restrict__ peN)
{
    int s = blockIdx.x, t = threadIdx.x;
    float v = pe[s*256 + t];
    float q = v*v;
    #pragma unroll
    for (int o=16;o;o>>=1) q += __shfl_down_sync(0xffffffffu, q, o);
    __shared__ float a[8];
    __shared__ float fac;
    if ((t&31)==0) a[t>>5] = q;
    __syncthreads();
    if (t==0){
        float S=0.f;
        #pragma unroll
        for (int i=0;i<8;i++) S += a[i];
        float n = sqrtf(S);
        fac = fminf(1.f, 1.f/fmaxf(n, 1e-7f));
    }
    __syncthreads();
    peN[s*256 + t] = v*fac;
}

// ---- NHWC fp16 zero ----
__global__ void zero_half_k(__half* buf, size_t n16)
{
    uint4 z = make_uint4(0,0,0,0);
    uint4* p = (uint4*)buf;
    for (size_t i = (size_t)blockIdx.x*blockDim.x + threadIdx.x; i < n16;
         i += (size_t)gridDim.x*blockDim.x) p[i] = z;
}

// big buffer fill: kv concat (128 imgs, 256 ch)
__global__ void fill_nhwc_k(const float* __restrict__ hid, const float* __restrict__ oq)
{
    __shared__ float s[32][257];
    int t = threadIdx.x;
    int img = blockIdx.x>>5, y = blockIdx.x&31;
    int xg = t&31, cg = t>>5;
    size_t rb = GUARD + (size_t)img*RPI + (size_t)(y+1)*34;
    #pragma unroll
    for (int cc=0; cc<32; cc++){
        int c = cc*8 + cg;
        const float* src = (c<128) ? hid + ((size_t)img*128 + c)*1024
                                   : oq  + ((size_t)img*128 + (c-128))*1024;
        s[xg][c] = src[y*32 + xg];
    }
    __syncthreads();
    #pragma unroll
    for (int xs=0; xs<32; xs++)
        g_nhwc[(rb + xs + 1)*256 + t] = __float2half(s[xs][t]);
}

// small buffer fill: ht (16 imgs, ch0-127; upper half stays zero)
__global__ void fill16_k(const float* __restrict__ src)
{
    __shared__ float s[32][129];
    int t = threadIdx.x;
    int img = blockIdx.x>>5, y = blockIdx.x&31;
    int xg = t&31, cg = t>>5;
    size_t rb = GUARD + (size_t)img*RPI + (size_t)(y+1)*34;
    #pragma unroll
    for (int cc=0; cc<16; cc++){
        int c = cc*8 + cg;
        s[xg][c] = src[((size_t)img*128 + c)*1024 + y*32 + xg];
    }
    __syncthreads();
    if (t < 128){
        #pragma unroll
        for (int xs=0; xs<32; xs++)
            g_nhwcS[(rb + xs + 1)*256 + t] = __float2half(s[xs][t]);
    }
}

// small buffer fill: concat(inputs[64], att+ht[128]) -> ch0-191 (192-255 stay zero)
__global__ void xcat_fill_k(const float* __restrict__ inputs)
{
    __shared__ float s[32][193];
    int t = threadIdx.x;
    int img = blockIdx.x>>5, y = blockIdx.x&31;
    int xg = t&31, cg = t>>5;
    size_t rb = GUARD + (size_t)img*RPI + (size_t)(y+1)*34;
    #pragma unroll
    for (int cc=0; cc<24; cc++){
        int c = cc*8 + cg;
        float val;
        if (c < 64) val = inputs[((size_t)img*64 + c)*1024 + y*32 + xg];
        else {
            int c2 = c - 64;
            val = g_att[((size_t)img*128 + c2)*1024 + y*32 + xg]
                + g_ht [((size_t)img*128 + c2)*1024 + y*32 + xg];
        }
        s[xg][c] = val;
    }
    __syncthreads();
    if (t < 192){
        #pragma unroll
        for (int xs=0; xs<32; xs++)
            g_nhwcS[(rb + xs + 1)*256 + t] = __float2half(s[xs][t]);
    }
}

// ---- weight repack: [sp][tap*nkc+kc][co][128k] fp16 hi/lo; zero-pad cin ----
__global__ void wrep_k(const float* __restrict__ w, __half* __restrict__ dst,
                       int cin, int nkc)
{
    int n = nkc*147456;
    int i = blockIdx.x*blockDim.x + threadIdx.x;
    if (i >= n) return;
    int kl = i & 127;
    int r = i >> 7;
    int co = r & 127; r >>= 7;
    int kc = r % nkc;
    int tap = r / nkc;
    int cin_idx = kc*128 + kl;
    float val = (cin_idx < cin) ? w[((size_t)co*cin + cin_idx)*9 + tap] : 0.f;
    __half h = __float2half(val);
    int o = ((tap*nkc+kc)*128 + co)*128 + kl;
    dst[o] = h;
    dst[n + o] = __float2half(val - __half2float(h));
}

// ---- pe correction with border masks: Pb[s][co][yc*3+xc] ----
__global__ void pbconv_k(const float* __restrict__ w)
{
    int s = blockIdx.x, co = threadIdx.x;
    float P[9];
    #pragma unroll
    for (int tap=0;tap<9;tap++){
        float acc = 0.f;
        for (int c=0;c<256;c++)
            acc += g_peN[s*256 + c] * w[((size_t)co*256 + c)*9 + tap];
        P[tap] = acc;
    }
    #pragma unroll
    for (int yc=0;yc<3;yc++){
        #pragma unroll
        for (int xc=0;xc<3;xc++){
            float tot = 0.f;
            #pragma unroll
            for (int dy=0;dy<3;dy++){
                if ((yc==0 && dy==0) || (yc==2 && dy==2)) continue;
                float rs = P[dy*3+1];
                if (xc!=0) rs += P[dy*3+0];
                if (xc!=2) rs += P[dy*3+2];
                tot += rs;
            }
            g_Pb[(s*128+co)*9 + yc*3+xc] = tot;
        }
    }
}

// ---- per-(tap,sp) MMA: 64co x 32px per warp ----
__device__ __forceinline__ void conv_tap_sp(uint32_t xb, uint32_t ab, int tap,
                                            int lane, int cob, int pxb,
                                            float acc[4][4][4])
{
    const int lr  = lane & 7;
    const int hsA = lane >> 4;
    const int hsB = (lane >> 3) & 1;
    const int dy = tap/3, dx = tap - dy*3;
    const int dlt = (dy-1)*34 + (dx-1);

    uint32_t rowA[4], rsA[4];
    #pragma unroll
    for (int mi=0;mi<4;mi++){
        int r = cob + mi*16 + lr + ((lane>>3)&1)*8;
        rowA[mi] = (uint32_t)r*256u; rsA[mi] = (uint32_t)(r&7);
    }
    uint32_t rowB[2], rsB[2];
    #pragma unroll
    for (int nn=0;nn<2;nn++){
        int r = 36 + dlt + pxb + nn*16 + lr + (lane>>4)*8;
        rowB[nn] = (uint32_t)r*256u; rsB[nn] = (uint32_t)(r&7);
    }
    #pragma unroll
    for (int k8=0;k8<8;k8++){
        uint32_t a[4][4];
        #pragma unroll
        for (int mi=0;mi<4;mi++){
            uint32_t sgi = (uint32_t)(k8*2 + hsA);
            uint32_t ad = ab + rowA[mi] + ((sgi ^ rsA[mi])<<4);
            ldsm4(a[mi][0],a[mi][1],a[mi][2],a[mi][3], ad);
        }
        #pragma unroll
        for (int nn=0;nn<2;nn++){
            uint32_t sgi = (uint32_t)(k8*2 + hsB);
            uint32_t ad = xb + rowB[nn] + ((sgi ^ rsB[nn])<<4);
            uint32_t b0,b1,b2,b3;
            ldsm4(b0,b1,b2,b3, ad);
            #pragma unroll
            for (int mi=0;mi<4;mi++){
                mma16816(acc[mi][2*nn],   a[mi][0],a[mi][1],a[mi][2],a[mi][3], b0,b1);
                mma16816(acc[mi][2*nn+1], a[mi][0],a[mi][1],a[mi][2],a[mi][3], b2,b3);
            }
        }
    }
}

// ---- mma.sync fp16 implicit conv: D[128co,128px], 2 CTAs/SM ----
// nkc = number of 128-ch K halves (1: cin<=128, 2: cin<=256)
__global__ __launch_bounds__(256,2)
void mmaconv_k(const __half* __restrict__ wrep,
               const __half* __restrict__ nhwc,
               const float* __restrict__ Pb,
               float* __restrict__ dst, int nkc)
{
    extern __shared__ char dsm[];
    const uint32_t sb = smem_u32(dsm);
    const uint32_t XB = sb;
    const uint32_t AB = sb + AB_OFF;
    const int t = threadIdx.x;
    const int wid = t>>5, lane = t&31;
    const int img = blockIdx.x/10;
    const int p0  = (blockIdx.x%10)*128;
    const int s   = img>>4;
    const int cob = (wid&1)*64;
    const int pxb = (wid>>1)*32;
    const int spstr = nkc*147456;

    float acc[4][4][4];
    #pragma unroll
    for (int mi=0;mi<4;mi++)
    #pragma unroll
    for (int ni=0;ni<4;ni++)
    #pragma unroll
    for (int e=0;e<4;e++) acc[mi][ni][e]=0.f;

    for (int kc=0; kc<nkc; kc++){
        // stage X window: 200 rows x 128k fp16 (one kc half)
        {
            const char* src = (const char*)nhwc
                + ((size_t)GUARD + (size_t)img*RPI + p0 - 36)*512 + kc*256;
            #pragma unroll
            for (int j=0;j<13;j++){
                int i = j*256 + t;
                if (i < 3200){
                    uint32_t r = (uint32_t)(i>>4), sg = (uint32_t)(i&15);
                    cpa16(XB + r*256 + ((sg^(r&7))<<4), src + (size_t)r*512 + sg*16);
                }
            }
            cp_commit();
        }
        for (int tap=0; tap<9; tap++){
            #pragma unroll
            for (int sp=0; sp<2; sp++){
                const char* asrc = (const char*)(wrep + (size_t)sp*spstr
                                                 + (size_t)(tap*nkc+kc)*16384);
                #pragma unroll
                for (int j=0;j<8;j++){
                    int i = j*256 + t;
                    uint32_t r = (uint32_t)(i>>4), sg = (uint32_t)(i&15);
                    cpa16(AB + r*256 + ((sg^(r&7))<<4), asrc + (size_t)i*16);
                }
                cp_commit(); cp_wait0(); __syncthreads();
                conv_tap_sp(XB, AB, tap, lane, cob, pxb, acc);
                __syncthreads();
            }
        }
    }

    // epilogue: register -> global stores with border mask + Pb correction
    const int g  = lane>>2;
    const int t2 = (lane&3)*2;
    #pragma unroll
    for (int mi=0;mi<4;mi++){
        #pragma unroll
        for (int n8=0;n8<4;n8++){
            #pragma unroll
            for (int e=0;e<4;e++){
                int co  = cob + mi*16 + g + ((e>>1)<<3);
                int col = pxb + n8*8 + t2 + (e&1);
                int pp  = p0 + col;
                int q34 = pp/34;
                int yy  = q34 - 1;
                int xx  = pp - q34*34 - 1;
                if ((unsigned)yy < 32u && (unsigned)xx < 32u){
                    float v = acc[mi][n8][e];
                    if (Pb){
                        int yc = (yy==0)?0:((yy==31)?2:1);
                        int xc = (xx==0)?0:((xx==31)?2:1);
                        v += Pb[(s*128+co)*9 + yc*3+xc];
                    }
                    dst[((size_t)img*128+co)*1024 + (yy<<5)+xx] = v;
                }
            }
        }
    }
}

// ---- FFMA 3x3 conv (enc only, mode 0) ----
__global__ __launch_bounds__(256,2)
void conv3x3_k(const float* __restrict__ s0, const float* __restrict__ wT,
               float* __restrict__ dst, int cin)
{
    __shared__ float sIn[8*6*34];
    __shared__ float sW [8*9*128];
    const int t   = threadIdx.x;
    const int img = blockIdx.x >> 3;
    const int y0  = (blockIdx.x & 7) << 2;
    const int x   = t & 31;
    const int cg  = t >> 5;
    float acc[64];
    #pragma unroll
    for (int i=0;i<64;i++) acc[i]=0.f;

    const int nchunk = cin >> 3;
    for (int cc=0; cc<nchunk; cc++){
        const float* wp = wT + cc*9216;
        for (int e=t; e<9216; e+=256) sW[e] = wp[e];
        for (int e=t; e<1632; e+=256){
            int ci = e/204; int rem = e - ci*204;
            int r  = rem/34; int xx = rem - r*34;
            int y  = y0 - 1 + r; int xg = xx - 1;
            float val = 0.f;
            if ((unsigned)y < 32u && (unsigned)xg < 32u)
                val = s0[((size_t)img*cin + (cc<<3)+ci)*1024 + (y<<5) + xg];
            sIn[(ci*6 + r)*34 + xx] = val;
        }
        __syncthreads();
        #pragma unroll 1
        for (int ci=0; ci<8; ci++){
            float inr[18];
            #pragma unroll
            for (int r=0;r<6;r++){
                #pragma unroll
                for (int d=0;d<3;d++) inr[r*3+d] = sIn[(ci*6+r)*34 + x + d];
            }
            #pragma unroll
            for (int tap=0; tap<9; tap++){
                const int dy = tap/3, dx = tap - dy*3;
                const float4* wq = (const float4*)&sW[(ci*9+tap)*128 + (cg<<4)];
                float4 w0 = wq[0], w1 = wq[1], w2 = wq[2], w3 = wq[3];
                #pragma unroll
                for (int y=0;y<4;y++){
                    float iv = inr[(y+dy)*3 + dx];
                    float* a = &acc[y*16];
                    a[0]+=iv*w0.x; a[1]+=iv*w0.y; a[2]+=iv*w0.z; a[3]+=iv*w0.w;
                    a[4]+=iv*w1.x; a[5]+=iv*w1.y; a[6]+=iv*w1.z; a[7]+=iv*w1.w;
                    a[8]+=iv*w2.x; a[9]+=iv*w2.y; a[10]+=iv*w2.z; a[11]+=iv*w2.w;
                    a[12]+=iv*w3.x; a[13]+=iv*w3.y; a[14]+=iv*w3.z; a[15]+=iv*w3.w;
                }
            }
        }
        __syncthreads();
    }
    #pragma unroll
    for (int j=0;j<16;j++){
        int co = (cg<<4) + j;
        #pragma unroll
        for (int y=0;y<4;y++)
            dst[((size_t)img*128 + co)*1024 + ((y0+y)<<5) + x] = acc[y*16+j];
    }
}

// ---- 1x1 conv (vpost) ----
__global__ __launch_bounds__(256,2)
void conv1x1_k(const float* __restrict__ src, const float* __restrict__ wT,
               float* __restrict__ dst)
{
    __shared__ float sIn[8*128];
    __shared__ float sW [8*128];
    const int t   = threadIdx.x;
    const int img = blockIdx.x >> 3;
    const int p0  = (blockIdx.x & 7) << 7;
    const int xl  = t & 31;
    const int cg  = t >> 5;
    float acc[64];
    #pragma unroll
    for (int i=0;i<64;i++) acc[i]=0.f;

    for (int cc=0; cc<16; cc++){
        for (int e=t; e<1024; e+=256){
            int ci = e>>7, i = e&127;
            sIn[e] = src[((size_t)img*128 + (cc<<3)+ci)*1024 + p0 + i];
            sW [e] = wT[(cc<<10) + e];
        }
        __syncthreads();
        #pragma unroll
        for (int ci=0;ci<8;ci++){
            float inr[4];
            #pragma unroll
            for (int y=0;y<4;y++) inr[y] = sIn[ci*128 + (y<<5) + xl];
            const float4* wq = (const float4*)&sW[ci*128 + (cg<<4)];
            float4 w0=wq[0], w1=wq[1], w2=wq[2], w3=wq[3];
            #pragma unroll
            for (int y=0;y<4;y++){
                float iv = inr[y];
                float* a = &acc[y*16];
                a[0]+=iv*w0.x; a[1]+=iv*w0.y; a[2]+=iv*w0.z; a[3]+=iv*w0.w;
                a[4]+=iv*w1.x; a[5]+=iv*w1.y; a[6]+=iv*w1.z; a[7]+=iv*w1.w;
                a[8]+=iv*w2.x; a[9]+=iv*w2.y; a[10]+=iv*w2.z; a[11]+=iv*w2.w;
                a[12]+=iv*w3.x; a[13]+=iv*w3.y; a[14]+=iv*w3.z; a[15]+=iv*w3.w;
            }
        }
        __syncthreads();
    }
    #pragma unroll
    for (int j=0;j<16;j++){
        int co = (cg<<4)+j;
        #pragma unroll
        for (int y=0;y<4;y++)
            dst[((size_t)img*128+co)*1024 + p0 + (y<<5) + xl] = acc[y*16+j];
    }
}

// ---- GroupNorm ----
__global__ void gn_reduce_k(const float* __restrict__ x, float* __restrict__ stats)
{
    const int img = blockIdx.x;
    const float4* p = (const float4*)(x + (size_t)img*CHW);
    float s=0.f, s2=0.f;
    for (int i=threadIdx.x; i<32768; i+=blockDim.x){
        float4 v = p[i];
        s  += v.x+v.y+v.z+v.w;
        s2 += v.x*v.x+v.y*v.y+v.z*v.z+v.w*v.w;
    }
    #pragma unroll
    for (int o=16;o;o>>=1){
        s  += __shfl_down_sync(0xffffffffu, s , o);
        s2 += __shfl_down_sync(0xffffffffu, s2, o);
    }
    __shared__ float sa[8], sb[8];
    if ((threadIdx.x&31)==0){ sa[threadIdx.x>>5]=s; sb[threadIdx.x>>5]=s2; }
    __syncthreads();
    if (threadIdx.x==0){
        float S=0.f, S2=0.f;
        #pragma unroll
        for (int i=0;i<8;i++){ S+=sa[i]; S2+=sb[i]; }
        float mu  = S*(1.f/131072.f);
        float var = S2*(1.f/131072.f) - mu*mu;
        stats[img*2]   = mu;
        stats[img*2+1] = rsqrtf(var + 1e-5f);
    }
}

__global__ void gn_apply_k(float* __restrict__ x, const float* __restrict__ stats,
                           const float* __restrict__ gw, const float* __restrict__ gb,
                           int nimg, int act)
{
    int n4 = nimg*32768;
    for (int i = blockIdx.x*blockDim.x + threadIdx.x; i < n4; i += gridDim.x*blockDim.x){
        int base = i<<2;
        int img = base>>17; int c = (base>>10)&127;
        float mu = stats[2*img], rs = stats[2*img+1];
        float sc = rs*gw[c];
        float sh = gb[c] - mu*sc;
        float4 v = ((float4*)x)[i];
        v.x = v.x*sc+sh; v.y = v.y*sc+sh; v.z = v.z*sc+sh; v.w = v.w*sc+sh;
        if (act){
            v.x *= sigmf(v.x); v.y *= sigmf(v.y); v.z *= sigmf(v.z); v.w *= sigmf(v.w);
        }
        ((float4*)x)[i] = v;
    }
}

// ---- pooling / spatial filter ----
__global__ void pool_k(const float* __restrict__ x, float* __restrict__ pool, int nimg)
{
    int i = blockIdx.x*blockDim.x + threadIdx.x;
    if (i >= nimg*HWN) return;
    int img = i>>10, p = i&1023;
    const float* base = x + (size_t)img*CHW + p;
    float s = 0.f, m = -3.402823466e38f;
    #pragma unroll 4
    for (int c=0;c<128;c++){
        float v = base[(size_t)c<<10];
        s += v; m = fmaxf(m, v);
    }
    pool[img*2048 + p]        = s*(1.f/128.f);
    pool[img*2048 + 1024 + p] = m;
}

__global__ void saconv_k(const float* __restrict__ pool, const float* __restrict__ w,
                         const float* __restrict__ b, float* __restrict__ sa, int nimg)
{
    int i = blockIdx.x*blockDim.x + threadIdx.x;
    if (i >= nimg*HWN) return;
    int img = i>>10, p = i&1023, y = p>>5, x = p&31;
    float acc = b[0];
    #pragma unroll
    for (int c2=0;c2<2;c2++)
    #pragma unroll
    for (int dy=-1;dy<=1;dy++)
    #pragma unroll
    for (int dx=-1;dx<=1;dx++){
        int yy=y+dy, xx=x+dx;
        if ((unsigned)yy<32u && (unsigned)xx<32u)
            acc += pool[img*2048 + c2*1024 + (yy<<5)+xx] * w[c2*9 + (dy+1)*3 + (dx+1)];
    }
    sa[i] = sigmf(acc);
}

// ---- attention pieces ----
__global__ void qfg_k()
{
    int wid  = (blockIdx.x*blockDim.x + threadIdx.x) >> 5;
    int lane = threadIdx.x & 31;
    if (wid >= SN*BN*CH) return;
    int c = wid & 127, b = (wid>>7)&15, s = wid>>11;
    const float* qp = g_q   + ((size_t)b*128 + c)*1024;
    const float* kp = g_ksa + (size_t)(s*16+b)*1024;
    float acc = 0.f;
    for (int p=lane; p<1024; p+=32) acc += qp[p]*kp[p];
    #pragma unroll
    for (int o=16;o;o>>=1) acc += __shfl_down_sync(0xffffffffu, acc, o);
    if (!lane) g_qfg[wid] = acc*(1.f/1024.f);
}

__global__ void sprob_k()
{
    int img = blockIdx.x;
    __shared__ float fq[128];
    int t = threadIdx.x;
    if (t < 128) fq[t] = g_qfg[img*128 + t];
    __syncthreads();
    for (int p=t; p<1024; p+=256){
        const float* kp = g_k + (size_t)img*CHW + p;
        float acc = 0.f;
        #pragma unroll 4
        for (int c=0;c<128;c++) acc += fq[c]*kp[(size_t)c<<10];
        g_sprob[img*1024 + p] = sigmf(acc);
    }
}

__global__ void tlogit_k()
{
    int img = blockIdx.x, b = img & 15;
    float acc = 0.f;
    for (int i=threadIdx.x; i<CHW; i+=256){
        int p = i & 1023;
        acc += g_q[(size_t)b*CHW + i]*g_qsa[b*1024+p]
             * g_k[(size_t)img*CHW + i]*g_ksa[img*1024+p];
    }
    #pragma unroll
    for (int o=16;o;o>>=1) acc += __shfl_down_sync(0xffffffffu, acc, o);
    __shared__ float sh[8];
    if ((threadIdx.x&31)==0) sh[threadIdx.x>>5] = acc;
    __syncthreads();
    if (threadIdx.x==0){
        float S=0.f;
        #pragma unroll
        for (int i=0;i<8;i++) S += sh[i];
        g_tl[img] = S * rsqrtf(131072.f);
    }
}

__global__ void tprob_k()
{
    int b = threadIdx.x;
    if (b >= 16) return;
    float m = -3.402823466e38f;
    #pragma unroll
    for (int s=0;s<8;s++) m = fmaxf(m, g_tl[s*16+b]);
    float e[8]; float sum = 0.f;
    #pragma unroll
    for (int s=0;s<8;s++){ e[s] = __expf(g_tl[s*16+b] - m); sum += e[s]; }
    float inv = 1.f/sum;
    #pragma unroll
    for (int s=0;s<8;s++) g_tp[s*16+b] = e[s]*inv;
}

__global__ void av_k()
{
    int i = blockIdx.x*blockDim.x + threadIdx.x;
    if (i >= BN*CHW/4) return;
    int base = i<<2;
    int b = base>>17; int c = (base>>10)&127; int p = base&1023;
    float4 acc = make_float4(0.f,0.f,0.f,0.f);
    #pragma unroll
    for (int s=0;s<8;s++){
        int img = s*16 + b;
        float tw = g_tp[img];
        float4 sp = *(const float4*)&g_sprob[img*1024 + p];
        float4 vv = *(const float4*)&g_v[((size_t)img*128 + c)*1024 + p];
        acc.x += tw*sp.x*vv.x; acc.y += tw*sp.y*vv.y;
        acc.z += tw*sp.z*vv.z; acc.w += tw*sp.w*vv.w;
    }
    *(float4*)&g_av[base] = acc;
}

__global__ void newout_k(const unsigned char* __restrict__ mask, float* __restrict__ out)
{
    int i = blockIdx.x*blockDim.x + threadIdx.x;
    if (i >= BN*CHW/4) return;
    int base = i<<2;
    int b = base>>17;
    float4 v = mask_at(mask, b) ? *(const float4*)&g_att[base]
                                : make_float4(0.f,0.f,0.f,0.f);
    *(float4*)&out[(size_t)2*BN*CHW + base] = v;
}

__global__ void semean_k()
{
    int b = blockIdx.x;
    int w = threadIdx.x>>5, lane = threadIdx.x&31;
    for (int c=w; c<128; c+=8){
        const float* p = g_o + ((size_t)b*128 + c)*1024;
        float s = 0.f;
        for (int i=lane; i<1024; i+=32) s += p[i];
        #pragma unroll
        for (int o=16;o;o>>=1) s += __shfl_down_sync(0xffffffffu, s, o);
        if (!lane) g_se1[b*128+c] = s*(1.f/1024.f);
    }
}

__global__ void sefc1_k(const float* __restrict__ w1, const float* __restrict__ b1)
{
    int t = threadIdx.x;
    int b = t>>5, j = t&31;
    float acc = b1[j];
    #pragma unroll 4
    for (int c=0;c<128;c++) acc += g_se1[b*128+c]*w1[j*128+c];
    g_se2[b*32+j] = fmaxf(acc, 0.f);
}

__global__ void sefc2_k(const float* __restrict__ w2, const float* __restrict__ b2)
{
    int i = blockIdx.x*blockDim.x + threadIdx.x;
    if (i >= BN*CH) return;
    int b = i>>7, c = i&127;
    float acc = b2[c];
    #pragma unroll
    for (int j=0;j<32;j++) acc += g_se2[b*32+j]*w2[c*32+j];
    g_se3[i] = sigmf(acc);
}

__global__ void final_k(float* __restrict__ out)
{
    int i = blockIdx.x*blockDim.x + threadIdx.x;
    if (i >= BN*CHW/4) return;
    int base = i<<2;
    int b = base>>17; int c = (base>>10)&127;
    float g = 1.f + g_se3[b*128+c];
    float4 o4 = *(const float4*)&g_o[base];
    o4.x*=g; o4.y*=g; o4.z*=g; o4.w*=g;
    *(float4*)&out[base] = o4;
    *(float4*)&out[(size_t)BN*CHW + base] = *(const float4*)&g_ht[base];
}

// ---- host launcher ----
extern "C" void kernel_launch(void* const* d_in, const int* in_sizes, int n_in,
                              void* d_out, int out_size)
{
    (void)in_sizes; (void)n_in; (void)out_size;
    const float* inputs  = (const float*)d_in[0];
    const float* hidden  = (const float*)d_in[1];
    const float* outq    = (const float*)d_in[2];
    const unsigned char* mask = (const unsigned char*)d_in[3];
    const float* enc_w   = (const float*)d_in[4];
    const float* enc_gw  = (const float*)d_in[5];
    const float* enc_gb  = (const float*)d_in[6];
    const float* qpre_w  = (const float*)d_in[7];
    const float* qpre_gw = (const float*)d_in[8];
    const float* qpre_gb = (const float*)d_in[9];
    const float* kpre_w  = (const float*)d_in[10];
    const float* kpre_gw = (const float*)d_in[11];
    const float* kpre_gb = (const float*)d_in[12];
    const float* vpre_w  = (const float*)d_in[13];
    const float* vpre_gw = (const float*)d_in[14];
    const float* vpre_gb = (const float*)d_in[15];
    const float* qsa_w   = (const float*)d_in[16];
    const float* qsa_b   = (const float*)d_in[17];
    const float* ksa_w   = (const float*)d_in[18];
    const float* ksa_b   = (const float*)d_in[19];
    const float* vpost_w = (const float*)d_in[20];
    const float* vpost_gw= (const float*)d_in[21];
    const float* vpost_gb= (const float*)d_in[22];
    const float* pos_emb = (const float*)d_in[23];
    const float* outt_w  = (const float*)d_in[24];
    const float* outt_gw = (const float*)d_in[25];
    const float* outt_gb = (const float*)d_in[26];
    const float* se_w1   = (const float*)d_in[27];
    const float* se_b1   = (const float*)d_in[28];
    const float* se_w2   = (const float*)d_in[29];
    const float* se_b2   = (const float*)d_in[30];
    float* out = (float*)d_out;

    float *ht,*q,*k,*v,*av,*att,*o,*stats,*pool,*qsa,*ksa,*peN,*wT,*Pb;
    __half *wrep, *nhwc, *nhwcS;
    cudaGetSymbolAddress((void**)&ht,   g_ht);
    cudaGetSymbolAddress((void**)&q,    g_q);
    cudaGetSymbolAddress((void**)&k,    g_k);
    cudaGetSymbolAddress((void**)&v,    g_v);
    cudaGetSymbolAddress((void**)&av,   g_av);
    cudaGetSymbolAddress((void**)&att,  g_att);
    cudaGetSymbolAddress((void**)&o,    g_o);
    cudaGetSymbolAddress((void**)&stats,g_stats);
    cudaGetSymbolAddress((void**)&pool, g_pool);
    cudaGetSymbolAddress((void**)&qsa,  g_qsa);
    cudaGetSymbolAddress((void**)&ksa,  g_ksa);
    cudaGetSymbolAddress((void**)&peN,  g_peN);
    cudaGetSymbolAddress((void**)&wT,   g_wT);
    cudaGetSymbolAddress((void**)&Pb,   g_Pb);
    cudaGetSymbolAddress((void**)&wrep, g_wrep);
    cudaGetSymbolAddress((void**)&nhwc, g_nhwc);
    cudaGetSymbolAddress((void**)&nhwcS,g_nhwcS);

    const int OFF_ENC   = 0;
    const int OFF_VPOST = 73728;
    // wrep offsets (halfs)
    const size_t WR_KPRE = 0;
    const size_t WR_VPRE = 589824;
    const size_t WR_QPRE = 1179648;
    const size_t WR_OUTT = 1474560;

    cudaFuncSetAttribute(mmaconv_k, cudaFuncAttributeMaxDynamicSharedMemorySize, DSMEM_TOTAL);

    // launch order keeps mmaconv(kpre) as launch #4 (profiled)
    zero_half_k<<<2048,256>>>(nhwc, ((size_t)TOTROWS*256*2)/16);      // 1
    fill_nhwc_k<<<4096,256>>>(hidden, outq);                          // 2
    wrep_k<<<1152,256>>>(kpre_w, wrep + WR_KPRE, 256, 2);             // 3
    mmaconv_k<<<1280,256,DSMEM_TOTAL>>>(wrep + WR_KPRE, nhwc, nullptr, k, 2);  // 4
    zero_half_k<<<1024,256>>>(nhwcS, ((size_t)TOTROWS_S*256*2)/16);   // 5
    wrep_k<<<1152,256>>>(vpre_w, wrep + WR_VPRE, 256, 2);
    pe_norm_k<<<8,256>>>(pos_emb, peN);
    pbconv_k<<<8,128>>>(vpre_w);
    mmaconv_k<<<1280,256,DSMEM_TOTAL>>>(wrep + WR_VPRE, nhwc, Pb, v, 2);
    wrep_k<<<576,256>>>(qpre_w, wrep + WR_QPRE, 128, 1);
    wrep_k<<<1152,256>>>(outt_w, wrep + WR_OUTT, 192, 2);
    transw_k<<<128,256>>>(enc_w,  wT+OFF_ENC,  64, 9);
    transw_k<<<64,256>>>(vpost_w, wT+OFF_VPOST, 128, 1);

    // ht = silu(gn(conv(inputs, enc_w)))
    conv3x3_k<<<BN*8,256>>>(inputs, wT+OFF_ENC, ht, 64);
    gn_reduce_k<<<BN,256>>>(ht, stats);
    gn_apply_k<<<2048,256>>>(ht, stats, enc_gw, enc_gb, BN, 1);

    // q = gn(mmaconv(ht, qpre_w))
    fill16_k<<<512,256>>>(ht);
    mmaconv_k<<<160,256,DSMEM_TOTAL>>>(wrep + WR_QPRE, nhwcS, nullptr, q, 1);
    gn_reduce_k<<<BN,256>>>(q, stats);
    gn_apply_k<<<2048,256>>>(q, stats, qpre_gw, qpre_gb, BN, 0);

    // gn for k and v
    gn_reduce_k<<<SBN,256>>>(k, stats);
    gn_apply_k<<<4096,256>>>(k, stats, kpre_gw, kpre_gb, SBN, 0);
    gn_reduce_k<<<SBN,256>>>(v, stats);
    gn_apply_k<<<4096,256>>>(v, stats, vpre_gw, vpre_gb, SBN, 0);

    // spatial filters
    pool_k<<<(BN*HWN+255)/256,256>>>(q, pool, BN);
    saconv_k<<<(BN*HWN+255)/256,256>>>(pool, qsa_w, qsa_b, qsa, BN);
    pool_k<<<(SBN*HWN+255)/256,256>>>(k, pool, SBN);
    saconv_k<<<(SBN*HWN+255)/256,256>>>(pool, ksa_w, ksa_b, ksa, SBN);

    // attention
    qfg_k<<<2048,256>>>();
    sprob_k<<<SBN,256>>>();
    tlogit_k<<<SBN,256>>>();
    tprob_k<<<1,32>>>();
    av_k<<<2048,256>>>();

    // att = silu(gn(conv1x1(av)))
    conv1x1_k<<<BN*8,256>>>(av, wT+OFF_VPOST, att);
    gn_reduce_k<<<BN,256>>>(att, stats);
    gn_apply_k<<<2048,256>>>(att, stats, vpost_gw, vpost_gb, BN, 1);

    newout_k<<<2048,256>>>(mask, out);

    // o = silu(gn(mmaconv(concat(inputs, att+ht), outt_w)))
    xcat_fill_k<<<512,256>>>(inputs);
    mmaconv_k<<<160,256,DSMEM_TOTAL>>>(wrep + WR_OUTT, nhwcS, nullptr, o, 2);
    gn_reduce_k<<<BN,256>>>(o, stats);
    gn_apply_k<<<2048,256>>>(o, stats, outt_gw, outt_gb, BN, 1);

    semean_k<<<BN,256>>>();
    sefc1_k<<<1,512>>>(se_w1, se_b1);
    sefc2_k<<<8,256>>>(se_w2, se_b2);
    final_k<<<2048,256>>>(out);
}

// round 10
// speedup vs baseline: 3.2061x; 1.0418x over previous
#include <cuda_runtime.h>
#include <cuda_fp16.h>
#include <cstdint>

#define BN   16
#define CH   128
#define HWN  1024
#define SN   8
#define SBN  128
#define CHW  131072

#define GUARD   64
#define RPI     1344
#define TOTROWS   (GUARD + 128*RPI + 256)
#define TOTROWS_S (GUARD + 16*RPI + 256)

// mmaconv smem (bytes): X window 200 rows x 256B, then one A buffer 32KB (2 sp x 64k)
#define AB_OFF 51200
#define DSMEM_TOTAL 83968

// stats slots (2 floats per img): K=0, V=256, HT=512, Q=544, ATT=576, O=608
#define ST_K   0
#define ST_V   256
#define ST_HT  512
#define ST_Q   544
#define ST_ATT 576
#define ST_O   608

__device__ float g_ht [BN*CHW];
__device__ float g_q  [BN*CHW];
__device__ float g_k  [SBN*CHW];
__device__ float g_v  [SBN*CHW];
__device__ float g_av [BN*CHW];
__device__ float g_att[BN*CHW];
__device__ float g_o  [BN*CHW];
__device__ float g_stats[640];
__device__ float g_pool[SBN*2*HWN];
__device__ float g_qsa[BN*HWN];
__device__ float g_ksa[SBN*HWN];
__device__ float g_qfg[SN*BN*CH];
__device__ float g_sprob[SBN*HWN];
__device__ float g_tl[SN*BN];
__device__ float g_tp[SN*BN];
__device__ float g_peN[SN*2*CH];
__device__ float g_se1[BN*CH];
__device__ float g_se2[BN*32];
__device__ float g_se3[BN*CH];
__device__ float g_Pb[SN*CH*9];
__device__ float g_wT[16384];
__device__ __half g_nhwc [(size_t)TOTROWS*256];
__device__ __half g_nhwcS[(size_t)TOTROWS_S*256];
// wrep: kpre(589824) | vpre(589824) | qpre(294912) | outt(589824) | enc(294912)
__device__ __half g_wrep[2359296];

__device__ __forceinline__ float sigmf(float x){ return 1.f/(1.f + __expf(-x)); }
__device__ __forceinline__ bool mask_at(const unsigned char* m, int b){
    if (m[1] != 0) return m[b] != 0;
    const unsigned int* w = (const unsigned int*)m;
    return w[b] != 0;
}

__device__ __forceinline__ uint32_t smem_u32(const void* p){
    uint32_t a;
    asm("{ .reg .u64 t; cvta.to.shared.u64 t, %1; cvt.u32.u64 %0, t; }" : "=r"(a) : "l"(p));
    return a;
}
__device__ __forceinline__ void mma16816(float* d, uint32_t a0, uint32_t a1, uint32_t a2,
                                         uint32_t a3, uint32_t b0, uint32_t b1){
    asm volatile("mma.sync.aligned.m16n8k16.row.col.f32.f16.f16.f32 "
        "{%0,%1,%2,%3}, {%4,%5,%6,%7}, {%8,%9}, {%0,%1,%2,%3};"
        : "+f"(d[0]),"+f"(d[1]),"+f"(d[2]),"+f"(d[3])
        : "r"(a0),"r"(a1),"r"(a2),"r"(a3),"r"(b0),"r"(b1));
}
__device__ __forceinline__ void ldsm4(uint32_t& r0,uint32_t& r1,uint32_t& r2,uint32_t& r3,
                                      uint32_t addr){
    asm volatile("ldmatrix.sync.aligned.m8n8.x4.shared.b16 {%0,%1,%2,%3}, [%4];"
        : "=r"(r0),"=r"(r1),"=r"(r2),"=r"(r3) : "r"(addr));
}
__device__ __forceinline__ void cpa16(uint32_t d, const void* s){
    asm volatile("cp.async.cg.shared.global [%0], [%1], 16;" :: "r"(d), "l"(s));
}
__device__ __forceinline__ void cp_commit(){ asm volatile("cp.async.commit_group;" ::: "memory"); }
__device__ __forceinline__ void cp_wait0(){ asm volatile("cp.async.wait_group 0;" ::: "memory"); }

// ---- misc small kernels ----
__global__ void zero_stats_k(){ if (threadIdx.x < 640) g_stats[threadIdx.x] = 0.f; }

__global__ void transw_k(const float* __restrict__ w, float* __restrict__ wT,
                         int cin, int ktaps)
{
    int n = cin*ktaps*128;
    for (int i = blockIdx.x*blockDim.x + threadIdx.x; i < n; i += gridDim.x*blockDim.x){
        int co = i & 127;
        int r  = i >> 7;
        int tap = r % ktaps;
        int c   = r / ktaps;
        wT[i] = w[(co*cin + c)*ktaps + tap];
    }
}

__global__ void pe_norm_k(const float* __restrict__ pe, float* __restrict__ peN)
{
    int s = blockIdx.x, t = threadIdx.x;
    float v = pe[s*256 + t];
    float q = v*v;
    #pragma unroll
    for (int o=16;o;o>>=1) q += __shfl_down_sync(0xffffffffu, q, o);
    __shared__ float a[8];
    __shared__ float fac;
    if ((t&31)==0) a[t>>5] = q;
    __syncthreads();
    if (t==0){
        float S=0.f;
        #pragma unroll
        for (int i=0;i<8;i++) S += a[i];
        float n = sqrtf(S);
        fac = fminf(1.f, 1.f/fmaxf(n, 1e-7f));
    }
    __syncthreads();
    peN[s*256 + t] = v*fac;
}

__global__ void zero_half_k(__half* buf, size_t n16)
{
    uint4 z = make_uint4(0,0,0,0);
    uint4* p = (uint4*)buf;
    for (size_t i = (size_t)blockIdx.x*blockDim.x + threadIdx.x; i < n16;
         i += (size_t)gridDim.x*blockDim.x) p[i] = z;
}

// big buffer fill: kv concat (128 imgs, 256 ch)
__global__ void fill_nhwc_k(const float* __restrict__ hid, const float* __restrict__ oq)
{
    __shared__ float s[32][257];
    int t = threadIdx.x;
    int img = blockIdx.x>>5, y = blockIdx.x&31;
    int xg = t&31, cg = t>>5;
    size_t rb = GUARD + (size_t)img*RPI + (size_t)(y+1)*34;
    #pragma unroll
    for (int cc=0; cc<32; cc++){
        int c = cc*8 + cg;
        const float* src = (c<128) ? hid + ((size_t)img*128 + c)*1024
                                   : oq  + ((size_t)img*128 + (c-128))*1024;
        s[xg][c] = src[y*32 + xg];
    }
    __syncthreads();
    #pragma unroll
    for (int xs=0; xs<32; xs++)
        g_nhwc[(rb + xs + 1)*256 + t] = __float2half(s[xs][t]);
}

// small buffer fill: inputs (ch0-63; 64-255 stay zero)
__global__ void fill_in_k(const float* __restrict__ inputs)
{
    __shared__ float s[32][65];
    int t = threadIdx.x;
    int img = blockIdx.x>>5, y = blockIdx.x&31;
    int xg = t&31, cg = t>>5;
    size_t rb = GUARD + (size_t)img*RPI + (size_t)(y+1)*34;
    #pragma unroll
    for (int cc=0; cc<8; cc++){
        int c = cc*8 + cg;
        s[xg][c] = inputs[((size_t)img*64 + c)*1024 + y*32 + xg];
    }
    __syncthreads();
    if (t < 64){
        #pragma unroll
        for (int xs=0; xs<32; xs++)
            g_nhwcS[(rb + xs + 1)*256 + t] = __float2half(s[xs][t]);
    }
}

// small buffer fill: ht (ch0-127)
__global__ void fill16_k(const float* __restrict__ src)
{
    __shared__ float s[32][129];
    int t = threadIdx.x;
    int img = blockIdx.x>>5, y = blockIdx.x&31;
    int xg = t&31, cg = t>>5;
    size_t rb = GUARD + (size_t)img*RPI + (size_t)(y+1)*34;
    #pragma unroll
    for (int cc=0; cc<16; cc++){
        int c = cc*8 + cg;
        s[xg][c] = src[((size_t)img*128 + c)*1024 + y*32 + xg];
    }
    __syncthreads();
    if (t < 128){
        #pragma unroll
        for (int xs=0; xs<32; xs++)
            g_nhwcS[(rb + xs + 1)*256 + t] = __float2half(s[xs][t]);
    }
}

// small buffer fill: concat(inputs[64], att+ht[128]) -> ch0-191
__global__ void xcat_fill_k(const float* __restrict__ inputs)
{
    __shared__ float s[32][193];
    int t = threadIdx.x;
    int img = blockIdx.x>>5, y = blockIdx.x&31;
    int xg = t&31, cg = t>>5;
    size_t rb = GUARD + (size_t)img*RPI + (size_t)(y+1)*34;
    #pragma unroll
    for (int cc=0; cc<24; cc++){
        int c = cc*8 + cg;
        float val;
        if (c < 64) val = inputs[((size_t)img*64 + c)*1024 + y*32 + xg];
        else {
            int c2 = c - 64;
            val = g_att[((size_t)img*128 + c2)*1024 + y*32 + xg]
                + g_ht [((size_t)img*128 + c2)*1024 + y*32 + xg];
        }
        s[xg][c] = val;
    }
    __syncthreads();
    if (t < 192){
        #pragma unroll
        for (int xs=0; xs<32; xs++)
            g_nhwcS[(rb + xs + 1)*256 + t] = __float2half(s[xs][t]);
    }
}

// ---- weight repack: [sp][tap*nkc+kc][co][128k] fp16 hi/lo; zero-pad cin ----
__global__ void wrep_k(const float* __restrict__ w, __half* __restrict__ dst,
                       int cin, int nkc)
{
    int n = nkc*147456;
    int i = blockIdx.x*blockDim.x + threadIdx.x;
    if (i >= n) return;
    int kl = i & 127;
    int r = i >> 7;
    int co = r & 127; r >>= 7;
    int kc = r % nkc;
    int tap = r / nkc;
    int cin_idx = kc*128 + kl;
    float val = (cin_idx < cin) ? w[((size_t)co*cin + cin_idx)*9 + tap] : 0.f;
    __half h = __float2half(val);
    int o = ((tap*nkc+kc)*128 + co)*128 + kl;
    dst[o] = h;
    dst[n + o] = __float2half(val - __half2float(h));
}

// ---- pe correction with border masks ----
__global__ void pbconv_k(const float* __restrict__ w)
{
    int s = blockIdx.x, co = threadIdx.x;
    float P[9];
    #pragma unroll
    for (int tap=0;tap<9;tap++){
        float acc = 0.f;
        for (int c=0;c<256;c++)
            acc += g_peN[s*256 + c] * w[((size_t)co*256 + c)*9 + tap];
        P[tap] = acc;
    }
    #pragma unroll
    for (int yc=0;yc<3;yc++){
        #pragma unroll
        for (int xc=0;xc<3;xc++){
            float tot = 0.f;
            #pragma unroll
            for (int dy=0;dy<3;dy++){
                if ((yc==0 && dy==0) || (yc==2 && dy==2)) continue;
                float rs = P[dy*3+1];
                if (xc!=0) rs += P[dy*3+0];
                if (xc!=2) rs += P[dy*3+2];
                tot += rs;
            }
            g_Pb[(s*128+co)*9 + yc*3+xc] = tot;
        }
    }
}

// ---- per-(tap,kh) MMA: B fragments shared across both A splits ----
__device__ __forceinline__ void conv_tap_kh(uint32_t xb, uint32_t ab, int tap, int kh,
                                            int lane, int cob, int pxb,
                                            float acc[4][4][4])
{
    const int lr  = lane & 7;
    const int hsA = lane >> 4;
    const int hsB = (lane >> 3) & 1;
    const int dy = tap/3, dx = tap - dy*3;
    const int dlt = (dy-1)*34 + (dx-1);

    uint32_t rowA[4], rsA[4];
    #pragma unroll
    for (int mi=0;mi<4;mi++){
        int r = cob + mi*16 + lr + ((lane>>3)&1)*8;
        rowA[mi] = (uint32_t)r*128u; rsA[mi] = (uint32_t)(r&7);
    }
    uint32_t rowB[2], rsB[2];
    #pragma unroll
    for (int nn=0;nn<2;nn++){
        int r = 36 + dlt + pxb + nn*16 + lr + (lane>>4)*8;
        rowB[nn] = (uint32_t)r*256u; rsB[nn] = (uint32_t)(r&7);
    }
    #pragma unroll
    for (int k8=0;k8<4;k8++){
        uint32_t b[2][4];
        #pragma unroll
        for (int nn=0;nn<2;nn++){
            uint32_t sgi = (uint32_t)((kh*4+k8)*2 + hsB);
            ldsm4(b[nn][0],b[nn][1],b[nn][2],b[nn][3],
                  xb + rowB[nn] + ((sgi ^ rsB[nn])<<4));
        }
        #pragma unroll
        for (int sp=0;sp<2;sp++){
            uint32_t a[4][4];
            #pragma unroll
            for (int mi=0;mi<4;mi++){
                uint32_t sgi = (uint32_t)(k8*2 + hsA);
                ldsm4(a[mi][0],a[mi][1],a[mi][2],a[mi][3],
                      ab + (uint32_t)sp*16384u + rowA[mi] + ((sgi ^ rsA[mi])<<4));
            }
            #pragma unroll
            for (int nn=0;nn<2;nn++){
                #pragma unroll
                for (int mi=0;mi<4;mi++){
                    mma16816(acc[mi][2*nn],   a[mi][0],a[mi][1],a[mi][2],a[mi][3],
                             b[nn][0],b[nn][1]);
                    mma16816(acc[mi][2*nn+1], a[mi][0],a[mi][1],a[mi][2],a[mi][3],
                             b[nn][2],b[nn][3]);
                }
            }
        }
    }
}

// ---- mma.sync fp16 implicit conv: D[128co,128px], 2 CTAs/SM, fused GN partial sums ----
__global__ __launch_bounds__(256,2)
void mmaconv_k(const __half* __restrict__ wrep,
               const __half* __restrict__ nhwc,
               const float* __restrict__ Pb,
               float* __restrict__ dst,
               float* __restrict__ stats, int nkc)
{
    extern __shared__ char dsm[];
    const uint32_t sb = smem_u32(dsm);
    const uint32_t XB = sb;
    const uint32_t AB = sb + AB_OFF;
    const int t = threadIdx.x;
    const int wid = t>>5, lane = t&31;
    const int img = blockIdx.x/10;
    const int p0  = (blockIdx.x%10)*128;
    const int s   = img>>4;
    const int cob = (wid&1)*64;
    const int pxb = (wid>>1)*32;
    const size_t spstrB = (size_t)nkc*294912;   // sp stride in bytes

    float acc[4][4][4];
    #pragma unroll
    for (int mi=0;mi<4;mi++)
    #pragma unroll
    for (int ni=0;ni<4;ni++)
    #pragma unroll
    for (int e=0;e<4;e++) acc[mi][ni][e]=0.f;

    for (int kc=0; kc<nkc; kc++){
        // stage X window: 200 rows x 128k fp16 (one kc half)
        {
            const char* src = (const char*)nhwc
                + ((size_t)GUARD + (size_t)img*RPI + p0 - 36)*512 + kc*256;
            #pragma unroll
            for (int j=0;j<13;j++){
                int i = j*256 + t;
                if (i < 3200){
                    uint32_t r = (uint32_t)(i>>4), sg = (uint32_t)(i&15);
                    cpa16(XB + r*256 + ((sg^(r&7))<<4), src + (size_t)r*512 + sg*16);
                }
            }
            cp_commit();
        }
        for (int tap=0; tap<9; tap++){
            for (int kh=0; kh<2; kh++){
                // stage A: both splits, 64-k slice -> 32KB
                const char* asrc = (const char*)(wrep + (size_t)(tap*nkc+kc)*16384 + kh*64);
                #pragma unroll
                for (int j=0;j<8;j++){
                    int i = j*256 + t;
                    int sp = i>>10, ii = i&1023;
                    uint32_t r = (uint32_t)(ii>>3), sg = (uint32_t)(ii&7);
                    cpa16(AB + sp*16384 + r*128 + ((sg^(r&7))<<4),
                          asrc + (size_t)sp*spstrB + (size_t)r*256 + sg*16);
                }
                cp_commit(); cp_wait0(); __syncthreads();
                conv_tap_kh(XB, AB, tap, kh, lane, cob, pxb, acc);
                __syncthreads();
            }
        }
    }

    // epilogue: stores + local GN partial sums
    const int g  = lane>>2;
    const int t2 = (lane&3)*2;
    float sm_=0.f, sq_=0.f;
    #pragma unroll
    for (int mi=0;mi<4;mi++){
        #pragma unroll
        for (int n8=0;n8<4;n8++){
            #pragma unroll
            for (int e=0;e<4;e++){
                int co  = cob + mi*16 + g + ((e>>1)<<3);
                int col = pxb + n8*8 + t2 + (e&1);
                int pp  = p0 + col;
                int q34 = pp/34;
                int yy  = q34 - 1;
                int xx  = pp - q34*34 - 1;
                if ((unsigned)yy < 32u && (unsigned)xx < 32u){
                    float v = acc[mi][n8][e];
                    if (Pb){
                        int yc = (yy==0)?0:((yy==31)?2:1);
                        int xc = (xx==0)?0:((xx==31)?2:1);
                        v += Pb[(s*128+co)*9 + yc*3+xc];
                    }
                    dst[((size_t)img*128+co)*1024 + (yy<<5)+xx] = v;
                    sm_ += v; sq_ += v*v;
                }
            }
        }
    }
    #pragma unroll
    for (int o=16;o;o>>=1){
        sm_ += __shfl_down_sync(0xffffffffu, sm_, o);
        sq_ += __shfl_down_sync(0xffffffffu, sq_, o);
    }
    float* red = (float*)dsm;
    __syncthreads();
    if (lane==0){ red[wid*2] = sm_; red[wid*2+1] = sq_; }
    __syncthreads();
    if (t==0){
        float S=0.f, S2=0.f;
        #pragma unroll
        for (int w=0;w<8;w++){ S += red[w*2]; S2 += red[w*2+1]; }
        atomicAdd(&stats[img*2],   S);
        atomicAdd(&stats[img*2+1], S2);
    }
}

// ---- 1x1 conv (vpost) ----
__global__ __launch_bounds__(256,2)
void conv1x1_k(const float* __restrict__ src, const float* __restrict__ wT,
               float* __restrict__ dst)
{
    __shared__ float sIn[8*128];
    __shared__ float sW [8*128];
    const int t   = threadIdx.x;
    const int img = blockIdx.x >> 3;
    const int p0  = (blockIdx.x & 7) << 7;
    const int xl  = t & 31;
    const int cg  = t >> 5;
    float acc[64];
    #pragma unroll
    for (int i=0;i<64;i++) acc[i]=0.f;

    for (int cc=0; cc<16; cc++){
        for (int e=t; e<1024; e+=256){
            int ci = e>>7, i = e&127;
            sIn[e] = src[((size_t)img*128 + (cc<<3)+ci)*1024 + p0 + i];
            sW [e] = wT[(cc<<10) + e];
        }
        __syncthreads();
        #pragma unroll
        for (int ci=0;ci<8;ci++){
            float inr[4];
            #pragma unroll
            for (int y=0;y<4;y++) inr[y] = sIn[ci*128 + (y<<5) + xl];
            const float4* wq = (const float4*)&sW[ci*128 + (cg<<4)];
            float4 w0=wq[0], w1=wq[1], w2=wq[2], w3=wq[3];
            #pragma unroll
            for (int y=0;y<4;y++){
                float iv = inr[y];
                float* a = &acc[y*16];
                a[0]+=iv*w0.x; a[1]+=iv*w0.y; a[2]+=iv*w0.z; a[3]+=iv*w0.w;
                a[4]+=iv*w1.x; a[5]+=iv*w1.y; a[6]+=iv*w1.z; a[7]+=iv*w1.w;
                a[8]+=iv*w2.x; a[9]+=iv*w2.y; a[10]+=iv*w2.z; a[11]+=iv*w2.w;
                a[12]+=iv*w3.x; a[13]+=iv*w3.y; a[14]+=iv*w3.z; a[15]+=iv*w3.w;
            }
        }
        __syncthreads();
    }
    #pragma unroll
    for (int j=0;j<16;j++){
        int co = (cg<<4)+j;
        #pragma unroll
        for (int y=0;y<4;y++)
            dst[((size_t)img*128+co)*1024 + p0 + (y<<5) + xl] = acc[y*16+j];
    }
}

// ---- GN reduce (att only): raw sums ----
__global__ void gn_reduce_k(const float* __restrict__ x, float* __restrict__ stats)
{
    const int img = blockIdx.x;
    const float4* p = (const float4*)(x + (size_t)img*CHW);
    float s=0.f, s2=0.f;
    for (int i=threadIdx.x; i<32768; i+=blockDim.x){
        float4 v = p[i];
        s  += v.x+v.y+v.z+v.w;
        s2 += v.x*v.x+v.y*v.y+v.z*v.z+v.w*v.w;
    }
    #pragma unroll
    for (int o=16;o;o>>=1){
        s  += __shfl_down_sync(0xffffffffu, s , o);
        s2 += __shfl_down_sync(0xffffffffu, s2, o);
    }
    __shared__ float sa[8], sb[8];
    if ((threadIdx.x&31)==0){ sa[threadIdx.x>>5]=s; sb[threadIdx.x>>5]=s2; }
    __syncthreads();
    if (threadIdx.x==0){
        float S=0.f, S2=0.f;
        #pragma unroll
        for (int i=0;i<8;i++){ S+=sa[i]; S2+=sb[i]; }
        stats[img*2]   = S;
        stats[img*2+1] = S2;
    }
}

// ---- GN apply from raw sums (elementwise, optional silu) ----
__global__ void gn_apply_k(float* __restrict__ x, const float* __restrict__ stats,
                           const float* __restrict__ gw, const float* __restrict__ gb,
                           int nimg, int act)
{
    int n4 = nimg*32768;
    for (int i = blockIdx.x*blockDim.x + threadIdx.x; i < n4; i += gridDim.x*blockDim.x){
        int base = i<<2;
        int img = base>>17; int c = (base>>10)&127;
        float sum = stats[2*img], ssq = stats[2*img+1];
        float mu = sum*(1.f/131072.f);
        float rs = rsqrtf(ssq*(1.f/131072.f) - mu*mu + 1e-5f);
        float sc = rs*gw[c];
        float sh = gb[c] - mu*sc;
        float4 v = ((float4*)x)[i];
        v.x = v.x*sc+sh; v.y = v.y*sc+sh; v.z = v.z*sc+sh; v.w = v.w*sc+sh;
        if (act){
            v.x *= sigmf(v.x); v.y *= sigmf(v.y); v.z *= sigmf(v.z); v.w *= sigmf(v.w);
        }
        ((float4*)x)[i] = v;
    }
}

// ---- GN apply + channel mean/max pool fused (k, q) ----
__global__ void gn_apply_pool_k(float* __restrict__ x, const float* __restrict__ stats,
                                const float* __restrict__ gw, const float* __restrict__ gb,
                                float* __restrict__ pool)
{
    __shared__ float sc[128], sh[128];
    int t = threadIdx.x;
    int img = blockIdx.x>>2;
    int p = ((blockIdx.x&3)<<8) + t;
    if (t < 128){
        float sum = stats[2*img], ssq = stats[2*img+1];
        float mu = sum*(1.f/131072.f);
        float rs = rsqrtf(ssq*(1.f/131072.f) - mu*mu + 1e-5f);
        float scv = rs*gw[t];
        sc[t] = scv; sh[t] = gb[t] - mu*scv;
    }
    __syncthreads();
    float* base = x + (size_t)img*CHW + p;
    float s = 0.f, m = -3.402823466e38f;
    #pragma unroll 4
    for (int c=0;c<128;c++){
        float y = base[(size_t)c<<10]*sc[c] + sh[c];
        base[(size_t)c<<10] = y;
        s += y; m = fmaxf(m, y);
    }
    pool[img*2048 + p]        = s*(1.f/128.f);
    pool[img*2048 + 1024 + p] = m;
}

// ---- GN apply att (silu) + newout write fused ----
__global__ void gn_apply_att_k(float* __restrict__ x, const float* __restrict__ stats,
                               const float* __restrict__ gw, const float* __restrict__ gb,
                               const unsigned char* __restrict__ mask,
                               float* __restrict__ out)
{
    int i = blockIdx.x*blockDim.x + threadIdx.x;
    if (i >= BN*32768) return;
    int base = i<<2;
    int img = base>>17; int c = (base>>10)&127;
    float sum = stats[2*img], ssq = stats[2*img+1];
    float mu = sum*(1.f/131072.f);
    float rs = rsqrtf(ssq*(1.f/131072.f) - mu*mu + 1e-5f);
    float sc = rs*gw[c];
    float sh = gb[c] - mu*sc;
    float4 v = ((float4*)x)[i];
    v.x = v.x*sc+sh; v.y = v.y*sc+sh; v.z = v.z*sc+sh; v.w = v.w*sc+sh;
    v.x *= sigmf(v.x); v.y *= sigmf(v.y); v.z *= sigmf(v.z); v.w *= sigmf(v.w);
    ((float4*)x)[i] = v;
    float4 z = mask_at(mask, img) ? v : make_float4(0.f,0.f,0.f,0.f);
    *(float4*)&out[(size_t)2*BN*CHW + base] = z;
}

// ---- 2->1 3x3 conv + sigmoid ----
__global__ void saconv_k(const float* __restrict__ pool, const float* __restrict__ w,
                         const float* __restrict__ b, float* __restrict__ sa, int nimg)
{
    int i = blockIdx.x*blockDim.x + threadIdx.x;
    if (i >= nimg*HWN) return;
    int img = i>>10, p = i&1023, y = p>>5, x = p&31;
    float acc = b[0];
    #pragma unroll
    for (int c2=0;c2<2;c2++)
    #pragma unroll
    for (int dy=-1;dy<=1;dy++)
    #pragma unroll
    for (int dx=-1;dx<=1;dx++){
        int yy=y+dy, xx=x+dx;
        if ((unsigned)yy<32u && (unsigned)xx<32u)
            acc += pool[img*2048 + c2*1024 + (yy<<5)+xx] * w[c2*9 + (dy+1)*3 + (dx+1)];
    }
    sa[i] = sigmf(acc);
}

// ---- attention pieces ----
__global__ void qfg_k()
{
    int wid  = (blockIdx.x*blockDim.x + threadIdx.x) >> 5;
    int lane = threadIdx.x & 31;
    if (wid >= SN*BN*CH) return;
    int c = wid & 127, b = (wid>>7)&15, s = wid>>11;
    const float* qp = g_q   + ((size_t)b*128 + c)*1024;
    const float* kp = g_ksa + (size_t)(s*16+b)*1024;
    float acc = 0.f;
    for (int p=lane; p<1024; p+=32) acc += qp[p]*kp[p];
    #pragma unroll
    for (int o=16;o;o>>=1) acc += __shfl_down_sync(0xffffffffu, acc, o);
    if (!lane) g_qfg[wid] = acc*(1.f/1024.f);
}

__global__ void sprob_k()
{
    int img = blockIdx.x;
    __shared__ float fq[128];
    int t = threadIdx.x;
    if (t < 128) fq[t] = g_qfg[img*128 + t];
    __syncthreads();
    for (int p=t; p<1024; p+=256){
        const float* kp = g_k + (size_t)img*CHW + p;
        float acc = 0.f;
        #pragma unroll 4
        for (int c=0;c<128;c++) acc += fq[c]*kp[(size_t)c<<10];
        g_sprob[img*1024 + p] = sigmf(acc);
    }
}

__global__ void tlogit_k()
{
    int img = blockIdx.x, b = img & 15;
    float acc = 0.f;
    for (int i=threadIdx.x; i<CHW; i+=256){
        int p = i & 1023;
        acc += g_q[(size_t)b*CHW + i]*g_qsa[b*1024+p]
             * g_k[(size_t)img*CHW + i]*g_ksa[img*1024+p];
    }
    #pragma unroll
    for (int o=16;o;o>>=1) acc += __shfl_down_sync(0xffffffffu, acc, o);
    __shared__ float sh[8];
    if ((threadIdx.x&31)==0) sh[threadIdx.x>>5] = acc;
    __syncthreads();
    if (threadIdx.x==0){
        float S=0.f;
        #pragma unroll
        for (int i=0;i<8;i++) S += sh[i];
        g_tl[img] = S * rsqrtf(131072.f);
    }
}

__global__ void tprob_k()
{
    int b = threadIdx.x;
    if (b >= 16) return;
    float m = -3.402823466e38f;
    #pragma unroll
    for (int s=0;s<8;s++) m = fmaxf(m, g_tl[s*16+b]);
    float e[8]; float sum = 0.f;
    #pragma unroll
    for (int s=0;s<8;s++){ e[s] = __expf(g_tl[s*16+b] - m); sum += e[s]; }
    float inv = 1.f/sum;
    #pragma unroll
    for (int s=0;s<8;s++) g_tp[s*16+b] = e[s]*inv;
}

__global__ void av_k()
{
    int i = blockIdx.x*blockDim.x + threadIdx.x;
    if (i >= BN*CHW/4) return;
    int base = i<<2;
    int b = base>>17; int c = (base>>10)&127; int p = base&1023;
    float4 acc = make_float4(0.f,0.f,0.f,0.f);
    #pragma unroll
    for (int s=0;s<8;s++){
        int img = s*16 + b;
        float tw = g_tp[img];
        float4 sp = *(const float4*)&g_sprob[img*1024 + p];
        float4 vv = *(const float4*)&g_v[((size_t)img*128 + c)*1024 + p];
        acc.x += tw*sp.x*vv.x; acc.y += tw*sp.y*vv.y;
        acc.z += tw*sp.z*vv.z; acc.w += tw*sp.w*vv.w;
    }
    *(float4*)&g_av[base] = acc;
}

__global__ void semean_k()
{
    int b = blockIdx.x;
    int w = threadIdx.x>>5, lane = threadIdx.x&31;
    for (int c=w; c<128; c+=8){
        const float* p = g_o + ((size_t)b*128 + c)*1024;
        float s = 0.f;
        for (int i=lane; i<1024; i+=32) s += p[i];
        #pragma unroll
        for (int o=16;o;o>>=1) s += __shfl_down_sync(0xffffffffu, s, o);
        if (!lane) g_se1[b*128+c] = s*(1.f/1024.f);
    }
}

__global__ void sefc1_k(const float* __restrict__ w1, const float* __restrict__ b1)
{
    int t = threadIdx.x;
    int b = t>>5, j = t&31;
    float acc = b1[j];
    #pragma unroll 4
    for (int c=0;c<128;c++) acc += g_se1[b*128+c]*w1[j*128+c];
    g_se2[b*32+j] = fmaxf(acc, 0.f);
}

__global__ void sefc2_k(const float* __restrict__ w2, const float* __restrict__ b2)
{
    int i = blockIdx.x*blockDim.x + threadIdx.x;
    if (i >= BN*CH) return;
    int b = i>>7, c = i&127;
    float acc = b2[c];
    #pragma unroll
    for (int j=0;j<32;j++) acc += g_se2[b*32+j]*w2[c*32+j];
    g_se3[i] = sigmf(acc);
}

__global__ void final_k(float* __restrict__ out)
{
    int i = blockIdx.x*blockDim.x + threadIdx.x;
    if (i >= BN*CHW/4) return;
    int base = i<<2;
    int b = base>>17; int c = (base>>10)&127;
    float g = 1.f + g_se3[b*128+c];
    float4 o4 = *(const float4*)&g_o[base];
    o4.x*=g; o4.y*=g; o4.z*=g; o4.w*=g;
    *(float4*)&out[base] = o4;
    *(float4*)&out[(size_t)BN*CHW + base] = *(const float4*)&g_ht[base];
}

// ---- host launcher ----
extern "C" void kernel_launch(void* const* d_in, const int* in_sizes, int n_in,
                              void* d_out, int out_size)
{
    (void)in_sizes; (void)n_in; (void)out_size;
    const float* inputs  = (const float*)d_in[0];
    const float* hidden  = (const float*)d_in[1];
    const float* outq    = (const float*)d_in[2];
    const unsigned char* mask = (const unsigned char*)d_in[3];
    const float* enc_w   = (const float*)d_in[4];
    const float* enc_gw  = (const float*)d_in[5];
    const float* enc_gb  = (const float*)d_in[6];
    const float* qpre_w  = (const float*)d_in[7];
    const float* qpre_gw = (const float*)d_in[8];
    const float* qpre_gb = (const float*)d_in[9];
    const float* kpre_w  = (const float*)d_in[10];
    const float* kpre_gw = (const float*)d_in[11];
    const float* kpre_gb = (const float*)d_in[12];
    const float* vpre_w  = (const float*)d_in[13];
    const float* vpre_gw = (const float*)d_in[14];
    const float* vpre_gb = (const float*)d_in[15];
    const float* qsa_w   = (const float*)d_in[16];
    const float* qsa_b   = (const float*)d_in[17];
    const float* ksa_w   = (const float*)d_in[18];
    const float* ksa_b   = (const float*)d_in[19];
    const float* vpost_w = (const float*)d_in[20];
    const float* vpost_gw= (const float*)d_in[21];
    const float* vpost_gb= (const float*)d_in[22];
    const float* pos_emb = (const float*)d_in[23];
    const float* outt_w  = (const float*)d_in[24];
    const float* outt_gw = (const float*)d_in[25];
    const float* outt_gb = (const float*)d_in[26];
    const float* se_w1   = (const float*)d_in[27];
    const float* se_b1   = (const float*)d_in[28];
    const float* se_w2   = (const float*)d_in[29];
    const float* se_b2   = (const float*)d_in[30];
    float* out = (float*)d_out;

    float *ht,*q,*k,*v,*av,*att,*o,*stats,*pool,*qsa,*ksa,*peN,*wT,*Pb;
    __half *wrep, *nhwc, *nhwcS;
    cudaGetSymbolAddress((void**)&ht,   g_ht);
    cudaGetSymbolAddress((void**)&q,    g_q);
    cudaGetSymbolAddress((void**)&k,    g_k);
    cudaGetSymbolAddress((void**)&v,    g_v);
    cudaGetSymbolAddress((void**)&av,   g_av);
    cudaGetSymbolAddress((void**)&att,  g_att);
    cudaGetSymbolAddress((void**)&o,    g_o);
    cudaGetSymbolAddress((void**)&stats,g_stats);
    cudaGetSymbolAddress((void**)&pool, g_pool);
    cudaGetSymbolAddress((void**)&qsa,  g_qsa);
    cudaGetSymbolAddress((void**)&ksa,  g_ksa);
    cudaGetSymbolAddress((void**)&peN,  g_peN);
    cudaGetSymbolAddress((void**)&wT,   g_wT);
    cudaGetSymbolAddress((void**)&Pb,   g_Pb);
    cudaGetSymbolAddress((void**)&wrep, g_wrep);
    cudaGetSymbolAddress((void**)&nhwc, g_nhwc);
    cudaGetSymbolAddress((void**)&nhwcS,g_nhwcS);

    // wrep offsets (halfs)
    const size_t WR_KPRE = 0;
    const size_t WR_VPRE = 589824;
    const size_t WR_QPRE = 1179648;
    const size_t WR_OUTT = 1474560;
    const size_t WR_ENC  = 2064384;

    cudaFuncSetAttribute(mmaconv_k, cudaFuncAttributeMaxDynamicSharedMemorySize, DSMEM_TOTAL);

    zero_stats_k<<<1,640>>>();
    zero_half_k<<<2048,256>>>(nhwc, ((size_t)TOTROWS*256*2)/16);
    fill_nhwc_k<<<4096,256>>>(hidden, outq);
    wrep_k<<<1152,256>>>(kpre_w, wrep + WR_KPRE, 256, 2);
    mmaconv_k<<<1280,256,DSMEM_TOTAL>>>(wrep + WR_KPRE, nhwc, nullptr, k, stats + ST_K, 2);
    wrep_k<<<1152,256>>>(vpre_w, wrep + WR_VPRE, 256, 2);
    pe_norm_k<<<8,256>>>(pos_emb, peN);
    pbconv_k<<<8,128>>>(vpre_w);
    mmaconv_k<<<1280,256,DSMEM_TOTAL>>>(wrep + WR_VPRE, nhwc, Pb, v, stats + ST_V, 2);

    zero_half_k<<<1024,256>>>(nhwcS, ((size_t)TOTROWS_S*256*2)/16);
    fill_in_k<<<512,256>>>(inputs);
    wrep_k<<<576,256>>>(enc_w,  wrep + WR_ENC,  64, 1);
    wrep_k<<<576,256>>>(qpre_w, wrep + WR_QPRE, 128, 1);
    wrep_k<<<1152,256>>>(outt_w, wrep + WR_OUTT, 192, 2);
    transw_k<<<64,256>>>(vpost_w, wT, 128, 1);

    // ht = silu(gn(mmaconv(inputs, enc_w)))
    mmaconv_k<<<160,256,DSMEM_TOTAL>>>(wrep + WR_ENC, nhwcS, nullptr, ht, stats + ST_HT, 1);
    gn_apply_k<<<2048,256>>>(ht, stats + ST_HT, enc_gw, enc_gb, BN, 1);

    // q = gn(mmaconv(ht, qpre_w)) + fused pool
    fill16_k<<<512,256>>>(ht);
    mmaconv_k<<<160,256,DSMEM_TOTAL>>>(wrep + WR_QPRE, nhwcS, nullptr, q, stats + ST_Q, 1);
    gn_apply_pool_k<<<64,256>>>(q, stats + ST_Q, qpre_gw, qpre_gb, pool);
    saconv_k<<<(BN*HWN+255)/256,256>>>(pool, qsa_w, qsa_b, qsa, BN);

    // k, v gn (k fused with pool)
    gn_apply_pool_k<<<512,256>>>(k, stats + ST_K, kpre_gw, kpre_gb, pool);
    saconv_k<<<(SBN*HWN+255)/256,256>>>(pool, ksa_w, ksa_b, ksa, SBN);
    gn_apply_k<<<4096,256>>>(v, stats + ST_V, vpre_gw, vpre_gb, SBN, 0);

    // attention
    qfg_k<<<2048,256>>>();
    sprob_k<<<SBN,256>>>();
    tlogit_k<<<SBN,256>>>();
    tprob_k<<<1,32>>>();
    av_k<<<2048,256>>>();

    // att = silu(gn(conv1x1(av))) + fused newout
    conv1x1_k<<<BN*8,256>>>(av, wT, att);
    gn_reduce_k<<<BN,256>>>(att, stats + ST_ATT);
    gn_apply_att_k<<<2048,256>>>(att, stats + ST_ATT, vpost_gw, vpost_gb, mask, out);

    // o = silu(gn(mmaconv(concat(inputs, att+ht), outt_w)))
    xcat_fill_k<<<512,256>>>(inputs);
    mmaconv_k<<<160,256,DSMEM_TOTAL>>>(wrep + WR_OUTT, nhwcS, nullptr, o, stats + ST_O, 2);
    gn_apply_k<<<2048,256>>>(o, stats + ST_O, outt_gw, outt_gb, BN, 1);

    semean_k<<<BN,256>>>();
    sefc1_k<<<1,512>>>(se_w1, se_b1);
    sefc2_k<<<8,256>>>(se_w2, se_b2);
    final_k<<<2048,256>>>(out);
}

// round 11
// speedup vs baseline: 4.3903x; 1.3694x over previous
#include <cuda_runtime.h>
#include <cuda_fp16.h>
#include <cstdint>

#define BN   16
#define CH   128
#define HWN  1024
#define SN   8
#define SBN  128
#define CHW  131072

#define GUARD   64
#define RPI     1344
#define TOTROWS   (GUARD + 128*RPI + 256)
#define TOTROWS_S (GUARD + 16*RPI + 256)

// mmaconv smem (bytes): X window 200 rows x 256B, then one A buffer 32KB (128co x 128k)
#define AB_OFF 51200
#define DSMEM_TOTAL 83968

// stats slots (2 floats per img): K=0, V=256, HT=512, Q=544, ATT=576, O=608
#define ST_K   0
#define ST_V   256
#define ST_HT  512
#define ST_Q   544
#define ST_ATT 576
#define ST_O   608

__device__ float g_ht [BN*CHW];
__device__ float g_q  [BN*CHW];
__device__ float g_k  [SBN*CHW];
__device__ float g_v  [SBN*CHW];
__device__ float g_av [BN*CHW];
__device__ float g_att[BN*CHW];
__device__ float g_o  [BN*CHW];
__device__ float g_stats[640];
__device__ float g_pool[SBN*2*HWN];
__device__ float g_qsa[BN*HWN];
__device__ float g_ksa[SBN*HWN];
__device__ float g_qfg[SN*BN*CH];
__device__ float g_sprob[SBN*HWN];
__device__ float g_tl[SN*BN];
__device__ float g_tp[SN*BN];
__device__ float g_peN[SN*2*CH];
__device__ float g_se1[BN*CH];
__device__ float g_se2[BN*32];
__device__ float g_se3[BN*CH];
__device__ float g_Pb[SN*CH*9];
__device__ float g_wT[16384];
__device__ __half g_nhwc [(size_t)TOTROWS*256];
__device__ __half g_nhwcS[(size_t)TOTROWS_S*256];
// wrep single-split: kpre(294912) | vpre(294912) | qpre(147456) | outt(294912) | enc(147456)
__device__ __half g_wrep[1179648];

__device__ __forceinline__ float sigmf(float x){ return 1.f/(1.f + __expf(-x)); }
__device__ __forceinline__ bool mask_at(const unsigned char* m, int b){
    if (m[1] != 0) return m[b] != 0;
    const unsigned int* w = (const unsigned int*)m;
    return w[b] != 0;
}

__device__ __forceinline__ uint32_t smem_u32(const void* p){
    uint32_t a;
    asm("{ .reg .u64 t; cvta.to.shared.u64 t, %1; cvt.u32.u64 %0, t; }" : "=r"(a) : "l"(p));
    return a;
}
__device__ __forceinline__ void mma16816(float* d, uint32_t a0, uint32_t a1, uint32_t a2,
                                         uint32_t a3, uint32_t b0, uint32_t b1){
    asm volatile("mma.sync.aligned.m16n8k16.row.col.f32.f16.f16.f32 "
        "{%0,%1,%2,%3}, {%4,%5,%6,%7}, {%8,%9}, {%0,%1,%2,%3};"
        : "+f"(d[0]),"+f"(d[1]),"+f"(d[2]),"+f"(d[3])
        : "r"(a0),"r"(a1),"r"(a2),"r"(a3),"r"(b0),"r"(b1));
}
__device__ __forceinline__ void ldsm4(uint32_t& r0,uint32_t& r1,uint32_t& r2,uint32_t& r3,
                                      uint32_t addr){
    asm volatile("ldmatrix.sync.aligned.m8n8.x4.shared.b16 {%0,%1,%2,%3}, [%4];"
        : "=r"(r0),"=r"(r1),"=r"(r2),"=r"(r3) : "r"(addr));
}
__device__ __forceinline__ void cpa16(uint32_t d, const void* s){
    asm volatile("cp.async.cg.shared.global [%0], [%1], 16;" :: "r"(d), "l"(s));
}
__device__ __forceinline__ void cp_commit(){ asm volatile("cp.async.commit_group;" ::: "memory"); }
__device__ __forceinline__ void cp_wait0(){ asm volatile("cp.async.wait_group 0;" ::: "memory"); }

// ---- misc small kernels ----
__global__ void zero_stats_k(){ if (threadIdx.x < 640) g_stats[threadIdx.x] = 0.f; }

__global__ void transw_k(const float* __restrict__ w, float* __restrict__ wT,
                         int cin, int ktaps)
{
    int n = cin*ktaps*128;
    for (int i = blockIdx.x*blockDim.x + threadIdx.x; i < n; i += gridDim.x*blockDim.x){
        int co = i & 127;
        int r  = i >> 7;
        int tap = r % ktaps;
        int c   = r / ktaps;
        wT[i] = w[(co*cin + c)*ktaps + tap];
    }
}

__global__ void pe_norm_k(const float* __restrict__ pe, float* __restrict__ peN)
{
    int s = blockIdx.x, t = threadIdx.x;
    float v = pe[s*256 + t];
    float q = v*v;
    #pragma unroll
    for (int o=16;o;o>>=1) q += __shfl_down_sync(0xffffffffu, q, o);
    __shared__ float a[8];
    __shared__ float fac;
    if ((t&31)==0) a[t>>5] = q;
    __syncthreads();
    if (t==0){
        float S=0.f;
        #pragma unroll
        for (int i=0;i<8;i++) S += a[i];
        float n = sqrtf(S);
        fac = fminf(1.f, 1.f/fmaxf(n, 1e-7f));
    }
    __syncthreads();
    peN[s*256 + t] = v*fac;
}

__global__ void zero_half_k(__half* buf, size_t n16)
{
    uint4 z = make_uint4(0,0,0,0);
    uint4* p = (uint4*)buf;
    for (size_t i = (size_t)blockIdx.x*blockDim.x + threadIdx.x; i < n16;
         i += (size_t)gridDim.x*blockDim.x) p[i] = z;
}

// big buffer fill: kv concat (128 imgs, 256 ch)
__global__ void fill_nhwc_k(const float* __restrict__ hid, const float* __restrict__ oq)
{
    __shared__ float s[32][257];
    int t = threadIdx.x;
    int img = blockIdx.x>>5, y = blockIdx.x&31;
    int xg = t&31, cg = t>>5;
    size_t rb = GUARD + (size_t)img*RPI + (size_t)(y+1)*34;
    #pragma unroll
    for (int cc=0; cc<32; cc++){
        int c = cc*8 + cg;
        const float* src = (c<128) ? hid + ((size_t)img*128 + c)*1024
                                   : oq  + ((size_t)img*128 + (c-128))*1024;
        s[xg][c] = src[y*32 + xg];
    }
    __syncthreads();
    #pragma unroll
    for (int xs=0; xs<32; xs++)
        g_nhwc[(rb + xs + 1)*256 + t] = __float2half(s[xs][t]);
}

// small buffer fill: inputs (ch0-63; 64-255 stay zero)
__global__ void fill_in_k(const float* __restrict__ inputs)
{
    __shared__ float s[32][65];
    int t = threadIdx.x;
    int img = blockIdx.x>>5, y = blockIdx.x&31;
    int xg = t&31, cg = t>>5;
    size_t rb = GUARD + (size_t)img*RPI + (size_t)(y+1)*34;
    #pragma unroll
    for (int cc=0; cc<8; cc++){
        int c = cc*8 + cg;
        s[xg][c] = inputs[((size_t)img*64 + c)*1024 + y*32 + xg];
    }
    __syncthreads();
    if (t < 64){
        #pragma unroll
        for (int xs=0; xs<32; xs++)
            g_nhwcS[(rb + xs + 1)*256 + t] = __float2half(s[xs][t]);
    }
}

// small buffer fill: ht (ch0-127)
__global__ void fill16_k(const float* __restrict__ src)
{
    __shared__ float s[32][129];
    int t = threadIdx.x;
    int img = blockIdx.x>>5, y = blockIdx.x&31;
    int xg = t&31, cg = t>>5;
    size_t rb = GUARD + (size_t)img*RPI + (size_t)(y+1)*34;
    #pragma unroll
    for (int cc=0; cc<16; cc++){
        int c = cc*8 + cg;
        s[xg][c] = src[((size_t)img*128 + c)*1024 + y*32 + xg];
    }
    __syncthreads();
    if (t < 128){
        #pragma unroll
        for (int xs=0; xs<32; xs++)
            g_nhwcS[(rb + xs + 1)*256 + t] = __float2half(s[xs][t]);
    }
}

// small buffer fill: concat(inputs[64], att+ht[128]) -> ch0-191
__global__ void xcat_fill_k(const float* __restrict__ inputs)
{
    __shared__ float s[32][193];
    int t = threadIdx.x;
    int img = blockIdx.x>>5, y = blockIdx.x&31;
    int xg = t&31, cg = t>>5;
    size_t rb = GUARD + (size_t)img*RPI + (size_t)(y+1)*34;
    #pragma unroll
    for (int cc=0; cc<24; cc++){
        int c = cc*8 + cg;
        float val;
        if (c < 64) val = inputs[((size_t)img*64 + c)*1024 + y*32 + xg];
        else {
            int c2 = c - 64;
            val = g_att[((size_t)img*128 + c2)*1024 + y*32 + xg]
                + g_ht [((size_t)img*128 + c2)*1024 + y*32 + xg];
        }
        s[xg][c] = val;
    }
    __syncthreads();
    if (t < 192){
        #pragma unroll
        for (int xs=0; xs<32; xs++)
            g_nhwcS[(rb + xs + 1)*256 + t] = __float2half(s[xs][t]);
    }
}

// ---- weight repack: [tap*nkc+kc][co][128k] fp16 (single split); zero-pad cin ----
__global__ void wrep_k(const float* __restrict__ w, __half* __restrict__ dst,
                       int cin, int nkc)
{
    int n = nkc*147456;
    int i = blockIdx.x*blockDim.x + threadIdx.x;
    if (i >= n) return;
    int kl = i & 127;
    int r = i >> 7;
    int co = r & 127; r >>= 7;
    int kc = r % nkc;
    int tap = r / nkc;
    int cin_idx = kc*128 + kl;
    float val = (cin_idx < cin) ? w[((size_t)co*cin + cin_idx)*9 + tap] : 0.f;
    dst[((tap*nkc+kc)*128 + co)*128 + kl] = __float2half(val);
}

// ---- pe correction with border masks ----
__global__ void pbconv_k(const float* __restrict__ w)
{
    int s = blockIdx.x, co = threadIdx.x;
    float P[9];
    #pragma unroll
    for (int tap=0;tap<9;tap++){
        float acc = 0.f;
        for (int c=0;c<256;c++)
            acc += g_peN[s*256 + c] * w[((size_t)co*256 + c)*9 + tap];
        P[tap] = acc;
    }
    #pragma unroll
    for (int yc=0;yc<3;yc++){
        #pragma unroll
        for (int xc=0;xc<3;xc++){
            float tot = 0.f;
            #pragma unroll
            for (int dy=0;dy<3;dy++){
                if ((yc==0 && dy==0) || (yc==2 && dy==2)) continue;
                float rs = P[dy*3+1];
                if (xc!=0) rs += P[dy*3+0];
                if (xc!=2) rs += P[dy*3+2];
                tot += rs;
            }
            g_Pb[(s*128+co)*9 + yc*3+xc] = tot;
        }
    }
}

// ---- per-tap MMA: single A product, full 128k ----
__device__ __forceinline__ void conv_tap(uint32_t xb, uint32_t ab, int tap,
                                         int lane, int cob, int pxb,
                                         float acc[4][4][4])
{
    const int lr  = lane & 7;
    const int hsA = lane >> 4;
    const int hsB = (lane >> 3) & 1;
    const int dy = tap/3, dx = tap - dy*3;
    const int dlt = (dy-1)*34 + (dx-1);

    uint32_t rowA[4], rsA[4];
    #pragma unroll
    for (int mi=0;mi<4;mi++){
        int r = cob + mi*16 + lr + ((lane>>3)&1)*8;
        rowA[mi] = (uint32_t)r*256u; rsA[mi] = (uint32_t)(r&7);
    }
    uint32_t rowB[2], rsB[2];
    #pragma unroll
    for (int nn=0;nn<2;nn++){
        int r = 36 + dlt + pxb + nn*16 + lr + (lane>>4)*8;
        rowB[nn] = (uint32_t)r*256u; rsB[nn] = (uint32_t)(r&7);
    }
    #pragma unroll
    for (int k8=0;k8<8;k8++){
        uint32_t a[4][4];
        #pragma unroll
        for (int mi=0;mi<4;mi++){
            uint32_t sgi = (uint32_t)(k8*2 + hsA);
            ldsm4(a[mi][0],a[mi][1],a[mi][2],a[mi][3],
                  ab + rowA[mi] + ((sgi ^ rsA[mi])<<4));
        }
        #pragma unroll
        for (int nn=0;nn<2;nn++){
            uint32_t sgi = (uint32_t)(k8*2 + hsB);
            uint32_t b0,b1,b2,b3;
            ldsm4(b0,b1,b2,b3, xb + rowB[nn] + ((sgi ^ rsB[nn])<<4));
            #pragma unroll
            for (int mi=0;mi<4;mi++){
                mma16816(acc[mi][2*nn],   a[mi][0],a[mi][1],a[mi][2],a[mi][3], b0,b1);
                mma16816(acc[mi][2*nn+1], a[mi][0],a[mi][1],a[mi][2],a[mi][3], b2,b3);
            }
        }
    }
}

// ---- mma.sync fp16 implicit conv: D[128co,128px], 2 CTAs/SM, fused GN sums ----
__global__ __launch_bounds__(256,2)
void mmaconv_k(const __half* __restrict__ wrep,
               const __half* __restrict__ nhwc,
               const float* __restrict__ Pb,
               float* __restrict__ dst,
               float* __restrict__ stats, int nkc)
{
    extern __shared__ char dsm[];
    const uint32_t sb = smem_u32(dsm);
    const uint32_t XB = sb;
    const uint32_t AB = sb + AB_OFF;
    const int t = threadIdx.x;
    const int wid = t>>5, lane = t&31;
    const int img = blockIdx.x/10;
    const int p0  = (blockIdx.x%10)*128;
    const int s   = img>>4;
    const int cob = (wid&1)*64;
    const int pxb = (wid>>1)*32;

    float acc[4][4][4];
    #pragma unroll
    for (int mi=0;mi<4;mi++)
    #pragma unroll
    for (int ni=0;ni<4;ni++)
    #pragma unroll
    for (int e=0;e<4;e++) acc[mi][ni][e]=0.f;

    for (int kc=0; kc<nkc; kc++){
        // stage X window: 200 rows x 128k fp16 (one kc half)
        {
            const char* src = (const char*)nhwc
                + ((size_t)GUARD + (size_t)img*RPI + p0 - 36)*512 + kc*256;
            #pragma unroll
            for (int j=0;j<13;j++){
                int i = j*256 + t;
                if (i < 3200){
                    uint32_t r = (uint32_t)(i>>4), sg = (uint32_t)(i&15);
                    cpa16(XB + r*256 + ((sg^(r&7))<<4), src + (size_t)r*512 + sg*16);
                }
            }
            cp_commit();
        }
        for (int tap=0; tap<9; tap++){
            // stage A: 128co x 128k fp16 = 32KB
            const char* asrc = (const char*)(wrep + (size_t)(tap*nkc+kc)*16384);
            #pragma unroll
            for (int j=0;j<8;j++){
                int i = j*256 + t;
                uint32_t r = (uint32_t)(i>>4), sg = (uint32_t)(i&15);
                cpa16(AB + r*256 + ((sg^(r&7))<<4), asrc + (size_t)i*16);
            }
            cp_commit(); cp_wait0(); __syncthreads();
            conv_tap(XB, AB, tap, lane, cob, pxb, acc);
            __syncthreads();
        }
    }

    // epilogue: stores + local GN partial sums
    const int g  = lane>>2;
    const int t2 = (lane&3)*2;
    float sm_=0.f, sq_=0.f;
    #pragma unroll
    for (int mi=0;mi<4;mi++){
        #pragma unroll
        for (int n8=0;n8<4;n8++){
            #pragma unroll
            for (int e=0;e<4;e++){
                int co  = cob + mi*16 + g + ((e>>1)<<3);
                int col = pxb + n8*8 + t2 + (e&1);
                int pp  = p0 + col;
                int q34 = pp/34;
                int yy  = q34 - 1;
                int xx  = pp - q34*34 - 1;
                if ((unsigned)yy < 32u && (unsigned)xx < 32u){
                    float v = acc[mi][n8][e];
                    if (Pb){
                        int yc = (yy==0)?0:((yy==31)?2:1);
                        int xc = (xx==0)?0:((xx==31)?2:1);
                        v += Pb[(s*128+co)*9 + yc*3+xc];
                    }
                    dst[((size_t)img*128+co)*1024 + (yy<<5)+xx] = v;
                    sm_ += v; sq_ += v*v;
                }
            }
        }
    }
    #pragma unroll
    for (int o=16;o;o>>=1){
        sm_ += __shfl_down_sync(0xffffffffu, sm_, o);
        sq_ += __shfl_down_sync(0xffffffffu, sq_, o);
    }
    float* red = (float*)dsm;
    __syncthreads();
    if (lane==0){ red[wid*2] = sm_; red[wid*2+1] = sq_; }
    __syncthreads();
    if (t==0){
        float S=0.f, S2=0.f;
        #pragma unroll
        for (int w=0;w<8;w++){ S += red[w*2]; S2 += red[w*2+1]; }
        atomicAdd(&stats[img*2],   S);
        atomicAdd(&stats[img*2+1], S2);
    }
}

// ---- 1x1 conv (vpost) ----
__global__ __launch_bounds__(256,2)
void conv1x1_k(const float* __restrict__ src, const float* __restrict__ wT,
               float* __restrict__ dst)
{
    __shared__ float sIn[8*128];
    __shared__ float sW [8*128];
    const int t   = threadIdx.x;
    const int img = blockIdx.x >> 3;
    const int p0  = (blockIdx.x & 7) << 7;
    const int xl  = t & 31;
    const int cg  = t >> 5;
    float acc[64];
    #pragma unroll
    for (int i=0;i<64;i++) acc[i]=0.f;

    for (int cc=0; cc<16; cc++){
        for (int e=t; e<1024; e+=256){
            int ci = e>>7, i = e&127;
            sIn[e] = src[((size_t)img*128 + (cc<<3)+ci)*1024 + p0 + i];
            sW [e] = wT[(cc<<10) + e];
        }
        __syncthreads();
        #pragma unroll
        for (int ci=0;ci<8;ci++){
            float inr[4];
            #pragma unroll
            for (int y=0;y<4;y++) inr[y] = sIn[ci*128 + (y<<5) + xl];
            const float4* wq = (const float4*)&sW[ci*128 + (cg<<4)];
            float4 w0=wq[0], w1=wq[1], w2=wq[2], w3=wq[3];
            #pragma unroll
            for (int y=0;y<4;y++){
                float iv = inr[y];
                float* a = &acc[y*16];
                a[0]+=iv*w0.x; a[1]+=iv*w0.y; a[2]+=iv*w0.z; a[3]+=iv*w0.w;
                a[4]+=iv*w1.x; a[5]+=iv*w1.y; a[6]+=iv*w1.z; a[7]+=iv*w1.w;
                a[8]+=iv*w2.x; a[9]+=iv*w2.y; a[10]+=iv*w2.z; a[11]+=iv*w2.w;
                a[12]+=iv*w3.x; a[13]+=iv*w3.y; a[14]+=iv*w3.z; a[15]+=iv*w3.w;
            }
        }
        __syncthreads();
    }
    #pragma unroll
    for (int j=0;j<16;j++){
        int co = (cg<<4)+j;
        #pragma unroll
        for (int y=0;y<4;y++)
            dst[((size_t)img*128+co)*1024 + p0 + (y<<5) + xl] = acc[y*16+j];
    }
}

// ---- GN reduce (att only): raw sums ----
__global__ void gn_reduce_k(const float* __restrict__ x, float* __restrict__ stats)
{
    const int img = blockIdx.x;
    const float4* p = (const float4*)(x + (size_t)img*CHW);
    float s=0.f, s2=0.f;
    for (int i=threadIdx.x; i<32768; i+=blockDim.x){
        float4 v = p[i];
        s  += v.x+v.y+v.z+v.w;
        s2 += v.x*v.x+v.y*v.y+v.z*v.z+v.w*v.w;
    }
    #pragma unroll
    for (int o=16;o;o>>=1){
        s  += __shfl_down_sync(0xffffffffu, s , o);
        s2 += __shfl_down_sync(0xffffffffu, s2, o);
    }
    __shared__ float sa[8], sb[8];
    if ((threadIdx.x&31)==0){ sa[threadIdx.x>>5]=s; sb[threadIdx.x>>5]=s2; }
    __syncthreads();
    if (threadIdx.x==0){
        float S=0.f, S2=0.f;
        #pragma unroll
        for (int i=0;i<8;i++){ S+=sa[i]; S2+=sb[i]; }
        stats[img*2]   = S;
        stats[img*2+1] = S2;
    }
}

// ---- GN apply from raw sums ----
__global__ void gn_apply_k(float* __restrict__ x, const float* __restrict__ stats,
                           const float* __restrict__ gw, const float* __restrict__ gb,
                           int nimg, int act)
{
    int n4 = nimg*32768;
    for (int i = blockIdx.x*blockDim.x + threadIdx.x; i < n4; i += gridDim.x*blockDim.x){
        int base = i<<2;
        int img = base>>17; int c = (base>>10)&127;
        float sum = stats[2*img], ssq = stats[2*img+1];
        float mu = sum*(1.f/131072.f);
        float rs = rsqrtf(ssq*(1.f/131072.f) - mu*mu + 1e-5f);
        float sc = rs*gw[c];
        float sh = gb[c] - mu*sc;
        float4 v = ((float4*)x)[i];
        v.x = v.x*sc+sh; v.y = v.y*sc+sh; v.z = v.z*sc+sh; v.w = v.w*sc+sh;
        if (act){
            v.x *= sigmf(v.x); v.y *= sigmf(v.y); v.z *= sigmf(v.z); v.w *= sigmf(v.w);
        }
        ((float4*)x)[i] = v;
    }
}

// ---- GN apply + channel mean/max pool fused (k, q) ----
__global__ void gn_apply_pool_k(float* __restrict__ x, const float* __restrict__ stats,
                                const float* __restrict__ gw, const float* __restrict__ gb,
                                float* __restrict__ pool)
{
    __shared__ float sc[128], sh[128];
    int t = threadIdx.x;
    int img = blockIdx.x>>2;
    int p = ((blockIdx.x&3)<<8) + t;
    if (t < 128){
        float sum = stats[2*img], ssq = stats[2*img+1];
        float mu = sum*(1.f/131072.f);
        float rs = rsqrtf(ssq*(1.f/131072.f) - mu*mu + 1e-5f);
        float scv = rs*gw[t];
        sc[t] = scv; sh[t] = gb[t] - mu*scv;
    }
    __syncthreads();
    float* base = x + (size_t)img*CHW + p;
    float s = 0.f, m = -3.402823466e38f;
    #pragma unroll 4
    for (int c=0;c<128;c++){
        float y = base[(size_t)c<<10]*sc[c] + sh[c];
        base[(size_t)c<<10] = y;
        s += y; m = fmaxf(m, y);
    }
    pool[img*2048 + p]        = s*(1.f/128.f);
    pool[img*2048 + 1024 + p] = m;
}

// ---- GN apply att (silu) + newout write fused ----
__global__ void gn_apply_att_k(float* __restrict__ x, const float* __restrict__ stats,
                               const float* __restrict__ gw, const float* __restrict__ gb,
                               const unsigned char* __restrict__ mask,
                               float* __restrict__ out)
{
    int i = blockIdx.x*blockDim.x + threadIdx.x;
    if (i >= BN*32768) return;
    int base = i<<2;
    int img = base>>17; int c = (base>>10)&127;
    float sum = stats[2*img], ssq = stats[2*img+1];
    float mu = sum*(1.f/131072.f);
    float rs = rsqrtf(ssq*(1.f/131072.f) - mu*mu + 1e-5f);
    float sc = rs*gw[c];
    float sh = gb[c] - mu*sc;
    float4 v = ((float4*)x)[i];
    v.x = v.x*sc+sh; v.y = v.y*sc+sh; v.z = v.z*sc+sh; v.w = v.w*sc+sh;
    v.x *= sigmf(v.x); v.y *= sigmf(v.y); v.z *= sigmf(v.z); v.w *= sigmf(v.w);
    ((float4*)x)[i] = v;
    float4 z = mask_at(mask, img) ? v : make_float4(0.f,0.f,0.f,0.f);
    *(float4*)&out[(size_t)2*BN*CHW + base] = z;
}

// ---- 2->1 3x3 conv + sigmoid ----
__global__ void saconv_k(const float* __restrict__ pool, const float* __restrict__ w,
                         const float* __restrict__ b, float* __restrict__ sa, int nimg)
{
    int i = blockIdx.x*blockDim.x + threadIdx.x;
    if (i >= nimg*HWN) return;
    int img = i>>10, p = i&1023, y = p>>5, x = p&31;
    float acc = b[0];
    #pragma unroll
    for (int c2=0;c2<2;c2++)
    #pragma unroll
    for (int dy=-1;dy<=1;dy++)
    #pragma unroll
    for (int dx=-1;dx<=1;dx++){
        int yy=y+dy, xx=x+dx;
        if ((unsigned)yy<32u && (unsigned)xx<32u)
            acc += pool[img*2048 + c2*1024 + (yy<<5)+xx] * w[c2*9 + (dy+1)*3 + (dx+1)];
    }
    sa[i] = sigmf(acc);
}

// ---- attention pieces ----
__global__ void qfg_k()
{
    int wid  = (blockIdx.x*blockDim.x + threadIdx.x) >> 5;
    int lane = threadIdx.x & 31;
    if (wid >= SN*BN*CH) return;
    int c = wid & 127, b = (wid>>7)&15, s = wid>>11;
    const float* qp = g_q   + ((size_t)b*128 + c)*1024;
    const float* kp = g_ksa + (size_t)(s*16+b)*1024;
    float acc = 0.f;
    for (int p=lane; p<1024; p+=32) acc += qp[p]*kp[p];
    #pragma unroll
    for (int o=16;o;o>>=1) acc += __shfl_down_sync(0xffffffffu, acc, o);
    if (!lane) g_qfg[wid] = acc*(1.f/1024.f);
}

__global__ void sprob_k()
{
    int img = blockIdx.x;
    __shared__ float fq[128];
    int t = threadIdx.x;
    if (t < 128) fq[t] = g_qfg[img*128 + t];
    __syncthreads();
    for (int p=t; p<1024; p+=256){
        const float* kp = g_k + (size_t)img*CHW + p;
        float acc = 0.f;
        #pragma unroll 4
        for (int c=0;c<128;c++) acc += fq[c]*kp[(size_t)c<<10];
        g_sprob[img*1024 + p] = sigmf(acc);
    }
}

__global__ void tlogit_k()
{
    int img = blockIdx.x, b = img & 15;
    float acc = 0.f;
    for (int i=threadIdx.x; i<CHW; i+=256){
        int p = i & 1023;
        acc += g_q[(size_t)b*CHW + i]*g_qsa[b*1024+p]
             * g_k[(size_t)img*CHW + i]*g_ksa[img*1024+p];
    }
    #pragma unroll
    for (int o=16;o;o>>=1) acc += __shfl_down_sync(0xffffffffu, acc, o);
    __shared__ float sh[8];
    if ((threadIdx.x&31)==0) sh[threadIdx.x>>5] = acc;
    __syncthreads();
    if (threadIdx.x==0){
        float S=0.f;
        #pragma unroll
        for (int i=0;i<8;i++) S += sh[i];
        g_tl[img] = S * rsqrtf(131072.f);
    }
}

__global__ void tprob_k()
{
    int b = threadIdx.x;
    if (b >= 16) return;
    float m = -3.402823466e38f;
    #pragma unroll
    for (int s=0;s<8;s++) m = fmaxf(m, g_tl[s*16+b]);
    float e[8]; float sum = 0.f;
    #pragma unroll
    for (int s=0;s<8;s++){ e[s] = __expf(g_tl[s*16+b] - m); sum += e[s]; }
    float inv = 1.f/sum;
    #pragma unroll
    for (int s=0;s<8;s++) g_tp[s*16+b] = e[s]*inv;
}

__global__ void av_k()
{
    int i = blockIdx.x*blockDim.x + threadIdx.x;
    if (i >= BN*CHW/4) return;
    int base = i<<2;
    int b = base>>17; int c = (base>>10)&127; int p = base&1023;
    float4 acc = make_float4(0.f,0.f,0.f,0.f);
    #pragma unroll
    for (int s=0;s<8;s++){
        int img = s*16 + b;
        float tw = g_tp[img];
        float4 sp = *(const float4*)&g_sprob[img*1024 + p];
        float4 vv = *(const float4*)&g_v[((size_t)img*128 + c)*1024 + p];
        acc.x += tw*sp.x*vv.x; acc.y += tw*sp.y*vv.y;
        acc.z += tw*sp.z*vv.z; acc.w += tw*sp.w*vv.w;
    }
    *(float4*)&g_av[base] = acc;
}

__global__ void semean_k()
{
    int b = blockIdx.x;
    int w = threadIdx.x>>5, lane = threadIdx.x&31;
    for (int c=w; c<128; c+=8){
        const float* p = g_o + ((size_t)b*128 + c)*1024;
        float s = 0.f;
        for (int i=lane; i<1024; i+=32) s += p[i];
        #pragma unroll
        for (int o=16;o;o>>=1) s += __shfl_down_sync(0xffffffffu, s, o);
        if (!lane) g_se1[b*128+c] = s*(1.f/1024.f);
    }
}

__global__ void sefc1_k(const float* __restrict__ w1, const float* __restrict__ b1)
{
    int t = threadIdx.x;
    int b = t>>5, j = t&31;
    float acc = b1[j];
    #pragma unroll 4
    for (int c=0;c<128;c++) acc += g_se1[b*128+c]*w1[j*128+c];
    g_se2[b*32+j] = fmaxf(acc, 0.f);
}

__global__ void sefc2_k(const float* __restrict__ w2, const float* __restrict__ b2)
{
    int i = blockIdx.x*blockDim.x + threadIdx.x;
    if (i >= BN*CH) return;
    int b = i>>7, c = i&127;
    float acc = b2[c];
    #pragma unroll
    for (int j=0;j<32;j++) acc += g_se2[b*32+j]*w2[c*32+j];
    g_se3[i] = sigmf(acc);
}

__global__ void final_k(float* __restrict__ out)
{
    int i = blockIdx.x*blockDim.x + threadIdx.x;
    if (i >= BN*CHW/4) return;
    int base = i<<2;
    int b = base>>17; int c = (base>>10)&127;
    float g = 1.f + g_se3[b*128+c];
    float4 o4 = *(const float4*)&g_o[base];
    o4.x*=g; o4.y*=g; o4.z*=g; o4.w*=g;
    *(float4*)&out[base] = o4;
    *(float4*)&out[(size_t)BN*CHW + base] = *(const float4*)&g_ht[base];
}

// ---- host launcher ----
extern "C" void kernel_launch(void* const* d_in, const int* in_sizes, int n_in,
                              void* d_out, int out_size)
{
    (void)in_sizes; (void)n_in; (void)out_size;
    const float* inputs  = (const float*)d_in[0];
    const float* hidden  = (const float*)d_in[1];
    const float* outq    = (const float*)d_in[2];
    const unsigned char* mask = (const unsigned char*)d_in[3];
    const float* enc_w   = (const float*)d_in[4];
    const float* enc_gw  = (const float*)d_in[5];
    const float* enc_gb  = (const float*)d_in[6];
    const float* qpre_w  = (const float*)d_in[7];
    const float* qpre_gw = (const float*)d_in[8];
    const float* qpre_gb = (const float*)d_in[9];
    const float* kpre_w  = (const float*)d_in[10];
    const float* kpre_gw = (const float*)d_in[11];
    const float* kpre_gb = (const float*)d_in[12];
    const float* vpre_w  = (const float*)d_in[13];
    const float* vpre_gw = (const float*)d_in[14];
    const float* vpre_gb = (const float*)d_in[15];
    const float* qsa_w   = (const float*)d_in[16];
    const float* qsa_b   = (const float*)d_in[17];
    const float* ksa_w   = (const float*)d_in[18];
    const float* ksa_b   = (const float*)d_in[19];
    const float* vpost_w = (const float*)d_in[20];
    const float* vpost_gw= (const float*)d_in[21];
    const float* vpost_gb= (const float*)d_in[22];
    const float* pos_emb = (const float*)d_in[23];
    const float* outt_w  = (const float*)d_in[24];
    const float* outt_gw = (const float*)d_in[25];
    const float* outt_gb = (const float*)d_in[26];
    const float* se_w1   = (const float*)d_in[27];
    const float* se_b1   = (const float*)d_in[28];
    const float* se_w2   = (const float*)d_in[29];
    const float* se_b2   = (const float*)d_in[30];
    float* out = (float*)d_out;

    float *ht,*q,*k,*v,*av,*att,*o,*stats,*pool,*qsa,*ksa,*peN,*wT,*Pb;
    __half *wrep, *nhwc, *nhwcS;
    cudaGetSymbolAddress((void**)&ht,   g_ht);
    cudaGetSymbolAddress((void**)&q,    g_q);
    cudaGetSymbolAddress((void**)&k,    g_k);
    cudaGetSymbolAddress((void**)&v,    g_v);
    cudaGetSymbolAddress((void**)&av,   g_av);
    cudaGetSymbolAddress((void**)&att,  g_att);
    cudaGetSymbolAddress((void**)&o,    g_o);
    cudaGetSymbolAddress((void**)&stats,g_stats);
    cudaGetSymbolAddress((void**)&pool, g_pool);
    cudaGetSymbolAddress((void**)&qsa,  g_qsa);
    cudaGetSymbolAddress((void**)&ksa,  g_ksa);
    cudaGetSymbolAddress((void**)&peN,  g_peN);
    cudaGetSymbolAddress((void**)&wT,   g_wT);
    cudaGetSymbolAddress((void**)&Pb,   g_Pb);
    cudaGetSymbolAddress((void**)&wrep, g_wrep);
    cudaGetSymbolAddress((void**)&nhwc, g_nhwc);
    cudaGetSymbolAddress((void**)&nhwcS,g_nhwcS);

    // wrep offsets (halfs), single-split
    const size_t WR_KPRE = 0;
    const size_t WR_VPRE = 294912;
    const size_t WR_QPRE = 589824;
    const size_t WR_OUTT = 737280;
    const size_t WR_ENC  = 1032192;

    cudaFuncSetAttribute(mmaconv_k, cudaFuncAttributeMaxDynamicSharedMemorySize, DSMEM_TOTAL);

    zero_stats_k<<<1,640>>>();
    zero_half_k<<<2048,256>>>(nhwc, ((size_t)TOTROWS*256*2)/16);
    fill_nhwc_k<<<4096,256>>>(hidden, outq);
    wrep_k<<<1152,256>>>(kpre_w, wrep + WR_KPRE, 256, 2);
    mmaconv_k<<<1280,256,DSMEM_TOTAL>>>(wrep + WR_KPRE, nhwc, nullptr, k, stats + ST_K, 2);
    wrep_k<<<1152,256>>>(vpre_w, wrep + WR_VPRE, 256, 2);
    pe_norm_k<<<8,256>>>(pos_emb, peN);
    pbconv_k<<<8,128>>>(vpre_w);
    mmaconv_k<<<1280,256,DSMEM_TOTAL>>>(wrep + WR_VPRE, nhwc, Pb, v, stats + ST_V, 2);

    zero_half_k<<<1024,256>>>(nhwcS, ((size_t)TOTROWS_S*256*2)/16);
    fill_in_k<<<512,256>>>(inputs);
    wrep_k<<<576,256>>>(enc_w,  wrep + WR_ENC,  64, 1);
    wrep_k<<<576,256>>>(qpre_w, wrep + WR_QPRE, 128, 1);
    wrep_k<<<1152,256>>>(outt_w, wrep + WR_OUTT, 192, 2);
    transw_k<<<64,256>>>(vpost_w, wT, 128, 1);

    // ht = silu(gn(mmaconv(inputs, enc_w)))
    mmaconv_k<<<160,256,DSMEM_TOTAL>>>(wrep + WR_ENC, nhwcS, nullptr, ht, stats + ST_HT, 1);
    gn_apply_k<<<2048,256>>>(ht, stats + ST_HT, enc_gw, enc_gb, BN, 1);

    // q = gn(mmaconv(ht, qpre_w)) + fused pool
    fill16_k<<<512,256>>>(ht);
    mmaconv_k<<<160,256,DSMEM_TOTAL>>>(wrep + WR_QPRE, nhwcS, nullptr, q, stats + ST_Q, 1);
    gn_apply_pool_k<<<64,256>>>(q, stats + ST_Q, qpre_gw, qpre_gb, pool);
    saconv_k<<<(BN*HWN+255)/256,256>>>(pool, qsa_w, qsa_b, qsa, BN);

    // k, v gn (k fused with pool)
    gn_apply_pool_k<<<512,256>>>(k, stats + ST_K, kpre_gw, kpre_gb, pool);
    saconv_k<<<(SBN*HWN+255)/256,256>>>(pool, ksa_w, ksa_b, ksa, SBN);
    gn_apply_k<<<4096,256>>>(v, stats + ST_V, vpre_gw, vpre_gb, SBN, 0);

    // attention
    qfg_k<<<2048,256>>>();
    sprob_k<<<SBN,256>>>();
    tlogit_k<<<SBN,256>>>();
    tprob_k<<<1,32>>>();
    av_k<<<2048,256>>>();

    // att = silu(gn(conv1x1(av))) + fused newout
    conv1x1_k<<<BN*8,256>>>(av, wT, att);
    gn_reduce_k<<<BN,256>>>(att, stats + ST_ATT);
    gn_apply_att_k<<<2048,256>>>(att, stats + ST_ATT, vpost_gw, vpost_gb, mask, out);

    // o = silu(gn(mmaconv(concat(inputs, att+ht), outt_w)))
    xcat_fill_k<<<512,256>>>(inputs);
    mmaconv_k<<<160,256,DSMEM_TOTAL>>>(wrep + WR_OUTT, nhwcS, nullptr, o, stats + ST_O, 2);
    gn_apply_k<<<2048,256>>>(o, stats + ST_O, outt_gw, outt_gb, BN, 1);

    semean_k<<<BN,256>>>();
    sefc1_k<<<1,512>>>(se_w1, se_b1);
    sefc2_k<<<8,256>>>(se_w2, se_b2);
    final_k<<<2048,256>>>(out);
}

// round 12
// speedup vs baseline: 5.1458x; 1.1721x over previous
#include <cuda_runtime.h>
#include <cuda_fp16.h>
#include <cstdint>

#define BN   16
#define CH   128
#define HWN  1024
#define SN   8
#define SBN  128
#define CHW  131072

#define GUARD   64
#define RPI     1344
#define TOTROWS   (GUARD + 128*RPI + 256)
#define TOTROWS_S (GUARD + 16*RPI + 256)

// mmaconv smem (bytes): X window 200 rows x 256B, then one A buffer 32KB
#define AB_OFF 51200
#define DSMEM_TOTAL 83968

// stats slots (2 floats per img): K=0, V=256, HT=512, Q=544, ATT=576, O=608
#define ST_K   0
#define ST_V   256
#define ST_HT  512
#define ST_Q   544
#define ST_ATT 576
#define ST_O   608

__device__ float g_ht [BN*CHW];
__device__ float g_q  [BN*CHW];
__device__ float g_k  [SBN*CHW];
__device__ float g_v  [SBN*CHW];
__device__ float g_att[BN*CHW];
__device__ float g_o  [BN*CHW];
__device__ float g_stats[640];
__device__ float g_pool[SBN*2*HWN];
__device__ float g_qsa[BN*HWN];
__device__ float g_ksa[SBN*HWN];
__device__ float g_qfg[SN*BN*CH];
__device__ float g_sprob[SBN*HWN];
__device__ float g_tl[SN*BN];
__device__ float g_tp[SN*BN];
__device__ float g_peN[SN*2*CH];
__device__ float g_se3[BN*CH];
__device__ float g_Pb[SN*CH*9];
__device__ __half g_nhwc [(size_t)TOTROWS*256];
__device__ __half g_nhwcS[(size_t)TOTROWS_S*256];
// wrep single-split: kpre(294912)|vpre(294912)|qpre(147456)|outt(294912)|enc(147456)|vpost(16384)
__device__ __half g_wrep[1196032];

__device__ __forceinline__ float sigmf(float x){ return 1.f/(1.f + __expf(-x)); }
__device__ __forceinline__ bool mask_at(const unsigned char* m, int b){
    if (m[1] != 0) return m[b] != 0;
    const unsigned int* w = (const unsigned int*)m;
    return w[b] != 0;
}

__device__ __forceinline__ uint32_t smem_u32(const void* p){
    uint32_t a;
    asm("{ .reg .u64 t; cvta.to.shared.u64 t, %1; cvt.u32.u64 %0, t; }" : "=r"(a) : "l"(p));
    return a;
}
__device__ __forceinline__ void mma16816(float* d, uint32_t a0, uint32_t a1, uint32_t a2,
                                         uint32_t a3, uint32_t b0, uint32_t b1){
    asm volatile("mma.sync.aligned.m16n8k16.row.col.f32.f16.f16.f32 "
        "{%0,%1,%2,%3}, {%4,%5,%6,%7}, {%8,%9}, {%0,%1,%2,%3};"
        : "+f"(d[0]),"+f"(d[1]),"+f"(d[2]),"+f"(d[3])
        : "r"(a0),"r"(a1),"r"(a2),"r"(a3),"r"(b0),"r"(b1));
}
__device__ __forceinline__ void ldsm4(uint32_t& r0,uint32_t& r1,uint32_t& r2,uint32_t& r3,
                                      uint32_t addr){
    asm volatile("ldmatrix.sync.aligned.m8n8.x4.shared.b16 {%0,%1,%2,%3}, [%4];"
        : "=r"(r0),"=r"(r1),"=r"(r2),"=r"(r3) : "r"(addr));
}
__device__ __forceinline__ void cpa16(uint32_t d, const void* s){
    asm volatile("cp.async.cg.shared.global [%0], [%1], 16;" :: "r"(d), "l"(s));
}
__device__ __forceinline__ void cp_commit(){ asm volatile("cp.async.commit_group;" ::: "memory"); }
__device__ __forceinline__ void cp_wait0(){ asm volatile("cp.async.wait_group 0;" ::: "memory"); }

// ---- zero stats + t-logits every launch (atomics accumulate otherwise) ----
__global__ void zero_stats_k(){
    int t = threadIdx.x;
    if (t < 640) g_stats[t] = 0.f;
    else if (t < 768) g_tl[t-640] = 0.f;
}

__global__ void pe_norm_k(const float* __restrict__ pe, float* __restrict__ peN)
{
    int s = blockIdx.x, t = threadIdx.x;
    float v = pe[s*256 + t];
    float q = v*v;
    #pragma unroll
    for (int o=16;o;o>>=1) q += __shfl_down_sync(0xffffffffu, q, o);
    __shared__ float a[8];
    __shared__ float fac;
    if ((t&31)==0) a[t>>5] = q;
    __syncthreads();
    if (t==0){
        float S=0.f;
        #pragma unroll
        for (int i=0;i<8;i++) S += a[i];
        float n = sqrtf(S);
        fac = fminf(1.f, 1.f/fmaxf(n, 1e-7f));
    }
    __syncthreads();
    peN[s*256 + t] = v*fac;
}

// big buffer fill: kv concat (128 imgs, 256 ch)
__global__ void fill_nhwc_k(const float* __restrict__ hid, const float* __restrict__ oq)
{
    __shared__ float s[32][257];
    int t = threadIdx.x;
    int img = blockIdx.x>>5, y = blockIdx.x&31;
    int xg = t&31, cg = t>>5;
    size_t rb = GUARD + (size_t)img*RPI + (size_t)(y+1)*34;
    #pragma unroll
    for (int cc=0; cc<32; cc++){
        int c = cc*8 + cg;
        const float* src = (c<128) ? hid + ((size_t)img*128 + c)*1024
                                   : oq  + ((size_t)img*128 + (c-128))*1024;
        s[xg][c] = src[y*32 + xg];
    }
    __syncthreads();
    #pragma unroll
    for (int xs=0; xs<32; xs++)
        g_nhwc[(rb + xs + 1)*256 + t] = __float2half(s[xs][t]);
}

// small buffer fill: inputs (ch0-63)
__global__ void fill_in_k(const float* __restrict__ inputs)
{
    __shared__ float s[32][65];
    int t = threadIdx.x;
    int img = blockIdx.x>>5, y = blockIdx.x&31;
    int xg = t&31, cg = t>>5;
    size_t rb = GUARD + (size_t)img*RPI + (size_t)(y+1)*34;
    #pragma unroll
    for (int cc=0; cc<8; cc++){
        int c = cc*8 + cg;
        s[xg][c] = inputs[((size_t)img*64 + c)*1024 + y*32 + xg];
    }
    __syncthreads();
    if (t < 64){
        #pragma unroll
        for (int xs=0; xs<32; xs++)
            g_nhwcS[(rb + xs + 1)*256 + t] = __float2half(s[xs][t]);
    }
}

// gn(ht)+silu applied in place AND written as fp16 NHWC (ch0-127)
__global__ void gn_ht_fill_k(const float* __restrict__ gw, const float* __restrict__ gb)
{
    __shared__ float sm[32][129];
    __shared__ float sc[128], sh[128];
    int t = threadIdx.x;
    int img = blockIdx.x>>5, y = blockIdx.x&31;
    int xg = t&31, cg = t>>5;
    if (t < 128){
        float sum = g_stats[ST_HT+2*img], ssq = g_stats[ST_HT+2*img+1];
        float mu = sum*(1.f/131072.f);
        float rs = rsqrtf(ssq*(1.f/131072.f) - mu*mu + 1e-5f);
        float s_ = rs*gw[t];
        sc[t] = s_; sh[t] = gb[t] - mu*s_;
    }
    __syncthreads();
    int p = y*32 + xg;
    #pragma unroll
    for (int cc=0; cc<16; cc++){
        int c = cc*8 + cg;
        float v = g_ht[((size_t)img*128 + c)*1024 + p];
        v = v*sc[c] + sh[c];
        v *= sigmf(v);
        g_ht[((size_t)img*128 + c)*1024 + p] = v;
        sm[xg][c] = v;
    }
    __syncthreads();
    size_t rb = GUARD + (size_t)img*RPI + (size_t)(y+1)*34;
    if (t < 128){
        #pragma unroll
        for (int xs=0; xs<32; xs++)
            g_nhwcS[(rb + xs + 1)*256 + t] = __float2half(sm[xs][t]);
    }
}

// small buffer fill: concat(inputs[64], att+ht[128]) -> ch0-191
__global__ void xcat_fill_k(const float* __restrict__ inputs)
{
    __shared__ float s[32][193];
    int t = threadIdx.x;
    int img = blockIdx.x>>5, y = blockIdx.x&31;
    int xg = t&31, cg = t>>5;
    size_t rb = GUARD + (size_t)img*RPI + (size_t)(y+1)*34;
    #pragma unroll
    for (int cc=0; cc<24; cc++){
        int c = cc*8 + cg;
        float val;
        if (c < 64) val = inputs[((size_t)img*64 + c)*1024 + y*32 + xg];
        else {
            int c2 = c - 64;
            val = g_att[((size_t)img*128 + c2)*1024 + y*32 + xg]
                + g_ht [((size_t)img*128 + c2)*1024 + y*32 + xg];
        }
        s[xg][c] = val;
    }
    __syncthreads();
    if (t < 192){
        #pragma unroll
        for (int xs=0; xs<32; xs++)
            g_nhwcS[(rb + xs + 1)*256 + t] = __float2half(s[xs][t]);
    }
}

// ---- weight repack: [tap*nkc+kc][co][128k] fp16 single split; zero-pad cin ----
__global__ void wrep_k(const float* __restrict__ w, __half* __restrict__ dst,
                       int cin, int nkc)
{
    int n = nkc*147456;
    int i = blockIdx.x*blockDim.x + threadIdx.x;
    if (i >= n) return;
    int kl = i & 127;
    int r = i >> 7;
    int co = r & 127; r >>= 7;
    int kc = r % nkc;
    int tap = r / nkc;
    int cin_idx = kc*128 + kl;
    float val = (cin_idx < cin) ? w[((size_t)co*cin + cin_idx)*9 + tap] : 0.f;
    dst[((tap*nkc+kc)*128 + co)*128 + kl] = __float2half(val);
}

// ---- 1x1 weight repack (vpost): plain [co][128k] tile ----
__global__ void wrep1x1_k(const float* __restrict__ w, __half* __restrict__ dst)
{
    int i = blockIdx.x*blockDim.x + threadIdx.x;
    if (i < 16384) dst[i] = __float2half(w[i]);
}

// ---- pe correction with border masks ----
__global__ void pbconv_k(const float* __restrict__ w)
{
    int s = blockIdx.x, co = threadIdx.x;
    float P[9];
    #pragma unroll
    for (int tap=0;tap<9;tap++){
        float acc = 0.f;
        for (int c=0;c<256;c++)
            acc += g_peN[s*256 + c] * w[((size_t)co*256 + c)*9 + tap];
        P[tap] = acc;
    }
    #pragma unroll
    for (int yc=0;yc<3;yc++){
        #pragma unroll
        for (int xc=0;xc<3;xc++){
            float tot = 0.f;
            #pragma unroll
            for (int dy=0;dy<3;dy++){
                if ((yc==0 && dy==0) || (yc==2 && dy==2)) continue;
                float rs = P[dy*3+1];
                if (xc!=0) rs += P[dy*3+0];
                if (xc!=2) rs += P[dy*3+2];
                tot += rs;
            }
            g_Pb[(s*128+co)*9 + yc*3+xc] = tot;
        }
    }
}

// ---- per-tap MMA ----
__device__ __forceinline__ void conv_tap(uint32_t xb, uint32_t ab, int tap,
                                         int lane, int cob, int pxb,
                                         float acc[4][4][4])
{
    const int lr  = lane & 7;
    const int hsA = lane >> 4;
    const int hsB = (lane >> 3) & 1;
    const int dy = tap/3, dx = tap - dy*3;
    const int dlt = (dy-1)*34 + (dx-1);

    uint32_t rowA[4], rsA[4];
    #pragma unroll
    for (int mi=0;mi<4;mi++){
        int r = cob + mi*16 + lr + ((lane>>3)&1)*8;
        rowA[mi] = (uint32_t)r*256u; rsA[mi] = (uint32_t)(r&7);
    }
    uint32_t rowB[2], rsB[2];
    #pragma unroll
    for (int nn=0;nn<2;nn++){
        int r = 36 + dlt + pxb + nn*16 + lr + (lane>>4)*8;
        rowB[nn] = (uint32_t)r*256u; rsB[nn] = (uint32_t)(r&7);
    }
    #pragma unroll
    for (int k8=0;k8<8;k8++){
        uint32_t a[4][4];
        #pragma unroll
        for (int mi=0;mi<4;mi++){
            uint32_t sgi = (uint32_t)(k8*2 + hsA);
            ldsm4(a[mi][0],a[mi][1],a[mi][2],a[mi][3],
                  ab + rowA[mi] + ((sgi ^ rsA[mi])<<4));
        }
        #pragma unroll
        for (int nn=0;nn<2;nn++){
            uint32_t sgi = (uint32_t)(k8*2 + hsB);
            uint32_t b0,b1,b2,b3;
            ldsm4(b0,b1,b2,b3, xb + rowB[nn] + ((sgi ^ rsB[nn])<<4));
            #pragma unroll
            for (int mi=0;mi<4;mi++){
                mma16816(acc[mi][2*nn],   a[mi][0],a[mi][1],a[mi][2],a[mi][3], b0,b1);
                mma16816(acc[mi][2*nn+1], a[mi][0],a[mi][1],a[mi][2],a[mi][3], b2,b3);
            }
        }
    }
}

// ---- mma.sync fp16 implicit conv: D[128co,128px], 2 CTAs/SM, fused GN sums ----
// tap range [t0,t1): 3x3 convs use [0,9); vpost 1x1 uses [4,5) (dlt=0)
__global__ __launch_bounds__(256,2)
void mmaconv_k(const __half* __restrict__ wrep,
               const __half* __restrict__ nhwc,
               const float* __restrict__ Pb,
               float* __restrict__ dst,
               float* __restrict__ stats, int nkc, int t0, int t1)
{
    extern __shared__ char dsm[];
    const uint32_t sb = smem_u32(dsm);
    const uint32_t XB = sb;
    const uint32_t AB = sb + AB_OFF;
    const int t = threadIdx.x;
    const int wid = t>>5, lane = t&31;
    const int img = blockIdx.x/10;
    const int p0  = (blockIdx.x%10)*128;
    const int s   = img>>4;
    const int cob = (wid&1)*64;
    const int pxb = (wid>>1)*32;

    float acc[4][4][4];
    #pragma unroll
    for (int mi=0;mi<4;mi++)
    #pragma unroll
    for (int ni=0;ni<4;ni++)
    #pragma unroll
    for (int e=0;e<4;e++) acc[mi][ni][e]=0.f;

    for (int kc=0; kc<nkc; kc++){
        {
            const char* src = (const char*)nhwc
                + ((size_t)GUARD + (size_t)img*RPI + p0 - 36)*512 + kc*256;
            #pragma unroll
            for (int j=0;j<13;j++){
                int i = j*256 + t;
                if (i < 3200){
                    uint32_t r = (uint32_t)(i>>4), sg = (uint32_t)(i&15);
                    cpa16(XB + r*256 + ((sg^(r&7))<<4), src + (size_t)r*512 + sg*16);
                }
            }
            cp_commit();
        }
        for (int tap=t0; tap<t1; tap++){
            const char* asrc = (const char*)(wrep + (size_t)(tap*nkc+kc)*16384);
            #pragma unroll
            for (int j=0;j<8;j++){
                int i = j*256 + t;
                uint32_t r = (uint32_t)(i>>4), sg = (uint32_t)(i&15);
                cpa16(AB + r*256 + ((sg^(r&7))<<4), asrc + (size_t)i*16);
            }
            cp_commit(); cp_wait0(); __syncthreads();
            conv_tap(XB, AB, tap, lane, cob, pxb, acc);
            __syncthreads();
        }
    }

    const int g  = lane>>2;
    const int t2 = (lane&3)*2;
    float sm_=0.f, sq_=0.f;
    #pragma unroll
    for (int mi=0;mi<4;mi++){
        #pragma unroll
        for (int n8=0;n8<4;n8++){
            #pragma unroll
            for (int e=0;e<4;e++){
                int co  = cob + mi*16 + g + ((e>>1)<<3);
                int col = pxb + n8*8 + t2 + (e&1);
                int pp  = p0 + col;
                int q34 = pp/34;
                int yy  = q34 - 1;
                int xx  = pp - q34*34 - 1;
                if ((unsigned)yy < 32u && (unsigned)xx < 32u){
                    float v = acc[mi][n8][e];
                    if (Pb){
                        int yc = (yy==0)?0:((yy==31)?2:1);
                        int xc = (xx==0)?0:((xx==31)?2:1);
                        v += Pb[(s*128+co)*9 + yc*3+xc];
                    }
                    dst[((size_t)img*128+co)*1024 + (yy<<5)+xx] = v;
                    sm_ += v; sq_ += v*v;
                }
            }
        }
    }
    #pragma unroll
    for (int o=16;o;o>>=1){
        sm_ += __shfl_down_sync(0xffffffffu, sm_, o);
        sq_ += __shfl_down_sync(0xffffffffu, sq_, o);
    }
    float* red = (float*)dsm;
    __syncthreads();
    if (lane==0){ red[wid*2] = sm_; red[wid*2+1] = sq_; }
    __syncthreads();
    if (t==0){
        float S=0.f, S2=0.f;
        #pragma unroll
        for (int w=0;w<8;w++){ S += red[w*2]; S2 += red[w*2+1]; }
        atomicAdd(&stats[img*2],   S);
        atomicAdd(&stats[img*2+1], S2);
    }
}

// ---- GN apply from raw sums (o) ----
__global__ void gn_apply_k(float* __restrict__ x, const float* __restrict__ stats,
                           const float* __restrict__ gw, const float* __restrict__ gb,
                           int nimg, int act)
{
    int n4 = nimg*32768;
    for (int i = blockIdx.x*blockDim.x + threadIdx.x; i < n4; i += gridDim.x*blockDim.x){
        int base = i<<2;
        int img = base>>17; int c = (base>>10)&127;
        float sum = stats[2*img], ssq = stats[2*img+1];
        float mu = sum*(1.f/131072.f);
        float rs = rsqrtf(ssq*(1.f/131072.f) - mu*mu + 1e-5f);
        float sc = rs*gw[c];
        float sh = gb[c] - mu*sc;
        float4 v = ((float4*)x)[i];
        v.x = v.x*sc+sh; v.y = v.y*sc+sh; v.z = v.z*sc+sh; v.w = v.w*sc+sh;
        if (act){
            v.x *= sigmf(v.x); v.y *= sigmf(v.y); v.z *= sigmf(v.z); v.w *= sigmf(v.w);
        }
        ((float4*)x)[i] = v;
    }
}

// ---- GN apply + channel mean/max pool fused (k, q) ----
__global__ void gn_apply_pool_k(float* __restrict__ x, const float* __restrict__ stats,
                                const float* __restrict__ gw, const float* __restrict__ gb,
                                float* __restrict__ pool)
{
    __shared__ float sc[128], sh[128];
    int t = threadIdx.x;
    int img = blockIdx.x>>2;
    int p = ((blockIdx.x&3)<<8) + t;
    if (t < 128){
        float sum = stats[2*img], ssq = stats[2*img+1];
        float mu = sum*(1.f/131072.f);
        float rs = rsqrtf(ssq*(1.f/131072.f) - mu*mu + 1e-5f);
        float scv = rs*gw[t];
        sc[t] = scv; sh[t] = gb[t] - mu*scv;
    }
    __syncthreads();
    float* base = x + (size_t)img*CHW + p;
    float s = 0.f, m = -3.402823466e38f;
    #pragma unroll 4
    for (int c=0;c<128;c++){
        float y = base[(size_t)c<<10]*sc[c] + sh[c];
        base[(size_t)c<<10] = y;
        s += y; m = fmaxf(m, y);
    }
    pool[img*2048 + p]        = s*(1.f/128.f);
    pool[img*2048 + 1024 + p] = m;
}

// ---- GN apply att (silu) + newout write fused ----
__global__ void gn_apply_att_k(float* __restrict__ x, const float* __restrict__ stats,
                               const float* __restrict__ gw, const float* __restrict__ gb,
                               const unsigned char* __restrict__ mask,
                               float* __restrict__ out)
{
    int i = blockIdx.x*blockDim.x + threadIdx.x;
    if (i >= BN*32768) return;
    int base = i<<2;
    int img = base>>17; int c = (base>>10)&127;
    float sum = stats[2*img], ssq = stats[2*img+1];
    float mu = sum*(1.f/131072.f);
    float rs = rsqrtf(ssq*(1.f/131072.f) - mu*mu + 1e-5f);
    float sc = rs*gw[c];
    float sh = gb[c] - mu*sc;
    float4 v = ((float4*)x)[i];
    v.x = v.x*sc+sh; v.y = v.y*sc+sh; v.z = v.z*sc+sh; v.w = v.w*sc+sh;
    v.x *= sigmf(v.x); v.y *= sigmf(v.y); v.z *= sigmf(v.z); v.w *= sigmf(v.w);
    ((float4*)x)[i] = v;
    float4 z = mask_at(mask, img) ? v : make_float4(0.f,0.f,0.f,0.f);
    *(float4*)&out[(size_t)2*BN*CHW + base] = z;
}

// ---- 2->1 3x3 conv + sigmoid ----
__global__ void saconv_k(const float* __restrict__ pool, const float* __restrict__ w,
                         const float* __restrict__ b, float* __restrict__ sa, int nimg)
{
    int i = blockIdx.x*blockDim.x + threadIdx.x;
    if (i >= nimg*HWN) return;
    int img = i>>10, p = i&1023, y = p>>5, x = p&31;
    float acc = b[0];
    #pragma unroll
    for (int c2=0;c2<2;c2++)
    #pragma unroll
    for (int dy=-1;dy<=1;dy++)
    #pragma unroll
    for (int dx=-1;dx<=1;dx++){
        int yy=y+dy, xx=x+dx;
        if ((unsigned)yy<32u && (unsigned)xx<32u)
            acc += pool[img*2048 + c2*1024 + (yy<<5)+xx] * w[c2*9 + (dy+1)*3 + (dx+1)];
    }
    sa[i] = sigmf(acc);
}

// ---- attention pieces ----
__global__ void qfg_k()
{
    int wid  = (blockIdx.x*blockDim.x + threadIdx.x) >> 5;
    int lane = threadIdx.x & 31;
    if (wid >= SN*BN*CH) return;
    int c = wid & 127, b = (wid>>7)&15, s = wid>>11;
    const float* qp = g_q   + ((size_t)b*128 + c)*1024;
    const float* kp = g_ksa + (size_t)(s*16+b)*1024;
    float acc = 0.f;
    for (int p=lane; p<1024; p+=32) acc += qp[p]*kp[p];
    #pragma unroll
    for (int o=16;o;o>>=1) acc += __shfl_down_sync(0xffffffffu, acc, o);
    if (!lane) g_qfg[wid] = acc*(1.f/1024.f);
}

__global__ void sprob_k()
{
    int img = blockIdx.x;
    __shared__ float fq[128];
    int t = threadIdx.x;
    if (t < 128) fq[t] = g_qfg[img*128 + t];
    __syncthreads();
    for (int p=t; p<1024; p+=256){
        const float* kp = g_k + (size_t)img*CHW + p;
        float acc = 0.f;
        #pragma unroll 4
        for (int c=0;c<128;c++) acc += fq[c]*kp[(size_t)c<<10];
        g_sprob[img*1024 + p] = sigmf(acc);
    }
}

// 1024 blocks: img x 8 chunks, atomic accumulate
__global__ void tlogit_k()
{
    int img = blockIdx.x>>3, chunk = blockIdx.x&7, b = img & 15;
    int base = chunk*16384;
    float acc = 0.f;
    for (int i = base + threadIdx.x; i < base + 16384; i += 256){
        int p = i & 1023;
        acc += g_q[(size_t)b*CHW + i]*g_qsa[b*1024+p]
             * g_k[(size_t)img*CHW + i]*g_ksa[img*1024+p];
    }
    #pragma unroll
    for (int o=16;o;o>>=1) acc += __shfl_down_sync(0xffffffffu, acc, o);
    __shared__ float sh[8];
    if ((threadIdx.x&31)==0) sh[threadIdx.x>>5] = acc;
    __syncthreads();
    if (threadIdx.x==0){
        float S=0.f;
        #pragma unroll
        for (int i=0;i<8;i++) S += sh[i];
        atomicAdd(&g_tl[img], S);
    }
}

__global__ void tprob_k()
{
    int b = threadIdx.x;
    if (b >= 16) return;
    const float SCL = rsqrtf(131072.f);
    float m = -3.402823466e38f;
    #pragma unroll
    for (int s=0;s<8;s++) m = fmaxf(m, g_tl[s*16+b]*SCL);
    float e[8]; float sum = 0.f;
    #pragma unroll
    for (int s=0;s<8;s++){ e[s] = __expf(g_tl[s*16+b]*SCL - m); sum += e[s]; }
    float inv = 1.f/sum;
    #pragma unroll
    for (int s=0;s<8;s++) g_tp[s*16+b] = e[s]*inv;
}

// ---- av with fused v-GN, writes fp16 NHWC directly (ch0-127 of small buffer) ----
__global__ void av_fill_k(const float* __restrict__ vgw, const float* __restrict__ vgb)
{
    __shared__ float sm[32][129];
    __shared__ float sc[8][128], sh[8][128];
    int t = threadIdx.x;
    int img = blockIdx.x>>5, y = blockIdx.x&31;
    int xg = t&31, cg = t>>5;
    if (t < 128){
        #pragma unroll
        for (int s=0;s<8;s++){
            int i2 = s*16 + img;
            float sum = g_stats[ST_V+2*i2], ssq = g_stats[ST_V+2*i2+1];
            float mu = sum*(1.f/131072.f);
            float rs = rsqrtf(ssq*(1.f/131072.f) - mu*mu + 1e-5f);
            float s_ = rs*vgw[t];
            sc[s][t] = s_; sh[s][t] = vgb[t] - mu*s_;
        }
    }
    __syncthreads();
    int p = y*32 + xg;
    float ws[8];
    #pragma unroll
    for (int s=0;s<8;s++){
        int i2 = s*16 + img;
        ws[s] = g_tp[i2]*g_sprob[i2*1024 + p];
    }
    #pragma unroll
    for (int cc=0; cc<16; cc++){
        int c = cc*8 + cg;
        float acc = 0.f;
        #pragma unroll
        for (int s=0;s<8;s++){
            int i2 = s*16 + img;
            float vv = g_v[((size_t)i2*128 + c)*1024 + p];
            acc += ws[s]*(vv*sc[s][c] + sh[s][c]);
        }
        sm[xg][c] = acc;
    }
    __syncthreads();
    size_t rb = GUARD + (size_t)img*RPI + (size_t)(y+1)*34;
    if (t < 128){
        #pragma unroll
        for (int xs=0; xs<32; xs++)
            g_nhwcS[(rb + xs + 1)*256 + t] = __float2half(sm[xs][t]);
    }
}

// ---- fused SE: mean -> fc1(relu) -> fc2(sigmoid) ----
__global__ void se_k(const float* __restrict__ w1, const float* __restrict__ b1,
                     const float* __restrict__ w2, const float* __restrict__ b2)
{
    __shared__ float mean[128], f1[32];
    int b = blockIdx.x;
    int w = threadIdx.x>>5, lane = threadIdx.x&31;
    for (int c=w; c<128; c+=8){
        const float* p = g_o + ((size_t)b*128 + c)*1024;
        float s = 0.f;
        for (int i=lane; i<1024; i+=32) s += p[i];
        #pragma unroll
        for (int o=16;o;o>>=1) s += __shfl_down_sync(0xffffffffu, s, o);
        if (!lane) mean[c] = s*(1.f/1024.f);
    }
    __syncthreads();
    if (threadIdx.x < 32){
        int j = threadIdx.x;
        float acc = b1[j];
        #pragma unroll 4
        for (int c=0;c<128;c++) acc += mean[c]*w1[j*128+c];
        f1[j] = fmaxf(acc, 0.f);
    }
    __syncthreads();
    if (threadIdx.x < 128){
        int c = threadIdx.x;
        float acc = b2[c];
        #pragma unroll
        for (int j=0;j<32;j++) acc += f1[j]*w2[c*32+j];
        g_se3[b*128+c] = sigmf(acc);
    }
}

__global__ void final_k(float* __restrict__ out)
{
    int i = blockIdx.x*blockDim.x + threadIdx.x;
    if (i >= BN*CHW/4) return;
    int base = i<<2;
    int b = base>>17; int c = (base>>10)&127;
    float g = 1.f + g_se3[b*128+c];
    float4 o4 = *(const float4*)&g_o[base];
    o4.x*=g; o4.y*=g; o4.z*=g; o4.w*=g;
    *(float4*)&out[base] = o4;
    *(float4*)&out[(size_t)BN*CHW + base] = *(const float4*)&g_ht[base];
}

// ---- host launcher ----
extern "C" void kernel_launch(void* const* d_in, const int* in_sizes, int n_in,
                              void* d_out, int out_size)
{
    (void)in_sizes; (void)n_in; (void)out_size;
    const float* inputs  = (const float*)d_in[0];
    const float* hidden  = (const float*)d_in[1];
    const float* outq    = (const float*)d_in[2];
    const unsigned char* mask = (const unsigned char*)d_in[3];
    const float* enc_w   = (const float*)d_in[4];
    const float* enc_gw  = (const float*)d_in[5];
    const float* enc_gb  = (const float*)d_in[6];
    const float* qpre_w  = (const float*)d_in[7];
    const float* qpre_gw = (const float*)d_in[8];
    const float* qpre_gb = (const float*)d_in[9];
    const float* kpre_w  = (const float*)d_in[10];
    const float* kpre_gw = (const float*)d_in[11];
    const float* kpre_gb = (const float*)d_in[12];
    const float* vpre_w  = (const float*)d_in[13];
    const float* vpre_gw = (const float*)d_in[14];
    const float* vpre_gb = (const float*)d_in[15];
    const float* qsa_w   = (const float*)d_in[16];
    const float* qsa_b   = (const float*)d_in[17];
    const float* ksa_w   = (const float*)d_in[18];
    const float* ksa_b   = (const float*)d_in[19];
    const float* vpost_w = (const float*)d_in[20];
    const float* vpost_gw= (const float*)d_in[21];
    const float* vpost_gb= (const float*)d_in[22];
    const float* pos_emb = (const float*)d_in[23];
    const float* outt_w  = (const float*)d_in[24];
    const float* outt_gw = (const float*)d_in[25];
    const float* outt_gb = (const float*)d_in[26];
    const float* se_w1   = (const float*)d_in[27];
    const float* se_b1   = (const float*)d_in[28];
    const float* se_w2   = (const float*)d_in[29];
    const float* se_b2   = (const float*)d_in[30];
    float* out = (float*)d_out;

    float *ht,*q,*k,*v,*att,*o,*stats,*pool,*qsa,*ksa,*peN,*Pb;
    __half *wrep, *nhwc, *nhwcS;
    cudaGetSymbolAddress((void**)&ht,   g_ht);
    cudaGetSymbolAddress((void**)&q,    g_q);
    cudaGetSymbolAddress((void**)&k,    g_k);
    cudaGetSymbolAddress((void**)&v,    g_v);
    cudaGetSymbolAddress((void**)&att,  g_att);
    cudaGetSymbolAddress((void**)&o,    g_o);
    cudaGetSymbolAddress((void**)&stats,g_stats);
    cudaGetSymbolAddress((void**)&pool, g_pool);
    cudaGetSymbolAddress((void**)&qsa,  g_qsa);
    cudaGetSymbolAddress((void**)&ksa,  g_ksa);
    cudaGetSymbolAddress((void**)&peN,  g_peN);
    cudaGetSymbolAddress((void**)&Pb,   g_Pb);
    cudaGetSymbolAddress((void**)&wrep, g_wrep);
    cudaGetSymbolAddress((void**)&nhwc, g_nhwc);
    cudaGetSymbolAddress((void**)&nhwcS,g_nhwcS);

    // wrep offsets (halfs), single-split
    const size_t WR_KPRE  = 0;
    const size_t WR_VPRE  = 294912;
    const size_t WR_QPRE  = 589824;
    const size_t WR_OUTT  = 737280;
    const size_t WR_ENC   = 1032192;
    const size_t WR_VPOST = 1179648;   // single tile; accessed as slot 4 via -4*16384 base

    cudaFuncSetAttribute(mmaconv_k, cudaFuncAttributeMaxDynamicSharedMemorySize, DSMEM_TOTAL);

    zero_stats_k<<<1,768>>>();
    fill_nhwc_k<<<4096,256>>>(hidden, outq);
    wrep_k<<<1152,256>>>(kpre_w, wrep + WR_KPRE, 256, 2);
    mmaconv_k<<<1280,256,DSMEM_TOTAL>>>(wrep + WR_KPRE, nhwc, nullptr, k, stats + ST_K, 2, 0, 9);
    wrep_k<<<1152,256>>>(vpre_w, wrep + WR_VPRE, 256, 2);
    pe_norm_k<<<8,256>>>(pos_emb, peN);
    pbconv_k<<<8,128>>>(vpre_w);
    mmaconv_k<<<1280,256,DSMEM_TOTAL>>>(wrep + WR_VPRE, nhwc, Pb, v, stats + ST_V, 2, 0, 9);

    fill_in_k<<<512,256>>>(inputs);
    wrep_k<<<576,256>>>(enc_w,  wrep + WR_ENC,  64, 1);
    wrep_k<<<576,256>>>(qpre_w, wrep + WR_QPRE, 128, 1);
    wrep_k<<<1152,256>>>(outt_w, wrep + WR_OUTT, 192, 2);
    wrep1x1_k<<<64,256>>>(vpost_w, wrep + WR_VPOST);

    // ht = silu(gn(mmaconv(inputs, enc_w))) ; also fills nhwcS for qpre
    mmaconv_k<<<160,256,DSMEM_TOTAL>>>(wrep + WR_ENC, nhwcS, nullptr, ht, stats + ST_HT, 1, 0, 9);
    gn_ht_fill_k<<<512,256>>>(enc_gw, enc_gb);

    // q = gn(mmaconv(ht)) + fused pool
    mmaconv_k<<<160,256,DSMEM_TOTAL>>>(wrep + WR_QPRE, nhwcS, nullptr, q, stats + ST_Q, 1, 0, 9);
    gn_apply_pool_k<<<64,256>>>(q, stats + ST_Q, qpre_gw, qpre_gb, pool);
    saconv_k<<<(BN*HWN+255)/256,256>>>(pool, qsa_w, qsa_b, qsa, BN);

    // k gn fused with pool; v GN deferred into av_fill
    gn_apply_pool_k<<<512,256>>>(k, stats + ST_K, kpre_gw, kpre_gb, pool);
    saconv_k<<<(SBN*HWN+255)/256,256>>>(pool, ksa_w, ksa_b, ksa, SBN);

    // attention
    qfg_k<<<2048,256>>>();
    sprob_k<<<SBN,256>>>();
    tlogit_k<<<1024,256>>>();
    tprob_k<<<1,32>>>();
    av_fill_k<<<512,256>>>(vpre_gw, vpre_gb);

    // att = silu(gn(mmaconv1x1(av))) + fused newout
    mmaconv_k<<<160,256,DSMEM_TOTAL>>>(wrep + WR_VPOST - 65536, nhwcS, nullptr,
                                       att, stats + ST_ATT, 1, 4, 5);
    gn_apply_att_k<<<2048,256>>>(att, stats + ST_ATT, vpost_gw, vpost_gb, mask, out);

    // o = silu(gn(mmaconv(concat(inputs, att+ht))))
    xcat_fill_k<<<512,256>>>(inputs);
    mmaconv_k<<<160,256,DSMEM_TOTAL>>>(wrep + WR_OUTT, nhwcS, nullptr, o, stats + ST_O, 2, 0, 9);
    gn_apply_k<<<2048,256>>>(o, stats + ST_O, outt_gw, outt_gb, BN, 1);

    se_k<<<BN,256>>>(se_w1, se_b1, se_w2, se_b2);
    final_k<<<2048,256>>>(out);
}